// round 4
// baseline (speedup 1.0000x reference)
#include <cuda_runtime.h>
#include <cuda_bf16.h>
#include <cstdint>

// Problem constants
#define BATCH   8
#define SEQ     1024
#define DIM     768
#define HEADS   12
#define HDIM    64
#define INNER   768
#define TRIPLE  2304
#define SCALE   0.125f

typedef __nv_bfloat16 bf16;

// ---------------- static scratch ----------------
__device__ __align__(128) float g_q[BATCH * HEADS * SEQ * HDIM];
__device__ __align__(128) float g_k[BATCH * HEADS * SEQ * HDIM];
__device__ __align__(128) float g_v[BATCH * HEADS * SEQ * HDIM];
__device__ __align__(128) float g_s[(size_t)BATCH * HEADS * SEQ * SEQ];
__device__ __align__(128) float g_o[BATCH * SEQ * INNER];

// bf16 hi/lo split operands for tensor-core GEMMs
__device__ __align__(128) bf16 g_xh[BATCH * SEQ * DIM];
__device__ __align__(128) bf16 g_xl[BATCH * SEQ * DIM];
__device__ __align__(128) bf16 g_wqh[TRIPLE * DIM];   // [n][k]
__device__ __align__(128) bf16 g_wql[TRIPLE * DIM];
__device__ __align__(128) bf16 g_woh[DIM * INNER];    // [n][k]
__device__ __align__(128) bf16 g_wol[DIM * INNER];
__device__ __align__(128) bf16 g_oh[BATCH * SEQ * INNER];
__device__ __align__(128) bf16 g_ol[BATCH * SEQ * INNER];

// ================= HMMA helpers (family-portable, no tcgen05) =============
__device__ __forceinline__ uint32_t smem_to_u32(const void* p) {
    uint32_t a;
    asm("{ .reg .u64 t; cvta.to.shared.u64 t, %1; cvt.u32.u64 %0, t; }"
        : "=r"(a) : "l"(p));
    return a;
}
__device__ __forceinline__ void ldmatrix_x4(uint32_t& r0, uint32_t& r1,
                                            uint32_t& r2, uint32_t& r3,
                                            uint32_t addr) {
    asm volatile("ldmatrix.sync.aligned.m8n8.x4.shared.b16 {%0,%1,%2,%3}, [%4];"
                 : "=r"(r0), "=r"(r1), "=r"(r2), "=r"(r3) : "r"(addr));
}
__device__ __forceinline__ void mma_bf16(float* c, const uint32_t* a,
                                         uint32_t b0, uint32_t b1) {
    asm volatile("mma.sync.aligned.m16n8k16.row.col.f32.bf16.bf16.f32 "
                 "{%0,%1,%2,%3}, {%4,%5,%6,%7}, {%8,%9}, {%0,%1,%2,%3};"
                 : "+f"(c[0]), "+f"(c[1]), "+f"(c[2]), "+f"(c[3])
                 : "r"(a[0]), "r"(a[1]), "r"(a[2]), "r"(a[3]),
                   "r"(b0), "r"(b1));
}
#define CP_ASYNC16(sa, g) \
    asm volatile("cp.async.cg.shared.global [%0], [%1], 16;" :: "r"(sa), "l"(g))
#define CP_COMMIT() asm volatile("cp.async.commit_group;" ::: "memory")
#define CP_WAIT1()  asm volatile("cp.async.wait_group 1;" ::: "memory")
#define CP_WAIT0()  asm volatile("cp.async.wait_group 0;" ::: "memory")

// ---------------- packed f32x2 helpers ----------------
__device__ __forceinline__ unsigned long long pack2(float x) {
    unsigned int u = __float_as_uint(x);
    unsigned long long d;
    asm("mov.b64 %0, {%1, %1};" : "=l"(d) : "r"(u));
    return d;
}
__device__ __forceinline__ void ffma2(unsigned long long& d, unsigned long long a,
                                      unsigned long long b) {
    asm("fma.rn.f32x2 %0, %1, %2, %0;" : "+l"(d) : "l"(a), "l"(b));
}
__device__ __forceinline__ float2 unpack2(unsigned long long v) {
    unsigned int lo, hi;
    asm("mov.b64 {%0, %1}, %2;" : "=r"(lo), "=r"(hi) : "l"(v));
    return make_float2(__uint_as_float(lo), __uint_as_float(hi));
}

// ---------------- FMA-pipe exp ----------------
__device__ __forceinline__ float fast_exp(float x) {
    const float LOG2E = 1.4426950408889634f;
    const float MAGIC = 12582912.0f;
    float z = fmaf(x, LOG2E, MAGIC);
    int   e = __float_as_int(z) - 0x4B400000;
    float i = z - MAGIC;
    float f = fmaf(x, LOG2E, -i);
    float p = 1.5403531e-4f;
    p = fmaf(p, f, 1.3333558e-3f);
    p = fmaf(p, f, 9.6181291e-3f);
    p = fmaf(p, f, 5.5504109e-2f);
    p = fmaf(p, f, 2.4022651e-1f);
    p = fmaf(p, f, 6.9314718e-1f);
    p = fmaf(p, f, 1.0f);
    return __int_as_float(__float_as_int(p) + (e << 23));
}

// =========================================================================
// Prep: elementwise hi/lo bf16 split
// =========================================================================
__global__ __launch_bounds__(256) void split_kernel(
    const float* __restrict__ in, bf16* __restrict__ hi, bf16* __restrict__ lo, int n4)
{
    int i = blockIdx.x * 256 + threadIdx.x;
    if (i >= n4) return;
    float4 v = ((const float4*)in)[i];
    bf16 h0 = __float2bfloat16(v.x), h1 = __float2bfloat16(v.y);
    bf16 h2 = __float2bfloat16(v.z), h3 = __float2bfloat16(v.w);
    bf16 l0 = __float2bfloat16(v.x - __bfloat162float(h0));
    bf16 l1 = __float2bfloat16(v.y - __bfloat162float(h1));
    bf16 l2 = __float2bfloat16(v.z - __bfloat162float(h2));
    bf16 l3 = __float2bfloat16(v.w - __bfloat162float(h3));
    __nv_bfloat162* H = (__nv_bfloat162*)hi;
    __nv_bfloat162* L = (__nv_bfloat162*)lo;
    H[2 * i] = __nv_bfloat162(h0, h1); H[2 * i + 1] = __nv_bfloat162(h2, h3);
    L[2 * i] = __nv_bfloat162(l0, l1); L[2 * i + 1] = __nv_bfloat162(l2, l3);
}

// =========================================================================
// Prep: transpose + split.  in[R][C] fp32 -> out hi/lo [C][R] bf16
// =========================================================================
__global__ __launch_bounds__(256) void transpose_split_kernel(
    const float* __restrict__ in, bf16* __restrict__ oh, bf16* __restrict__ ol,
    int R, int C)
{
    __shared__ float t[32][33];
    const int tx = threadIdx.x, ty = threadIdx.y;
    const int bx = blockIdx.x, by = blockIdx.y;
    #pragma unroll
    for (int i = 0; i < 4; i++) {
        int r = by * 32 + ty + i * 8;
        t[ty + i * 8][tx] = in[(size_t)r * C + bx * 32 + tx];
    }
    __syncthreads();
    #pragma unroll
    for (int i = 0; i < 4; i++) {
        int c = bx * 32 + ty + i * 8;
        int r = by * 32 + tx;
        float v = t[tx][ty + i * 8];
        bf16 h = __float2bfloat16(v);
        bf16 l = __float2bfloat16(v - __bfloat162float(h));
        oh[(size_t)c * R + r] = h;
        ol[(size_t)c * R + r] = l;
    }
}

// =========================================================================
// HMMA GEMM (bf16 hi/lo 3-MMA split).
// C[8192 x Ntot] = A[8192 x 768] @ B^T, B stored [Ntot][768] K-major.
// 128x128x32 tiles, 8 warps (4x2), warp tile 32x64 (2x8 m16n8k16).
// cp.async 2-stage pipeline. mode 0: qkv scatter; mode 1: oproj + bias.
// =========================================================================
#define GS 40                    // smem row stride (bf16) — conflict-free ldmatrix
#define MAT_ELEMS (128 * GS)     // 5120 bf16 per matrix tile
#define BUF_ELEMS (4 * MAT_ELEMS)
#define HM_SMEM_BYTES (2 * BUF_ELEMS * 2)   // 81920

__global__ __launch_bounds__(256) void hmma_gemm_kernel(
    const bf16* __restrict__ Ah, const bf16* __restrict__ Al,
    const bf16* __restrict__ Bh, const bf16* __restrict__ Bl,
    const float* __restrict__ bias, float* __restrict__ outp, int mode)
{
    extern __shared__ bf16 sm[];
    const int tid = threadIdx.x, lane = tid & 31, wid = tid >> 5;
    const int wr = wid >> 1, wc = wid & 1;
    const int bn = blockIdx.x * 128, bm = blockIdx.y * 128;
    const uint32_t smem_base = smem_to_u32(sm);

    const int row0 = tid >> 2;          // 0..63
    const int row1 = row0 + 64;
    const int ch = tid & 3;             // 16B chunk

    const bf16* srcs[4] = {Ah, Al, Bh, Bl};
    const int rb[4] = {bm, bm, bn, bn};

    float acc[2][8][4] = {};

    // ---- issue cp.async loads for iteration `it` into buffer `b` ----
    auto issue = [&](int it, int b) {
        const int k0 = it * 32;
        #pragma unroll
        for (int m = 0; m < 4; m++) {
            const bf16* s = srcs[m];
            const bf16* g0 = s + (size_t)(rb[m] + row0) * DIM + k0 + ch * 8;
            const bf16* g1 = s + (size_t)(rb[m] + row1) * DIM + k0 + ch * 8;
            uint32_t d0 = smem_base + (uint32_t)(b * BUF_ELEMS + m * MAT_ELEMS + row0 * GS + ch * 8) * 2;
            uint32_t d1 = smem_base + (uint32_t)(b * BUF_ELEMS + m * MAT_ELEMS + row1 * GS + ch * 8) * 2;
            CP_ASYNC16(d0, g0);
            CP_ASYNC16(d1, g1);
        }
        CP_COMMIT();
    };

    issue(0, 0);
    const int NIT = DIM / 32;   // 24

    for (int it = 0; it < NIT; ++it) {
        const int b = it & 1;
        if (it + 1 < NIT) { issue(it + 1, b ^ 1); CP_WAIT1(); }
        else              { CP_WAIT0(); }
        __syncthreads();

        const uint32_t bufb = smem_base + (uint32_t)(b * BUF_ELEMS) * 2;
        #pragma unroll
        for (int ks = 0; ks < 2; ks++) {
            const uint32_t col = ks * 16 + (lane >> 4) * 8;
            uint32_t ah[2][4], al[2][4];
            #pragma unroll
            for (int mt = 0; mt < 2; mt++) {
                uint32_t r = wr * 32 + mt * 16 + (lane & 15);
                ldmatrix_x4(ah[mt][0], ah[mt][1], ah[mt][2], ah[mt][3],
                            bufb + (0 * MAT_ELEMS + r * GS + col) * 2);
                ldmatrix_x4(al[mt][0], al[mt][1], al[mt][2], al[mt][3],
                            bufb + (1 * MAT_ELEMS + r * GS + col) * 2);
            }
            #pragma unroll
            for (int p = 0; p < 4; p++) {
                uint32_t r = wc * 64 + p * 16 + (lane & 15);
                uint32_t bh0, bh1, bh2, bh3, bl0, bl1, bl2, bl3;
                ldmatrix_x4(bh0, bh1, bh2, bh3,
                            bufb + (2 * MAT_ELEMS + r * GS + col) * 2);
                ldmatrix_x4(bl0, bl1, bl2, bl3,
                            bufb + (3 * MAT_ELEMS + r * GS + col) * 2);
                #pragma unroll
                for (int mt = 0; mt < 2; mt++) {
                    mma_bf16(acc[mt][2 * p + 0], ah[mt], bh0, bh2);
                    mma_bf16(acc[mt][2 * p + 0], al[mt], bh0, bh2);
                    mma_bf16(acc[mt][2 * p + 0], ah[mt], bl0, bl2);
                    mma_bf16(acc[mt][2 * p + 1], ah[mt], bh1, bh3);
                    mma_bf16(acc[mt][2 * p + 1], al[mt], bh1, bh3);
                    mma_bf16(acc[mt][2 * p + 1], ah[mt], bl1, bl3);
                }
            }
        }
        __syncthreads();
    }

    // ---- epilogue ----
    #pragma unroll
    for (int mt = 0; mt < 2; mt++) {
        const int r = bm + wr * 32 + mt * 16 + (lane >> 2);
        #pragma unroll
        for (int nt = 0; nt < 8; nt++) {
            const int c = bn + wc * 64 + nt * 8 + 2 * (lane & 3);
            float2 v0 = make_float2(acc[mt][nt][0], acc[mt][nt][1]);
            float2 v1 = make_float2(acc[mt][nt][2], acc[mt][nt][3]);
            if (mode == 0) {
                int chunk = c / INNER;
                int e = c % INNER;
                int h = e >> 6, d = e & 63;
                float* dst = (chunk == 0) ? g_q : (chunk == 1 ? g_k : g_v);
                int b0 = r >> 10, n0 = r & 1023;
                *(float2*)&dst[(((size_t)(b0 * HEADS + h) * SEQ) + n0) * HDIM + d] = v0;
                int r2 = r + 8;
                int b1 = r2 >> 10, n1 = r2 & 1023;
                *(float2*)&dst[(((size_t)(b1 * HEADS + h) * SEQ) + n1) * HDIM + d] = v1;
            } else {
                float2 bq = *(const float2*)&bias[c];
                v0.x += bq.x; v0.y += bq.y;
                v1.x += bq.x; v1.y += bq.y;
                *(float2*)&outp[(size_t)r * DIM + c] = v0;
                *(float2*)&outp[(size_t)(r + 8) * DIM + c] = v1;
            }
        }
    }
}

// =========================================================================
// K2: scores+exp (proven R2 version)
// =========================================================================
__global__ __launch_bounds__(256, 2) void score_kernel()
{
    __shared__ float As[2][8][128];
    __shared__ float Bs[2][8][128];

    const int bh = blockIdx.z;
    const int n0 = blockIdx.y * 128;
    const int m0 = blockIdx.x * 128;
    const int tid = threadIdx.x;
    const int ty = tid >> 4, tx = tid & 15;
    const int r0 = ty * 4, r1 = r0 + 64;
    const int c0 = tx * 4, c1 = c0 + 64;

    const int aRow = tid >> 1, aK = (tid & 1) * 4;
    const float* aPtr = g_q + ((size_t)bh * SEQ + n0 + aRow) * HDIM + aK;
    const float* bPtr = g_k + ((size_t)bh * SEQ + m0 + aRow) * HDIM + aK;

    float4 av = *(const float4*)aPtr;
    float4 bv = *(const float4*)bPtr;
    As[0][aK + 0][aRow] = av.x; As[0][aK + 1][aRow] = av.y;
    As[0][aK + 2][aRow] = av.z; As[0][aK + 3][aRow] = av.w;
    Bs[0][aK + 0][aRow] = bv.x; Bs[0][aK + 1][aRow] = bv.y;
    Bs[0][aK + 2][aRow] = bv.z; Bs[0][aK + 3][aRow] = bv.w;
    __syncthreads();

    unsigned long long acc[8][4] = {};
    int buf = 0;
    const int NIT = HDIM / 8;

    for (int it = 0; it < NIT; ++it) {
        if (it + 1 < NIT) {
            av = *(const float4*)(aPtr + (it + 1) * 8);
            bv = *(const float4*)(bPtr + (it + 1) * 8);
        }
        #pragma unroll
        for (int k = 0; k < 8; k++) {
            float4 a0 = *(const float4*)&As[buf][k][r0];
            float4 a1 = *(const float4*)&As[buf][k][r1];
            ulonglong2 b0 = *(const ulonglong2*)&Bs[buf][k][c0];
            ulonglong2 b1 = *(const ulonglong2*)&Bs[buf][k][c1];
            float ar[8] = {a0.x, a0.y, a0.z, a0.w, a1.x, a1.y, a1.z, a1.w};
            #pragma unroll
            for (int i = 0; i < 8; i++) {
                unsigned long long ap = pack2(ar[i]);
                ffma2(acc[i][0], ap, b0.x);
                ffma2(acc[i][1], ap, b0.y);
                ffma2(acc[i][2], ap, b1.x);
                ffma2(acc[i][3], ap, b1.y);
            }
        }
        if (it + 1 < NIT) {
            buf ^= 1;
            As[buf][aK + 0][aRow] = av.x; As[buf][aK + 1][aRow] = av.y;
            As[buf][aK + 2][aRow] = av.z; As[buf][aK + 3][aRow] = av.w;
            Bs[buf][aK + 0][aRow] = bv.x; Bs[buf][aK + 1][aRow] = bv.y;
            Bs[buf][aK + 2][aRow] = bv.z; Bs[buf][aK + 3][aRow] = bv.w;
            __syncthreads();
        }
    }

    #pragma unroll
    for (int i = 0; i < 8; i++) {
        int n = n0 + ((i < 4) ? (r0 + i) : (r1 + i - 4));
        float* srow = g_s + ((size_t)bh * SEQ + n) * SEQ;
        #pragma unroll
        for (int jq = 0; jq < 2; jq++) {
            int m = m0 + (jq ? c1 : c0);
            float2 p0 = unpack2(acc[i][jq * 2 + 0]);
            float2 p1 = unpack2(acc[i][jq * 2 + 1]);
            float4 val = make_float4(fast_exp(p0.x * SCALE), fast_exp(p0.y * SCALE),
                                     fast_exp(p1.x * SCALE), fast_exp(p1.y * SCALE));
            *(float4*)&srow[m] = val;
        }
    }
}

// =========================================================================
// K3: normalize over heads
// =========================================================================
__global__ __launch_bounds__(256) void norm_kernel()
{
    size_t idx = (size_t)blockIdx.x * 256 + threadIdx.x;
    int m4 = idx & 255;
    int n = (idx >> 8) & 1023;
    int b = (int)(idx >> 18);

    float4* base = (float4*)g_s;
    float4 v[HEADS];
    float4 s = make_float4(0.f, 0.f, 0.f, 0.f);
    #pragma unroll
    for (int h = 0; h < HEADS; h++) {
        size_t off = ((size_t)(b * HEADS + h) * SEQ + n) * (SEQ / 4) + m4;
        v[h] = base[off];
        s.x += v[h].x; s.y += v[h].y; s.z += v[h].z; s.w += v[h].w;
    }
    float rx = 1.0f / s.x, ry = 1.0f / s.y, rz = 1.0f / s.z, rw = 1.0f / s.w;
    #pragma unroll
    for (int h = 0; h < HEADS; h++) {
        size_t off = ((size_t)(b * HEADS + h) * SEQ + n) * (SEQ / 4) + m4;
        float4 p = v[h];
        p.x *= rx; p.y *= ry; p.z *= rz; p.w *= rw;
        base[off] = p;
    }
}

// =========================================================================
// K4: attention @ V
// =========================================================================
__global__ __launch_bounds__(256, 2) void av_kernel()
{
    __shared__ float As[2][8][128];
    __shared__ float Bs[2][8][64];

    const int n0 = blockIdx.x * 128;
    const int bh = blockIdx.y;
    const int b = bh / HEADS, h = bh % HEADS;
    const int tid = threadIdx.x;
    const int ty = tid >> 4, tx = tid & 15;
    const int r0 = ty * 4, r1 = r0 + 64;
    const int c0 = tx * 4;

    const int aRow = tid >> 1, aK = (tid & 1) * 4;
    const float* aPtr = g_s + ((size_t)bh * SEQ + n0 + aRow) * SEQ + aK;
    const int bK = tid >> 4, bCol = (tid & 15) * 4;
    const float* bPtr = g_v + (size_t)bh * SEQ * HDIM + (size_t)bK * HDIM + bCol;

    float4 av = *(const float4*)aPtr;
    float4 bv = make_float4(0.f, 0.f, 0.f, 0.f);
    if (tid < 128) bv = *(const float4*)bPtr;
    As[0][aK + 0][aRow] = av.x; As[0][aK + 1][aRow] = av.y;
    As[0][aK + 2][aRow] = av.z; As[0][aK + 3][aRow] = av.w;
    if (tid < 128) *(float4*)&Bs[0][bK][bCol] = bv;
    __syncthreads();

    unsigned long long acc[8][2] = {};
    int buf = 0;
    const int NIT = SEQ / 8;

    for (int it = 0; it < NIT; ++it) {
        if (it + 1 < NIT) {
            av = *(const float4*)(aPtr + (it + 1) * 8);
            if (tid < 128) bv = *(const float4*)(bPtr + (size_t)(it + 1) * 8 * HDIM);
        }
        #pragma unroll
        for (int k = 0; k < 8; k++) {
            float4 a0 = *(const float4*)&As[buf][k][r0];
            float4 a1 = *(const float4*)&As[buf][k][r1];
            ulonglong2 b2 = *(const ulonglong2*)&Bs[buf][k][c0];
            float ar[8] = {a0.x, a0.y, a0.z, a0.w, a1.x, a1.y, a1.z, a1.w};
            #pragma unroll
            for (int i = 0; i < 8; i++) {
                unsigned long long ap = pack2(ar[i]);
                ffma2(acc[i][0], ap, b2.x);
                ffma2(acc[i][1], ap, b2.y);
            }
        }
        if (it + 1 < NIT) {
            buf ^= 1;
            As[buf][aK + 0][aRow] = av.x; As[buf][aK + 1][aRow] = av.y;
            As[buf][aK + 2][aRow] = av.z; As[buf][aK + 3][aRow] = av.w;
            if (tid < 128) *(float4*)&Bs[buf][bK][bCol] = bv;
            __syncthreads();
        }
    }

    #pragma unroll
    for (int i = 0; i < 8; i++) {
        int n = n0 + ((i < 4) ? (r0 + i) : (r1 + i - 4));
        float2 p0 = unpack2(acc[i][0]);
        float2 p1 = unpack2(acc[i][1]);
        float4 val = make_float4(p0.x, p0.y, p1.x, p1.y);
        *(float4*)&g_o[((size_t)(b * SEQ + n)) * INNER + h * HDIM + c0] = val;
    }
}

// =========================================================================
extern "C" void kernel_launch(void* const* d_in, const int* in_sizes, int n_in,
                              void* d_out, int out_size)
{
    const float* x     = (const float*)d_in[0];
    const float* w_qkv = (const float*)d_in[1];
    const float* w_out = (const float*)d_in[2];
    const float* b_out = (const float*)d_in[3];
    float* out = (float*)d_out;

    cudaFuncSetAttribute(hmma_gemm_kernel,
                         cudaFuncAttributeMaxDynamicSharedMemorySize, HM_SMEM_BYTES);

    bf16 *xh, *xl, *wqh, *wql, *woh, *wol, *oh, *ol;
    cudaGetSymbolAddress((void**)&xh,  g_xh);
    cudaGetSymbolAddress((void**)&xl,  g_xl);
    cudaGetSymbolAddress((void**)&wqh, g_wqh);
    cudaGetSymbolAddress((void**)&wql, g_wql);
    cudaGetSymbolAddress((void**)&woh, g_woh);
    cudaGetSymbolAddress((void**)&wol, g_wol);
    cudaGetSymbolAddress((void**)&oh,  g_oh);
    cudaGetSymbolAddress((void**)&ol,  g_ol);
    float* o_fp32;
    cudaGetSymbolAddress((void**)&o_fp32, g_o);

    // Prep: split x, transpose+split weights
    {
        int n4 = BATCH * SEQ * DIM / 4;
        split_kernel<<<(n4 + 255) / 256, 256>>>(x, xh, xl, n4);
    }
    {
        dim3 grid(TRIPLE / 32, DIM / 32);
        transpose_split_kernel<<<grid, dim3(32, 8)>>>(w_qkv, wqh, wql, DIM, TRIPLE);
    }
    {
        dim3 grid(DIM / 32, INNER / 32);
        transpose_split_kernel<<<grid, dim3(32, 8)>>>(w_out, woh, wol, INNER, DIM);
    }

    // K1: QKV projection on tensor cores (HMMA), scatter -> g_q/g_k/g_v
    {
        dim3 grid(TRIPLE / 128, (BATCH * SEQ) / 128);   // 18 x 64
        hmma_gemm_kernel<<<grid, 256, HM_SMEM_BYTES>>>(xh, xl, wqh, wql, nullptr, nullptr, 0);
    }
    // K2: scores -> exp
    {
        dim3 grid(SEQ / 128, SEQ / 128, BATCH * HEADS);
        score_kernel<<<grid, 256>>>();
    }
    // K3: normalize over heads
    {
        int total = BATCH * SEQ * (SEQ / 4);
        norm_kernel<<<total / 256, 256>>>();
    }
    // K4: attention @ V
    {
        dim3 grid(SEQ / 128, BATCH * HEADS);
        av_kernel<<<grid, 256>>>();
    }
    // Split attention output for projection
    {
        int n4 = BATCH * SEQ * INNER / 4;
        split_kernel<<<(n4 + 255) / 256, 256>>>(o_fp32, oh, ol, n4);
    }
    // K5: output projection on tensor cores (HMMA) + bias
    {
        dim3 grid(DIM / 128, (BATCH * SEQ) / 128);      // 6 x 64
        hmma_gemm_kernel<<<grid, 256, HM_SMEM_BYTES>>>(oh, ol, woh, wol, b_out, out, 1);
    }
}

// round 5
// speedup vs baseline: 2.0799x; 2.0799x over previous
#include <cuda_runtime.h>
#include <cuda_bf16.h>
#include <cstdint>

// Problem constants
#define BATCH   8
#define SEQ     1024
#define DIM     768
#define HEADS   12
#define HDIM    64
#define INNER   768
#define TRIPLE  2304
#define SCALE   0.125f

typedef __nv_bfloat16 bf16;

// ---------------- static scratch ----------------
__device__ __align__(128) float g_s[(size_t)BATCH * HEADS * SEQ * SEQ];   // E (fp32)

// bf16 hi/lo split tensors
__device__ __align__(128) bf16 g_xh[BATCH * SEQ * DIM];
__device__ __align__(128) bf16 g_xl[BATCH * SEQ * DIM];
__device__ __align__(128) bf16 g_wqh[TRIPLE * DIM];
__device__ __align__(128) bf16 g_wql[TRIPLE * DIM];
__device__ __align__(128) bf16 g_woh[DIM * INNER];
__device__ __align__(128) bf16 g_wol[DIM * INNER];
__device__ __align__(128) bf16 g_qh[BATCH * HEADS * SEQ * HDIM];
__device__ __align__(128) bf16 g_ql[BATCH * HEADS * SEQ * HDIM];
__device__ __align__(128) bf16 g_kh[BATCH * HEADS * SEQ * HDIM];
__device__ __align__(128) bf16 g_kl[BATCH * HEADS * SEQ * HDIM];
__device__ __align__(128) bf16 g_vh[BATCH * HEADS * SEQ * HDIM];
__device__ __align__(128) bf16 g_vl[BATCH * HEADS * SEQ * HDIM];
__device__ __align__(128) bf16 g_ph[(size_t)BATCH * HEADS * SEQ * SEQ];  // P hi
__device__ __align__(128) bf16 g_pl[(size_t)BATCH * HEADS * SEQ * SEQ];  // P lo
__device__ __align__(128) bf16 g_oh[BATCH * SEQ * INNER];
__device__ __align__(128) bf16 g_ol[BATCH * SEQ * INNER];

// ================= helpers =================
__device__ __forceinline__ uint32_t smem_to_u32(const void* p) {
    uint32_t a;
    asm("{ .reg .u64 t; cvta.to.shared.u64 t, %1; cvt.u32.u64 %0, t; }"
        : "=r"(a) : "l"(p));
    return a;
}
__device__ __forceinline__ void ldmatrix_x4(uint32_t& r0, uint32_t& r1,
                                            uint32_t& r2, uint32_t& r3,
                                            uint32_t addr) {
    asm volatile("ldmatrix.sync.aligned.m8n8.x4.shared.b16 {%0,%1,%2,%3}, [%4];"
                 : "=r"(r0), "=r"(r1), "=r"(r2), "=r"(r3) : "r"(addr));
}
__device__ __forceinline__ void ldmatrix_x4_trans(uint32_t& r0, uint32_t& r1,
                                                  uint32_t& r2, uint32_t& r3,
                                                  uint32_t addr) {
    asm volatile("ldmatrix.sync.aligned.m8n8.x4.trans.shared.b16 {%0,%1,%2,%3}, [%4];"
                 : "=r"(r0), "=r"(r1), "=r"(r2), "=r"(r3) : "r"(addr));
}
__device__ __forceinline__ void mma_bf16(float* c, const uint32_t* a,
                                         uint32_t b0, uint32_t b1) {
    asm volatile("mma.sync.aligned.m16n8k16.row.col.f32.bf16.bf16.f32 "
                 "{%0,%1,%2,%3}, {%4,%5,%6,%7}, {%8,%9}, {%0,%1,%2,%3};"
                 : "+f"(c[0]), "+f"(c[1]), "+f"(c[2]), "+f"(c[3])
                 : "r"(a[0]), "r"(a[1]), "r"(a[2]), "r"(a[3]),
                   "r"(b0), "r"(b1));
}
#define CP_ASYNC16(sa, g) \
    asm volatile("cp.async.cg.shared.global [%0], [%1], 16;" :: "r"(sa), "l"(g))
#define CP_COMMIT() asm volatile("cp.async.commit_group;" ::: "memory")
#define CP_WAIT1()  asm volatile("cp.async.wait_group 1;" ::: "memory")
#define CP_WAIT0()  asm volatile("cp.async.wait_group 0;" ::: "memory")

__device__ __forceinline__ float fast_exp(float x) {
    const float LOG2E = 1.4426950408889634f;
    const float MAGIC = 12582912.0f;
    float z = fmaf(x, LOG2E, MAGIC);
    int   e = __float_as_int(z) - 0x4B400000;
    float i = z - MAGIC;
    float f = fmaf(x, LOG2E, -i);
    float p = 1.5403531e-4f;
    p = fmaf(p, f, 1.3333558e-3f);
    p = fmaf(p, f, 9.6181291e-3f);
    p = fmaf(p, f, 5.5504109e-2f);
    p = fmaf(p, f, 2.4022651e-1f);
    p = fmaf(p, f, 6.9314718e-1f);
    p = fmaf(p, f, 1.0f);
    return __int_as_float(__float_as_int(p) + (e << 23));
}
__device__ __forceinline__ void split2(float2 v, __nv_bfloat162& h, __nv_bfloat162& l) {
    bf16 hx = __float2bfloat16(v.x), hy = __float2bfloat16(v.y);
    h = __nv_bfloat162(hx, hy);
    l = __nv_bfloat162(__float2bfloat16(v.x - __bfloat162float(hx)),
                       __float2bfloat16(v.y - __bfloat162float(hy)));
}

// =========================================================================
// Prep kernels
// =========================================================================
__global__ __launch_bounds__(256) void split_kernel(
    const float* __restrict__ in, bf16* __restrict__ hi, bf16* __restrict__ lo, int n4)
{
    int i = blockIdx.x * 256 + threadIdx.x;
    if (i >= n4) return;
    float4 v = ((const float4*)in)[i];
    __nv_bfloat162 h0, l0, h1, l1;
    split2(make_float2(v.x, v.y), h0, l0);
    split2(make_float2(v.z, v.w), h1, l1);
    __nv_bfloat162* H = (__nv_bfloat162*)hi;
    __nv_bfloat162* L = (__nv_bfloat162*)lo;
    H[2 * i] = h0; H[2 * i + 1] = h1;
    L[2 * i] = l0; L[2 * i + 1] = l1;
}

__global__ __launch_bounds__(256) void transpose_split_kernel(
    const float* __restrict__ in, bf16* __restrict__ oh, bf16* __restrict__ ol,
    int R, int C)
{
    __shared__ float t[32][33];
    const int tx = threadIdx.x, ty = threadIdx.y;
    const int bx = blockIdx.x, by = blockIdx.y;
    #pragma unroll
    for (int i = 0; i < 4; i++) {
        int r = by * 32 + ty + i * 8;
        t[ty + i * 8][tx] = in[(size_t)r * C + bx * 32 + tx];
    }
    __syncthreads();
    #pragma unroll
    for (int i = 0; i < 4; i++) {
        int c = bx * 32 + ty + i * 8;
        int r = by * 32 + tx;
        float v = t[tx][ty + i * 8];
        bf16 h = __float2bfloat16(v);
        bf16 l = __float2bfloat16(v - __bfloat162float(h));
        oh[(size_t)c * R + r] = h;
        ol[(size_t)c * R + r] = l;
    }
}

// =========================================================================
// HMMA GEMM (hi/lo 3-MMA). 128x128x32 tiles, 8 warps, warp 32x64.
// mode 0: qkv — epilogue splits to q/k/v bf16 hi/lo head-major.
// mode 1: oproj — epilogue adds bias, writes fp32 out.
// =========================================================================
#define GS 40
#define MAT_ELEMS (128 * GS)
#define BUF_ELEMS (4 * MAT_ELEMS)
#define HM_SMEM_BYTES (2 * BUF_ELEMS * 2)   // 81920

__global__ __launch_bounds__(256) void hmma_gemm_kernel(
    const bf16* __restrict__ Ah, const bf16* __restrict__ Al,
    const bf16* __restrict__ Bh, const bf16* __restrict__ Bl,
    const float* __restrict__ bias, float* __restrict__ outp, int mode)
{
    extern __shared__ bf16 sm[];
    const int tid = threadIdx.x, lane = tid & 31, wid = tid >> 5;
    const int wr = wid >> 1, wc = wid & 1;
    const int bn = blockIdx.x * 128, bm = blockIdx.y * 128;
    const uint32_t smem_base = smem_to_u32(sm);

    const int row0 = tid >> 2;
    const int row1 = row0 + 64;
    const int ch = tid & 3;

    const bf16* srcs[4] = {Ah, Al, Bh, Bl};
    const int rb[4] = {bm, bm, bn, bn};

    float acc[2][8][4] = {};

    auto issue = [&](int it, int b) {
        const int k0 = it * 32;
        #pragma unroll
        for (int m = 0; m < 4; m++) {
            const bf16* s = srcs[m];
            const bf16* g0 = s + (size_t)(rb[m] + row0) * DIM + k0 + ch * 8;
            const bf16* g1 = s + (size_t)(rb[m] + row1) * DIM + k0 + ch * 8;
            uint32_t d0 = smem_base + (uint32_t)(b * BUF_ELEMS + m * MAT_ELEMS + row0 * GS + ch * 8) * 2;
            uint32_t d1 = smem_base + (uint32_t)(b * BUF_ELEMS + m * MAT_ELEMS + row1 * GS + ch * 8) * 2;
            CP_ASYNC16(d0, g0);
            CP_ASYNC16(d1, g1);
        }
        CP_COMMIT();
    };

    issue(0, 0);
    const int NIT = DIM / 32;

    for (int it = 0; it < NIT; ++it) {
        const int b = it & 1;
        if (it + 1 < NIT) { issue(it + 1, b ^ 1); CP_WAIT1(); }
        else              { CP_WAIT0(); }
        __syncthreads();

        const uint32_t bufb = smem_base + (uint32_t)(b * BUF_ELEMS) * 2;
        #pragma unroll
        for (int ks = 0; ks < 2; ks++) {
            const uint32_t col = ks * 16 + (lane >> 4) * 8;
            uint32_t ah[2][4], al[2][4];
            #pragma unroll
            for (int mt = 0; mt < 2; mt++) {
                uint32_t r = wr * 32 + mt * 16 + (lane & 15);
                ldmatrix_x4(ah[mt][0], ah[mt][1], ah[mt][2], ah[mt][3],
                            bufb + (0 * MAT_ELEMS + r * GS + col) * 2);
                ldmatrix_x4(al[mt][0], al[mt][1], al[mt][2], al[mt][3],
                            bufb + (1 * MAT_ELEMS + r * GS + col) * 2);
            }
            #pragma unroll
            for (int p = 0; p < 4; p++) {
                uint32_t r = wc * 64 + p * 16 + (lane & 15);
                uint32_t bh0, bh1, bh2, bh3, bl0, bl1, bl2, bl3;
                ldmatrix_x4(bh0, bh1, bh2, bh3,
                            bufb + (2 * MAT_ELEMS + r * GS + col) * 2);
                ldmatrix_x4(bl0, bl1, bl2, bl3,
                            bufb + (3 * MAT_ELEMS + r * GS + col) * 2);
                // pass-interleaved: same-acc reuse distance 4
                #pragma unroll
                for (int mt = 0; mt < 2; mt++) {
                    mma_bf16(acc[mt][2 * p + 0], ah[mt], bh0, bh2);
                    mma_bf16(acc[mt][2 * p + 1], ah[mt], bh1, bh3);
                }
                #pragma unroll
                for (int mt = 0; mt < 2; mt++) {
                    mma_bf16(acc[mt][2 * p + 0], al[mt], bh0, bh2);
                    mma_bf16(acc[mt][2 * p + 1], al[mt], bh1, bh3);
                }
                #pragma unroll
                for (int mt = 0; mt < 2; mt++) {
                    mma_bf16(acc[mt][2 * p + 0], ah[mt], bl0, bl2);
                    mma_bf16(acc[mt][2 * p + 1], ah[mt], bl1, bl3);
                }
            }
        }
        __syncthreads();
    }

    // ---- epilogue ----
    #pragma unroll
    for (int mt = 0; mt < 2; mt++) {
        const int r = bm + wr * 32 + mt * 16 + (lane >> 2);
        #pragma unroll
        for (int nt = 0; nt < 8; nt++) {
            const int c = bn + wc * 64 + nt * 8 + 2 * (lane & 3);
            float2 v0 = make_float2(acc[mt][nt][0], acc[mt][nt][1]);
            float2 v1 = make_float2(acc[mt][nt][2], acc[mt][nt][3]);
            if (mode == 0) {
                int chunk = c / INNER;
                int e = c % INNER;
                int h = e >> 6, d = e & 63;
                bf16 *dh, *dl;
                if (chunk == 0)      { dh = g_qh; dl = g_ql; }
                else if (chunk == 1) { dh = g_kh; dl = g_kl; }
                else                 { dh = g_vh; dl = g_vl; }
                __nv_bfloat162 hh, ll;
                int b0 = r >> 10, n0 = r & 1023;
                size_t i0 = (((size_t)(b0 * HEADS + h) * SEQ) + n0) * HDIM + d;
                split2(v0, hh, ll);
                *(__nv_bfloat162*)&dh[i0] = hh;
                *(__nv_bfloat162*)&dl[i0] = ll;
                int r2 = r + 8;
                int b1 = r2 >> 10, n1 = r2 & 1023;
                size_t i1 = (((size_t)(b1 * HEADS + h) * SEQ) + n1) * HDIM + d;
                split2(v1, hh, ll);
                *(__nv_bfloat162*)&dh[i1] = hh;
                *(__nv_bfloat162*)&dl[i1] = ll;
            } else {
                float2 bq = *(const float2*)&bias[c];
                v0.x += bq.x; v0.y += bq.y;
                v1.x += bq.x; v1.y += bq.y;
                *(float2*)&outp[(size_t)r * DIM + c] = v0;
                *(float2*)&outp[(size_t)(r + 8) * DIM + c] = v1;
            }
        }
    }
}

// =========================================================================
// Score HMMA: E[b,h,n,m] = exp(SCALE * Q . K) per (b,h), 128x128 tile, K=64.
// A = Q (hi/lo), B = K (hi/lo), both [row][64] K-major.
// =========================================================================
#define SGS 72
#define SC_MAT (128 * SGS)
#define SC_SMEM_BYTES (4 * SC_MAT * 2)   // 73728

__global__ __launch_bounds__(256) void score_hmma_kernel()
{
    extern __shared__ bf16 sm[];
    const int tid = threadIdx.x, lane = tid & 31, wid = tid >> 5;
    const int wr = wid >> 1, wc = wid & 1;
    const int bh = blockIdx.z;
    const int n0 = blockIdx.y * 128;
    const int m0 = blockIdx.x * 128;
    const uint32_t smem_base = smem_to_u32(sm);

    const bf16* srcs[4] = {
        g_qh + ((size_t)bh * SEQ + n0) * HDIM,
        g_ql + ((size_t)bh * SEQ + n0) * HDIM,
        g_kh + ((size_t)bh * SEQ + m0) * HDIM,
        g_kl + ((size_t)bh * SEQ + m0) * HDIM
    };
    #pragma unroll
    for (int m = 0; m < 4; m++) {
        #pragma unroll
        for (int t = 0; t < 4; t++) {
            int i = tid + t * 256;
            int row = i >> 3, ch = i & 7;
            *(uint4*)&sm[m * SC_MAT + row * SGS + ch * 8] =
                *(const uint4*)(srcs[m] + (size_t)row * HDIM + ch * 8);
        }
    }
    __syncthreads();

    float acc[2][8][4] = {};

    #pragma unroll
    for (int ks = 0; ks < 4; ks++) {
        const uint32_t col = ks * 16 + (lane >> 4) * 8;
        uint32_t ah[2][4], al[2][4];
        #pragma unroll
        for (int mt = 0; mt < 2; mt++) {
            uint32_t r = wr * 32 + mt * 16 + (lane & 15);
            ldmatrix_x4(ah[mt][0], ah[mt][1], ah[mt][2], ah[mt][3],
                        smem_base + (0 * SC_MAT + r * SGS + col) * 2);
            ldmatrix_x4(al[mt][0], al[mt][1], al[mt][2], al[mt][3],
                        smem_base + (1 * SC_MAT + r * SGS + col) * 2);
        }
        #pragma unroll
        for (int p = 0; p < 4; p++) {
            uint32_t r = wc * 64 + p * 16 + (lane & 15);
            uint32_t bh0, bh1, bh2, bh3, bl0, bl1, bl2, bl3;
            ldmatrix_x4(bh0, bh1, bh2, bh3,
                        smem_base + (2 * SC_MAT + r * SGS + col) * 2);
            ldmatrix_x4(bl0, bl1, bl2, bl3,
                        smem_base + (3 * SC_MAT + r * SGS + col) * 2);
            #pragma unroll
            for (int mt = 0; mt < 2; mt++) {
                mma_bf16(acc[mt][2 * p + 0], ah[mt], bh0, bh2);
                mma_bf16(acc[mt][2 * p + 1], ah[mt], bh1, bh3);
            }
            #pragma unroll
            for (int mt = 0; mt < 2; mt++) {
                mma_bf16(acc[mt][2 * p + 0], al[mt], bh0, bh2);
                mma_bf16(acc[mt][2 * p + 1], al[mt], bh1, bh3);
            }
            #pragma unroll
            for (int mt = 0; mt < 2; mt++) {
                mma_bf16(acc[mt][2 * p + 0], ah[mt], bl0, bl2);
                mma_bf16(acc[mt][2 * p + 1], ah[mt], bl1, bl3);
            }
        }
    }

    // epilogue: exp + store fp32 E
    float* sbase = g_s + (size_t)bh * SEQ * SEQ;
    #pragma unroll
    for (int mt = 0; mt < 2; mt++) {
        const int r = n0 + wr * 32 + mt * 16 + (lane >> 2);
        #pragma unroll
        for (int nt = 0; nt < 8; nt++) {
            const int c = m0 + wc * 64 + nt * 8 + 2 * (lane & 3);
            float2 e0 = make_float2(fast_exp(acc[mt][nt][0] * SCALE),
                                    fast_exp(acc[mt][nt][1] * SCALE));
            float2 e1 = make_float2(fast_exp(acc[mt][nt][2] * SCALE),
                                    fast_exp(acc[mt][nt][3] * SCALE));
            *(float2*)&sbase[(size_t)r * SEQ + c] = e0;
            *(float2*)&sbase[(size_t)(r + 8) * SEQ + c] = e1;
        }
    }
}

// =========================================================================
// Norm: P = E / sum_h E ; write P as bf16 hi/lo.
// =========================================================================
__global__ __launch_bounds__(256) void norm_kernel()
{
    size_t idx = (size_t)blockIdx.x * 256 + threadIdx.x;  // < 2M
    int m4 = idx & 255;
    int n = (idx >> 8) & 1023;
    int b = (int)(idx >> 18);

    const float4* base = (const float4*)g_s;
    float4 v[HEADS];
    float4 s = make_float4(0.f, 0.f, 0.f, 0.f);
    #pragma unroll
    for (int h = 0; h < HEADS; h++) {
        size_t off = ((size_t)(b * HEADS + h) * SEQ + n) * (SEQ / 4) + m4;
        v[h] = base[off];
        s.x += v[h].x; s.y += v[h].y; s.z += v[h].z; s.w += v[h].w;
    }
    float rx = 1.0f / s.x, ry = 1.0f / s.y, rz = 1.0f / s.z, rw = 1.0f / s.w;
    #pragma unroll
    for (int h = 0; h < HEADS; h++) {
        size_t off = ((size_t)(b * HEADS + h) * SEQ + n) * (SEQ / 4) + m4;
        float2 p0 = make_float2(v[h].x * rx, v[h].y * ry);
        float2 p1 = make_float2(v[h].z * rz, v[h].w * rw);
        __nv_bfloat162 h0, l0, h1, l1;
        split2(p0, h0, l0);
        split2(p1, h1, l1);
        *(__nv_bfloat162*)&g_ph[off * 4]     = h0;
        *(__nv_bfloat162*)&g_ph[off * 4 + 2] = h1;
        *(__nv_bfloat162*)&g_pl[off * 4]     = l0;
        *(__nv_bfloat162*)&g_pl[off * 4 + 2] = l1;
    }
}

// =========================================================================
// AV HMMA: O = P @ V per (b,h). 128(n) x 64(d) tile, K=1024 in 32-chunks.
// A = P hi/lo [n][m]; B = V hi/lo [m][d] via ldmatrix.trans.
// Epilogue writes O split bf16 hi/lo at [b, n, h*64+d].
// =========================================================================
#define AGS 40                    // P smem stride
#define VGS 72                    // V smem stride
#define AV_P_ELEMS (128 * AGS)    // 5120
#define AV_V_ELEMS (32 * VGS)     // 2304
#define AV_STAGE (2 * AV_P_ELEMS + 2 * AV_V_ELEMS)   // 14848
#define AV_SMEM_BYTES (2 * AV_STAGE * 2)             // 59392

__global__ __launch_bounds__(256) void av_hmma_kernel()
{
    extern __shared__ bf16 sm[];
    const int tid = threadIdx.x, lane = tid & 31, wid = tid >> 5;
    const int wr = wid >> 1, wc = wid & 1;
    const int n0 = blockIdx.x * 128;
    const int bh = blockIdx.y;
    const int b = bh / HEADS, h = bh % HEADS;
    const uint32_t smem_base = smem_to_u32(sm);

    const bf16* php = g_ph + ((size_t)bh * SEQ + n0) * SEQ;
    const bf16* plp = g_pl + ((size_t)bh * SEQ + n0) * SEQ;
    const bf16* vhp = g_vh + (size_t)bh * SEQ * HDIM;
    const bf16* vlp = g_vl + (size_t)bh * SEQ * HDIM;

    float acc[2][4][4] = {};

    auto issue = [&](int it, int bb) {
        const int k0 = it * 32;
        const uint32_t sb = smem_base + (uint32_t)(bb * AV_STAGE) * 2;
        // P hi/lo: 128 rows x 32 cols, 4 chunks/row -> 512 chunks each
        #pragma unroll
        for (int t = 0; t < 2; t++) {
            int i = tid + t * 256;
            int row = i >> 2, ch = i & 3;
            uint32_t doff = (uint32_t)(row * AGS + ch * 8) * 2;
            CP_ASYNC16(sb + doff,
                       php + (size_t)row * SEQ + k0 + ch * 8);
            CP_ASYNC16(sb + (uint32_t)AV_P_ELEMS * 2 + doff,
                       plp + (size_t)row * SEQ + k0 + ch * 8);
        }
        // V hi/lo: 32 rows x 64 cols, 8 chunks/row -> 256 chunks each
        {
            int row = tid >> 3, ch = tid & 7;
            uint32_t doff = (uint32_t)(row * VGS + ch * 8) * 2;
            CP_ASYNC16(sb + (uint32_t)(2 * AV_P_ELEMS) * 2 + doff,
                       vhp + (size_t)(k0 + row) * HDIM + ch * 8);
            CP_ASYNC16(sb + (uint32_t)(2 * AV_P_ELEMS + AV_V_ELEMS) * 2 + doff,
                       vlp + (size_t)(k0 + row) * HDIM + ch * 8);
        }
        CP_COMMIT();
    };

    issue(0, 0);
    const int NIT = SEQ / 32;   // 32

    for (int it = 0; it < NIT; ++it) {
        const int bb = it & 1;
        if (it + 1 < NIT) { issue(it + 1, bb ^ 1); CP_WAIT1(); }
        else              { CP_WAIT0(); }
        __syncthreads();

        const uint32_t sb = smem_base + (uint32_t)(bb * AV_STAGE) * 2;
        const uint32_t vhb = sb + (uint32_t)(2 * AV_P_ELEMS) * 2;
        const uint32_t vlb = vhb + (uint32_t)AV_V_ELEMS * 2;

        #pragma unroll
        for (int ks = 0; ks < 2; ks++) {
            const uint32_t colA = ks * 16 + (lane >> 4) * 8;
            uint32_t ah[2][4], al[2][4];
            #pragma unroll
            for (int mt = 0; mt < 2; mt++) {
                uint32_t r = wr * 32 + mt * 16 + (lane & 15);
                ldmatrix_x4(ah[mt][0], ah[mt][1], ah[mt][2], ah[mt][3],
                            sb + (r * AGS + colA) * 2);
                ldmatrix_x4(al[mt][0], al[mt][1], al[mt][2], al[mt][3],
                            sb + (uint32_t)AV_P_ELEMS * 2 + (r * AGS + colA) * 2);
            }
            const uint32_t kb = ks * 16;
            #pragma unroll
            for (int nb = 0; nb < 2; nb++) {
                const uint32_t d0 = wc * 32 + nb * 16;
                // trans load: rows = k (m), cols = d. x4 covers k16 x d16.
                uint32_t vrow = kb + (lane & 7) + ((lane >> 3) & 1) * 8;
                uint32_t vcol = d0 + (lane >> 4) * 8;
                uint32_t bh0, bh1, bh2, bh3, bl0, bl1, bl2, bl3;
                ldmatrix_x4_trans(bh0, bh1, bh2, bh3, vhb + (vrow * VGS + vcol) * 2);
                ldmatrix_x4_trans(bl0, bl1, bl2, bl3, vlb + (vrow * VGS + vcol) * 2);
                const int nt0 = nb * 2, nt1 = nb * 2 + 1;
                // trans pairs: {r0,r1} = d-block0, {r2,r3} = d-block1
                #pragma unroll
                for (int mt = 0; mt < 2; mt++) {
                    mma_bf16(acc[mt][nt0], ah[mt], bh0, bh1);
                    mma_bf16(acc[mt][nt1], ah[mt], bh2, bh3);
                }
                #pragma unroll
                for (int mt = 0; mt < 2; mt++) {
                    mma_bf16(acc[mt][nt0], al[mt], bh0, bh1);
                    mma_bf16(acc[mt][nt1], al[mt], bh2, bh3);
                }
                #pragma unroll
                for (int mt = 0; mt < 2; mt++) {
                    mma_bf16(acc[mt][nt0], ah[mt], bl0, bl1);
                    mma_bf16(acc[mt][nt1], ah[mt], bl2, bl3);
                }
            }
        }
        __syncthreads();
    }

    // epilogue: split O to bf16 hi/lo at [b, n, h*64+d]
    #pragma unroll
    for (int mt = 0; mt < 2; mt++) {
        const int r = n0 + wr * 32 + mt * 16 + (lane >> 2);
        #pragma unroll
        for (int nt = 0; nt < 4; nt++) {
            const int c = wc * 32 + nt * 8 + 2 * (lane & 3);
            float2 v0 = make_float2(acc[mt][nt][0], acc[mt][nt][1]);
            float2 v1 = make_float2(acc[mt][nt][2], acc[mt][nt][3]);
            __nv_bfloat162 hh, ll;
            size_t i0 = ((size_t)(b * SEQ + r)) * INNER + h * HDIM + c;
            split2(v0, hh, ll);
            *(__nv_bfloat162*)&g_oh[i0] = hh;
            *(__nv_bfloat162*)&g_ol[i0] = ll;
            size_t i1 = ((size_t)(b * SEQ + r + 8)) * INNER + h * HDIM + c;
            split2(v1, hh, ll);
            *(__nv_bfloat162*)&g_oh[i1] = hh;
            *(__nv_bfloat162*)&g_ol[i1] = ll;
        }
    }
}

// =========================================================================
extern "C" void kernel_launch(void* const* d_in, const int* in_sizes, int n_in,
                              void* d_out, int out_size)
{
    const float* x     = (const float*)d_in[0];
    const float* w_qkv = (const float*)d_in[1];
    const float* w_out = (const float*)d_in[2];
    const float* b_out = (const float*)d_in[3];
    float* out = (float*)d_out;

    cudaFuncSetAttribute(hmma_gemm_kernel,
                         cudaFuncAttributeMaxDynamicSharedMemorySize, HM_SMEM_BYTES);
    cudaFuncSetAttribute(score_hmma_kernel,
                         cudaFuncAttributeMaxDynamicSharedMemorySize, SC_SMEM_BYTES);
    cudaFuncSetAttribute(av_hmma_kernel,
                         cudaFuncAttributeMaxDynamicSharedMemorySize, AV_SMEM_BYTES);

    bf16 *xh, *xl, *wqh, *wql, *woh, *wol, *oh, *ol;
    cudaGetSymbolAddress((void**)&xh,  g_xh);
    cudaGetSymbolAddress((void**)&xl,  g_xl);
    cudaGetSymbolAddress((void**)&wqh, g_wqh);
    cudaGetSymbolAddress((void**)&wql, g_wql);
    cudaGetSymbolAddress((void**)&woh, g_woh);
    cudaGetSymbolAddress((void**)&wol, g_wol);
    cudaGetSymbolAddress((void**)&oh,  g_oh);
    cudaGetSymbolAddress((void**)&ol,  g_ol);

    // Prep
    {
        int n4 = BATCH * SEQ * DIM / 4;
        split_kernel<<<(n4 + 255) / 256, 256>>>(x, xh, xl, n4);
    }
    {
        dim3 grid(TRIPLE / 32, DIM / 32);
        transpose_split_kernel<<<grid, dim3(32, 8)>>>(w_qkv, wqh, wql, DIM, TRIPLE);
    }
    {
        dim3 grid(DIM / 32, INNER / 32);
        transpose_split_kernel<<<grid, dim3(32, 8)>>>(w_out, woh, wol, INNER, DIM);
    }

    // K1: QKV projection (HMMA) -> q/k/v bf16 hi/lo
    {
        dim3 grid(TRIPLE / 128, (BATCH * SEQ) / 128);
        hmma_gemm_kernel<<<grid, 256, HM_SMEM_BYTES>>>(xh, xl, wqh, wql, nullptr, nullptr, 0);
    }
    // K2: scores -> exp (HMMA)
    {
        dim3 grid(SEQ / 128, SEQ / 128, BATCH * HEADS);
        score_hmma_kernel<<<grid, 256, SC_SMEM_BYTES>>>();
    }
    // K3: normalize over heads -> P hi/lo
    {
        int total = BATCH * SEQ * (SEQ / 4);
        norm_kernel<<<total / 256, 256>>>();
    }
    // K4: O = P @ V (HMMA) -> O hi/lo
    {
        dim3 grid(SEQ / 128, BATCH * HEADS);
        av_hmma_kernel<<<grid, 256, AV_SMEM_BYTES>>>();
    }
    // K5: output projection (HMMA) + bias
    {
        dim3 grid(DIM / 128, (BATCH * SEQ) / 128);
        hmma_gemm_kernel<<<grid, 256, HM_SMEM_BYTES>>>(oh, ol, woh, wol, b_out, out, 1);
    }
}

// round 6
// speedup vs baseline: 2.2316x; 1.0730x over previous
#include <cuda_runtime.h>
#include <cuda_bf16.h>
#include <cstdint>

// Problem constants
#define BATCH   8
#define SEQ     1024
#define DIM     768
#define HEADS   12
#define HDIM    64
#define INNER   768
#define TRIPLE  2304
#define SCALE   0.125f

typedef __nv_bfloat16 bf16;

// ---------------- static scratch ----------------
__device__ __align__(128) float g_s[(size_t)BATCH * HEADS * SEQ * SEQ];   // E (fp32)

// bf16 hi/lo split tensors
__device__ __align__(128) bf16 g_xh[BATCH * SEQ * DIM];
__device__ __align__(128) bf16 g_xl[BATCH * SEQ * DIM];
__device__ __align__(128) bf16 g_wqh[TRIPLE * DIM];
__device__ __align__(128) bf16 g_wql[TRIPLE * DIM];
__device__ __align__(128) bf16 g_woh[DIM * INNER];
__device__ __align__(128) bf16 g_wol[DIM * INNER];
__device__ __align__(128) bf16 g_qh[BATCH * HEADS * SEQ * HDIM];
__device__ __align__(128) bf16 g_ql[BATCH * HEADS * SEQ * HDIM];
__device__ __align__(128) bf16 g_kh[BATCH * HEADS * SEQ * HDIM];
__device__ __align__(128) bf16 g_kl[BATCH * HEADS * SEQ * HDIM];
__device__ __align__(128) bf16 g_vh[BATCH * HEADS * SEQ * HDIM];
__device__ __align__(128) bf16 g_vl[BATCH * HEADS * SEQ * HDIM];
__device__ __align__(128) bf16 g_ph[(size_t)BATCH * HEADS * SEQ * SEQ];  // P hi
__device__ __align__(128) bf16 g_pl[(size_t)BATCH * HEADS * SEQ * SEQ];  // P lo
__device__ __align__(128) bf16 g_oh[BATCH * SEQ * INNER];
__device__ __align__(128) bf16 g_ol[BATCH * SEQ * INNER];

// ================= helpers =================
__device__ __forceinline__ uint32_t smem_to_u32(const void* p) {
    uint32_t a;
    asm("{ .reg .u64 t; cvta.to.shared.u64 t, %1; cvt.u32.u64 %0, t; }"
        : "=r"(a) : "l"(p));
    return a;
}
__device__ __forceinline__ void ldmatrix_x4(uint32_t& r0, uint32_t& r1,
                                            uint32_t& r2, uint32_t& r3,
                                            uint32_t addr) {
    asm volatile("ldmatrix.sync.aligned.m8n8.x4.shared.b16 {%0,%1,%2,%3}, [%4];"
                 : "=r"(r0), "=r"(r1), "=r"(r2), "=r"(r3) : "r"(addr));
}
__device__ __forceinline__ void ldmatrix_x4_trans(uint32_t& r0, uint32_t& r1,
                                                  uint32_t& r2, uint32_t& r3,
                                                  uint32_t addr) {
    asm volatile("ldmatrix.sync.aligned.m8n8.x4.trans.shared.b16 {%0,%1,%2,%3}, [%4];"
                 : "=r"(r0), "=r"(r1), "=r"(r2), "=r"(r3) : "r"(addr));
}
__device__ __forceinline__ void mma_bf16(float* c, const uint32_t* a,
                                         uint32_t b0, uint32_t b1) {
    asm volatile("mma.sync.aligned.m16n8k16.row.col.f32.bf16.bf16.f32 "
                 "{%0,%1,%2,%3}, {%4,%5,%6,%7}, {%8,%9}, {%0,%1,%2,%3};"
                 : "+f"(c[0]), "+f"(c[1]), "+f"(c[2]), "+f"(c[3])
                 : "r"(a[0]), "r"(a[1]), "r"(a[2]), "r"(a[3]),
                   "r"(b0), "r"(b1));
}
#define CP_ASYNC16(sa, g) \
    asm volatile("cp.async.cg.shared.global [%0], [%1], 16;" :: "r"(sa), "l"(g))
#define CP_COMMIT() asm volatile("cp.async.commit_group;" ::: "memory")
#define CP_WAIT1()  asm volatile("cp.async.wait_group 1;" ::: "memory")
#define CP_WAIT0()  asm volatile("cp.async.wait_group 0;" ::: "memory")

__device__ __forceinline__ float fast_exp(float x) {
    const float LOG2E = 1.4426950408889634f;
    const float MAGIC = 12582912.0f;
    float z = fmaf(x, LOG2E, MAGIC);
    int   e = __float_as_int(z) - 0x4B400000;
    float i = z - MAGIC;
    float f = fmaf(x, LOG2E, -i);
    float p = 1.5403531e-4f;
    p = fmaf(p, f, 1.3333558e-3f);
    p = fmaf(p, f, 9.6181291e-3f);
    p = fmaf(p, f, 5.5504109e-2f);
    p = fmaf(p, f, 2.4022651e-1f);
    p = fmaf(p, f, 6.9314718e-1f);
    p = fmaf(p, f, 1.0f);
    return __int_as_float(__float_as_int(p) + (e << 23));
}
__device__ __forceinline__ void split2(float2 v, __nv_bfloat162& h, __nv_bfloat162& l) {
    bf16 hx = __float2bfloat16(v.x), hy = __float2bfloat16(v.y);
    h = __nv_bfloat162(hx, hy);
    l = __nv_bfloat162(__float2bfloat16(v.x - __bfloat162float(hx)),
                       __float2bfloat16(v.y - __bfloat162float(hy)));
}

// =========================================================================
// Prep kernels
// =========================================================================
__global__ __launch_bounds__(256) void split_kernel(
    const float* __restrict__ in, bf16* __restrict__ hi, bf16* __restrict__ lo, int n4)
{
    int i = blockIdx.x * 256 + threadIdx.x;
    if (i >= n4) return;
    float4 v = ((const float4*)in)[i];
    __nv_bfloat162 h0, l0, h1, l1;
    split2(make_float2(v.x, v.y), h0, l0);
    split2(make_float2(v.z, v.w), h1, l1);
    __nv_bfloat162* H = (__nv_bfloat162*)hi;
    __nv_bfloat162* L = (__nv_bfloat162*)lo;
    H[2 * i] = h0; H[2 * i + 1] = h1;
    L[2 * i] = l0; L[2 * i + 1] = l1;
}

__global__ __launch_bounds__(256) void transpose_split_kernel(
    const float* __restrict__ in, bf16* __restrict__ oh, bf16* __restrict__ ol,
    int R, int C)
{
    __shared__ float t[32][33];
    const int tx = threadIdx.x, ty = threadIdx.y;
    const int bx = blockIdx.x, by = blockIdx.y;
    #pragma unroll
    for (int i = 0; i < 4; i++) {
        int r = by * 32 + ty + i * 8;
        t[ty + i * 8][tx] = in[(size_t)r * C + bx * 32 + tx];
    }
    __syncthreads();
    #pragma unroll
    for (int i = 0; i < 4; i++) {
        int c = bx * 32 + ty + i * 8;
        int r = by * 32 + tx;
        float v = t[tx][ty + i * 8];
        bf16 h = __float2bfloat16(v);
        bf16 l = __float2bfloat16(v - __bfloat162float(h));
        oh[(size_t)c * R + r] = h;
        ol[(size_t)c * R + r] = l;
    }
}

// =========================================================================
// HMMA GEMM (hi/lo 3-MMA). 128x128x32 tiles, 8 warps, warp 32x64.
// mode 0: qkv — epilogue splits to q/k/v bf16 hi/lo head-major (q pre-scaled).
// mode 1: oproj — epilogue adds bias, writes fp32 out.
// =========================================================================
#define GS 40
#define MAT_ELEMS (128 * GS)
#define BUF_ELEMS (4 * MAT_ELEMS)
#define HM_SMEM_BYTES (2 * BUF_ELEMS * 2)   // 81920

__global__ __launch_bounds__(256, 2) void hmma_gemm_kernel(
    const bf16* __restrict__ Ah, const bf16* __restrict__ Al,
    const bf16* __restrict__ Bh, const bf16* __restrict__ Bl,
    const float* __restrict__ bias, float* __restrict__ outp, int mode)
{
    extern __shared__ bf16 sm[];
    const int tid = threadIdx.x, lane = tid & 31, wid = tid >> 5;
    const int wr = wid >> 1, wc = wid & 1;
    const int bn = blockIdx.x * 128, bm = blockIdx.y * 128;
    const uint32_t smem_base = smem_to_u32(sm);

    const int row0 = tid >> 2;
    const int row1 = row0 + 64;
    const int ch = tid & 3;

    const bf16* srcs[4] = {Ah, Al, Bh, Bl};
    const int rb[4] = {bm, bm, bn, bn};

    float acc[2][8][4] = {};

    auto issue = [&](int it, int b) {
        const int k0 = it * 32;
        #pragma unroll
        for (int m = 0; m < 4; m++) {
            const bf16* s = srcs[m];
            const bf16* g0 = s + (size_t)(rb[m] + row0) * DIM + k0 + ch * 8;
            const bf16* g1 = s + (size_t)(rb[m] + row1) * DIM + k0 + ch * 8;
            uint32_t d0 = smem_base + (uint32_t)(b * BUF_ELEMS + m * MAT_ELEMS + row0 * GS + ch * 8) * 2;
            uint32_t d1 = smem_base + (uint32_t)(b * BUF_ELEMS + m * MAT_ELEMS + row1 * GS + ch * 8) * 2;
            CP_ASYNC16(d0, g0);
            CP_ASYNC16(d1, g1);
        }
        CP_COMMIT();
    };

    issue(0, 0);
    const int NIT = DIM / 32;

    for (int it = 0; it < NIT; ++it) {
        const int b = it & 1;
        if (it + 1 < NIT) { issue(it + 1, b ^ 1); CP_WAIT1(); }
        else              { CP_WAIT0(); }
        __syncthreads();

        const uint32_t bufb = smem_base + (uint32_t)(b * BUF_ELEMS) * 2;
        #pragma unroll
        for (int ks = 0; ks < 2; ks++) {
            const uint32_t col = ks * 16 + (lane >> 4) * 8;
            uint32_t ah[2][4], al[2][4];
            #pragma unroll
            for (int mt = 0; mt < 2; mt++) {
                uint32_t r = wr * 32 + mt * 16 + (lane & 15);
                ldmatrix_x4(ah[mt][0], ah[mt][1], ah[mt][2], ah[mt][3],
                            bufb + (0 * MAT_ELEMS + r * GS + col) * 2);
                ldmatrix_x4(al[mt][0], al[mt][1], al[mt][2], al[mt][3],
                            bufb + (1 * MAT_ELEMS + r * GS + col) * 2);
            }
            #pragma unroll
            for (int p = 0; p < 4; p++) {
                uint32_t r = wc * 64 + p * 16 + (lane & 15);
                uint32_t bh0, bh1, bh2, bh3, bl0, bl1, bl2, bl3;
                ldmatrix_x4(bh0, bh1, bh2, bh3,
                            bufb + (2 * MAT_ELEMS + r * GS + col) * 2);
                ldmatrix_x4(bl0, bl1, bl2, bl3,
                            bufb + (3 * MAT_ELEMS + r * GS + col) * 2);
                #pragma unroll
                for (int mt = 0; mt < 2; mt++) {
                    mma_bf16(acc[mt][2 * p + 0], ah[mt], bh0, bh2);
                    mma_bf16(acc[mt][2 * p + 1], ah[mt], bh1, bh3);
                }
                #pragma unroll
                for (int mt = 0; mt < 2; mt++) {
                    mma_bf16(acc[mt][2 * p + 0], al[mt], bh0, bh2);
                    mma_bf16(acc[mt][2 * p + 1], al[mt], bh1, bh3);
                }
                #pragma unroll
                for (int mt = 0; mt < 2; mt++) {
                    mma_bf16(acc[mt][2 * p + 0], ah[mt], bl0, bl2);
                    mma_bf16(acc[mt][2 * p + 1], ah[mt], bl1, bl3);
                }
            }
        }
        __syncthreads();
    }

    // ---- epilogue ----
    #pragma unroll
    for (int mt = 0; mt < 2; mt++) {
        const int r = bm + wr * 32 + mt * 16 + (lane >> 2);
        #pragma unroll
        for (int nt = 0; nt < 8; nt++) {
            const int c = bn + wc * 64 + nt * 8 + 2 * (lane & 3);
            float2 v0 = make_float2(acc[mt][nt][0], acc[mt][nt][1]);
            float2 v1 = make_float2(acc[mt][nt][2], acc[mt][nt][3]);
            if (mode == 0) {
                int chunk = c / INNER;
                int e = c % INNER;
                int h = e >> 6, d = e & 63;
                bf16 *dh, *dl;
                if (chunk == 0) {
                    dh = g_qh; dl = g_ql;
                    // fold attention SCALE into Q (exact: power of two)
                    v0.x *= SCALE; v0.y *= SCALE;
                    v1.x *= SCALE; v1.y *= SCALE;
                }
                else if (chunk == 1) { dh = g_kh; dl = g_kl; }
                else                 { dh = g_vh; dl = g_vl; }
                __nv_bfloat162 hh, ll;
                int b0 = r >> 10, n0 = r & 1023;
                size_t i0 = (((size_t)(b0 * HEADS + h) * SEQ) + n0) * HDIM + d;
                split2(v0, hh, ll);
                *(__nv_bfloat162*)&dh[i0] = hh;
                *(__nv_bfloat162*)&dl[i0] = ll;
                int r2 = r + 8;
                int b1 = r2 >> 10, n1 = r2 & 1023;
                size_t i1 = (((size_t)(b1 * HEADS + h) * SEQ) + n1) * HDIM + d;
                split2(v1, hh, ll);
                *(__nv_bfloat162*)&dh[i1] = hh;
                *(__nv_bfloat162*)&dl[i1] = ll;
            } else {
                float2 bq = *(const float2*)&bias[c];
                v0.x += bq.x; v0.y += bq.y;
                v1.x += bq.x; v1.y += bq.y;
                *(float2*)&outp[(size_t)r * DIM + c] = v0;
                *(float2*)&outp[(size_t)(r + 8) * DIM + c] = v1;
            }
        }
    }
}

// =========================================================================
// Score HMMA: E[b,h,n,m] = exp(Q . K) per (b,h), 128x128 tile, K=64.
// (SCALE pre-folded into Q.)
// =========================================================================
#define SGS 72
#define SC_MAT (128 * SGS)
#define SC_SMEM_BYTES (4 * SC_MAT * 2)   // 73728

__global__ __launch_bounds__(256, 2) void score_hmma_kernel()
{
    extern __shared__ bf16 sm[];
    const int tid = threadIdx.x, lane = tid & 31, wid = tid >> 5;
    const int wr = wid >> 1, wc = wid & 1;
    const int bh = blockIdx.z;
    const int n0 = blockIdx.y * 128;
    const int m0 = blockIdx.x * 128;
    const uint32_t smem_base = smem_to_u32(sm);

    const bf16* srcs[4] = {
        g_qh + ((size_t)bh * SEQ + n0) * HDIM,
        g_ql + ((size_t)bh * SEQ + n0) * HDIM,
        g_kh + ((size_t)bh * SEQ + m0) * HDIM,
        g_kl + ((size_t)bh * SEQ + m0) * HDIM
    };
    #pragma unroll
    for (int m = 0; m < 4; m++) {
        #pragma unroll
        for (int t = 0; t < 4; t++) {
            int i = tid + t * 256;
            int row = i >> 3, ch = i & 7;
            *(uint4*)&sm[m * SC_MAT + row * SGS + ch * 8] =
                *(const uint4*)(srcs[m] + (size_t)row * HDIM + ch * 8);
        }
    }
    __syncthreads();

    float acc[2][8][4] = {};

    #pragma unroll
    for (int ks = 0; ks < 4; ks++) {
        const uint32_t col = ks * 16 + (lane >> 4) * 8;
        uint32_t ah[2][4], al[2][4];
        #pragma unroll
        for (int mt = 0; mt < 2; mt++) {
            uint32_t r = wr * 32 + mt * 16 + (lane & 15);
            ldmatrix_x4(ah[mt][0], ah[mt][1], ah[mt][2], ah[mt][3],
                        smem_base + (0 * SC_MAT + r * SGS + col) * 2);
            ldmatrix_x4(al[mt][0], al[mt][1], al[mt][2], al[mt][3],
                        smem_base + (1 * SC_MAT + r * SGS + col) * 2);
        }
        #pragma unroll
        for (int p = 0; p < 4; p++) {
            uint32_t r = wc * 64 + p * 16 + (lane & 15);
            uint32_t bh0, bh1, bh2, bh3, bl0, bl1, bl2, bl3;
            ldmatrix_x4(bh0, bh1, bh2, bh3,
                        smem_base + (2 * SC_MAT + r * SGS + col) * 2);
            ldmatrix_x4(bl0, bl1, bl2, bl3,
                        smem_base + (3 * SC_MAT + r * SGS + col) * 2);
            #pragma unroll
            for (int mt = 0; mt < 2; mt++) {
                mma_bf16(acc[mt][2 * p + 0], ah[mt], bh0, bh2);
                mma_bf16(acc[mt][2 * p + 1], ah[mt], bh1, bh3);
            }
            #pragma unroll
            for (int mt = 0; mt < 2; mt++) {
                mma_bf16(acc[mt][2 * p + 0], al[mt], bh0, bh2);
                mma_bf16(acc[mt][2 * p + 1], al[mt], bh1, bh3);
            }
            #pragma unroll
            for (int mt = 0; mt < 2; mt++) {
                mma_bf16(acc[mt][2 * p + 0], ah[mt], bl0, bl2);
                mma_bf16(acc[mt][2 * p + 1], ah[mt], bl1, bl3);
            }
        }
    }

    // epilogue: exp + store fp32 E
    float* sbase = g_s + (size_t)bh * SEQ * SEQ;
    #pragma unroll
    for (int mt = 0; mt < 2; mt++) {
        const int r = n0 + wr * 32 + mt * 16 + (lane >> 2);
        #pragma unroll
        for (int nt = 0; nt < 8; nt++) {
            const int c = m0 + wc * 64 + nt * 8 + 2 * (lane & 3);
            float2 e0 = make_float2(fast_exp(acc[mt][nt][0]),
                                    fast_exp(acc[mt][nt][1]));
            float2 e1 = make_float2(fast_exp(acc[mt][nt][2]),
                                    fast_exp(acc[mt][nt][3]));
            *(float2*)&sbase[(size_t)r * SEQ + c] = e0;
            *(float2*)&sbase[(size_t)(r + 8) * SEQ + c] = e1;
        }
    }
}

// =========================================================================
// Norm: P = E / sum_h E ; write P as bf16 hi/lo.
// =========================================================================
__global__ __launch_bounds__(256) void norm_kernel()
{
    size_t idx = (size_t)blockIdx.x * 256 + threadIdx.x;  // < 2M
    int m4 = idx & 255;
    int n = (idx >> 8) & 1023;
    int b = (int)(idx >> 18);

    const float4* base = (const float4*)g_s;
    float4 v[HEADS];
    float4 s = make_float4(0.f, 0.f, 0.f, 0.f);
    #pragma unroll
    for (int h = 0; h < HEADS; h++) {
        size_t off = ((size_t)(b * HEADS + h) * SEQ + n) * (SEQ / 4) + m4;
        v[h] = base[off];
        s.x += v[h].x; s.y += v[h].y; s.z += v[h].z; s.w += v[h].w;
    }
    float rx = 1.0f / s.x, ry = 1.0f / s.y, rz = 1.0f / s.z, rw = 1.0f / s.w;
    #pragma unroll
    for (int h = 0; h < HEADS; h++) {
        size_t off = ((size_t)(b * HEADS + h) * SEQ + n) * (SEQ / 4) + m4;
        float2 p0 = make_float2(v[h].x * rx, v[h].y * ry);
        float2 p1 = make_float2(v[h].z * rz, v[h].w * rw);
        __nv_bfloat162 h0, l0, h1, l1;
        split2(p0, h0, l0);
        split2(p1, h1, l1);
        *(__nv_bfloat162*)&g_ph[off * 4]     = h0;
        *(__nv_bfloat162*)&g_ph[off * 4 + 2] = h1;
        *(__nv_bfloat162*)&g_pl[off * 4]     = l0;
        *(__nv_bfloat162*)&g_pl[off * 4 + 2] = l1;
    }
}

// =========================================================================
// AV HMMA: O = P @ V per (b,h). 128(n) x 64(d) tile, K=1024 in 32-chunks.
// =========================================================================
#define AGS 40
#define VGS 72
#define AV_P_ELEMS (128 * AGS)
#define AV_V_ELEMS (32 * VGS)
#define AV_STAGE (2 * AV_P_ELEMS + 2 * AV_V_ELEMS)
#define AV_SMEM_BYTES (2 * AV_STAGE * 2)             // 59392

__global__ __launch_bounds__(256, 2) void av_hmma_kernel()
{
    extern __shared__ bf16 sm[];
    const int tid = threadIdx.x, lane = tid & 31, wid = tid >> 5;
    const int wr = wid >> 1, wc = wid & 1;
    const int n0 = blockIdx.x * 128;
    const int bh = blockIdx.y;
    const int b = bh / HEADS, h = bh % HEADS;
    const uint32_t smem_base = smem_to_u32(sm);

    const bf16* php = g_ph + ((size_t)bh * SEQ + n0) * SEQ;
    const bf16* plp = g_pl + ((size_t)bh * SEQ + n0) * SEQ;
    const bf16* vhp = g_vh + (size_t)bh * SEQ * HDIM;
    const bf16* vlp = g_vl + (size_t)bh * SEQ * HDIM;

    float acc[2][4][4] = {};

    auto issue = [&](int it, int bb) {
        const int k0 = it * 32;
        const uint32_t sb = smem_base + (uint32_t)(bb * AV_STAGE) * 2;
        #pragma unroll
        for (int t = 0; t < 2; t++) {
            int i = tid + t * 256;
            int row = i >> 2, ch = i & 3;
            uint32_t doff = (uint32_t)(row * AGS + ch * 8) * 2;
            CP_ASYNC16(sb + doff,
                       php + (size_t)row * SEQ + k0 + ch * 8);
            CP_ASYNC16(sb + (uint32_t)AV_P_ELEMS * 2 + doff,
                       plp + (size_t)row * SEQ + k0 + ch * 8);
        }
        {
            int row = tid >> 3, ch = tid & 7;
            uint32_t doff = (uint32_t)(row * VGS + ch * 8) * 2;
            CP_ASYNC16(sb + (uint32_t)(2 * AV_P_ELEMS) * 2 + doff,
                       vhp + (size_t)(k0 + row) * HDIM + ch * 8);
            CP_ASYNC16(sb + (uint32_t)(2 * AV_P_ELEMS + AV_V_ELEMS) * 2 + doff,
                       vlp + (size_t)(k0 + row) * HDIM + ch * 8);
        }
        CP_COMMIT();
    };

    issue(0, 0);
    const int NIT = SEQ / 32;

    for (int it = 0; it < NIT; ++it) {
        const int bb = it & 1;
        if (it + 1 < NIT) { issue(it + 1, bb ^ 1); CP_WAIT1(); }
        else              { CP_WAIT0(); }
        __syncthreads();

        const uint32_t sb = smem_base + (uint32_t)(bb * AV_STAGE) * 2;
        const uint32_t vhb = sb + (uint32_t)(2 * AV_P_ELEMS) * 2;
        const uint32_t vlb = vhb + (uint32_t)AV_V_ELEMS * 2;

        #pragma unroll
        for (int ks = 0; ks < 2; ks++) {
            const uint32_t colA = ks * 16 + (lane >> 4) * 8;
            uint32_t ah[2][4], al[2][4];
            #pragma unroll
            for (int mt = 0; mt < 2; mt++) {
                uint32_t r = wr * 32 + mt * 16 + (lane & 15);
                ldmatrix_x4(ah[mt][0], ah[mt][1], ah[mt][2], ah[mt][3],
                            sb + (r * AGS + colA) * 2);
                ldmatrix_x4(al[mt][0], al[mt][1], al[mt][2], al[mt][3],
                            sb + (uint32_t)AV_P_ELEMS * 2 + (r * AGS + colA) * 2);
            }
            const uint32_t kb = ks * 16;
            #pragma unroll
            for (int nb = 0; nb < 2; nb++) {
                const uint32_t d0 = wc * 32 + nb * 16;
                uint32_t vrow = kb + (lane & 7) + ((lane >> 3) & 1) * 8;
                uint32_t vcol = d0 + (lane >> 4) * 8;
                uint32_t bh0, bh1, bh2, bh3, bl0, bl1, bl2, bl3;
                ldmatrix_x4_trans(bh0, bh1, bh2, bh3, vhb + (vrow * VGS + vcol) * 2);
                ldmatrix_x4_trans(bl0, bl1, bl2, bl3, vlb + (vrow * VGS + vcol) * 2);
                const int nt0 = nb * 2, nt1 = nb * 2 + 1;
                #pragma unroll
                for (int mt = 0; mt < 2; mt++) {
                    mma_bf16(acc[mt][nt0], ah[mt], bh0, bh1);
                    mma_bf16(acc[mt][nt1], ah[mt], bh2, bh3);
                }
                #pragma unroll
                for (int mt = 0; mt < 2; mt++) {
                    mma_bf16(acc[mt][nt0], al[mt], bh0, bh1);
                    mma_bf16(acc[mt][nt1], al[mt], bh2, bh3);
                }
                #pragma unroll
                for (int mt = 0; mt < 2; mt++) {
                    mma_bf16(acc[mt][nt0], ah[mt], bl0, bl1);
                    mma_bf16(acc[mt][nt1], ah[mt], bl2, bl3);
                }
            }
        }
        __syncthreads();
    }

    #pragma unroll
    for (int mt = 0; mt < 2; mt++) {
        const int r = n0 + wr * 32 + mt * 16 + (lane >> 2);
        #pragma unroll
        for (int nt = 0; nt < 4; nt++) {
            const int c = wc * 32 + nt * 8 + 2 * (lane & 3);
            float2 v0 = make_float2(acc[mt][nt][0], acc[mt][nt][1]);
            float2 v1 = make_float2(acc[mt][nt][2], acc[mt][nt][3]);
            __nv_bfloat162 hh, ll;
            size_t i0 = ((size_t)(b * SEQ + r)) * INNER + h * HDIM + c;
            split2(v0, hh, ll);
            *(__nv_bfloat162*)&g_oh[i0] = hh;
            *(__nv_bfloat162*)&g_ol[i0] = ll;
            size_t i1 = ((size_t)(b * SEQ + r + 8)) * INNER + h * HDIM + c;
            split2(v1, hh, ll);
            *(__nv_bfloat162*)&g_oh[i1] = hh;
            *(__nv_bfloat162*)&g_ol[i1] = ll;
        }
    }
}

// =========================================================================
extern "C" void kernel_launch(void* const* d_in, const int* in_sizes, int n_in,
                              void* d_out, int out_size)
{
    const float* x     = (const float*)d_in[0];
    const float* w_qkv = (const float*)d_in[1];
    const float* w_out = (const float*)d_in[2];
    const float* b_out = (const float*)d_in[3];
    float* out = (float*)d_out;

    cudaFuncSetAttribute(hmma_gemm_kernel,
                         cudaFuncAttributeMaxDynamicSharedMemorySize, HM_SMEM_BYTES);
    cudaFuncSetAttribute(score_hmma_kernel,
                         cudaFuncAttributeMaxDynamicSharedMemorySize, SC_SMEM_BYTES);
    cudaFuncSetAttribute(av_hmma_kernel,
                         cudaFuncAttributeMaxDynamicSharedMemorySize, AV_SMEM_BYTES);

    bf16 *xh, *xl, *wqh, *wql, *woh, *wol, *oh, *ol;
    cudaGetSymbolAddress((void**)&xh,  g_xh);
    cudaGetSymbolAddress((void**)&xl,  g_xl);
    cudaGetSymbolAddress((void**)&wqh, g_wqh);
    cudaGetSymbolAddress((void**)&wql, g_wql);
    cudaGetSymbolAddress((void**)&woh, g_woh);
    cudaGetSymbolAddress((void**)&wol, g_wol);
    cudaGetSymbolAddress((void**)&oh,  g_oh);
    cudaGetSymbolAddress((void**)&ol,  g_ol);

    // Prep
    {
        int n4 = BATCH * SEQ * DIM / 4;
        split_kernel<<<(n4 + 255) / 256, 256>>>(x, xh, xl, n4);
    }
    {
        dim3 grid(TRIPLE / 32, DIM / 32);
        transpose_split_kernel<<<grid, dim3(32, 8)>>>(w_qkv, wqh, wql, DIM, TRIPLE);
    }
    {
        dim3 grid(DIM / 32, INNER / 32);
        transpose_split_kernel<<<grid, dim3(32, 8)>>>(w_out, woh, wol, INNER, DIM);
    }

    // K1: QKV projection (HMMA) -> q/k/v bf16 hi/lo (q pre-scaled)
    {
        dim3 grid(TRIPLE / 128, (BATCH * SEQ) / 128);
        hmma_gemm_kernel<<<grid, 256, HM_SMEM_BYTES>>>(xh, xl, wqh, wql, nullptr, nullptr, 0);
    }
    // K2: scores -> exp (HMMA)
    {
        dim3 grid(SEQ / 128, SEQ / 128, BATCH * HEADS);
        score_hmma_kernel<<<grid, 256, SC_SMEM_BYTES>>>();
    }
    // K3: normalize over heads -> P hi/lo
    {
        int total = BATCH * SEQ * (SEQ / 4);
        norm_kernel<<<total / 256, 256>>>();
    }
    // K4: O = P @ V (HMMA) -> O hi/lo
    {
        dim3 grid(SEQ / 128, BATCH * HEADS);
        av_hmma_kernel<<<grid, 256, AV_SMEM_BYTES>>>();
    }
    // K5: output projection (HMMA) + bias
    {
        dim3 grid(DIM / 128, (BATCH * SEQ) / 128);
        hmma_gemm_kernel<<<grid, 256, HM_SMEM_BYTES>>>(oh, ol, woh, wol, b_out, out, 1);
    }
}

// round 7
// speedup vs baseline: 2.5413x; 1.1388x over previous
#include <cuda_runtime.h>
#include <cuda_bf16.h>
#include <cuda_fp16.h>
#include <cstdint>

// Problem constants
#define BATCH   8
#define SEQ     1024
#define DIM     768
#define HEADS   12
#define HDIM    64
#define INNER   768
#define TRIPLE  2304
#define SCALE   0.125f

typedef __nv_bfloat16 bf16;
typedef __half f16;

// ---------------- static scratch ----------------
__device__ __align__(128) f16 g_e[(size_t)BATCH * HEADS * SEQ * SEQ];   // E = exp(S)/16 (fp16)
__device__ __align__(128) f16 g_p[(size_t)BATCH * HEADS * SEQ * SEQ];   // P (fp16)

// bf16 hi/lo split tensors (x, weights, q, k, o)
__device__ __align__(128) bf16 g_xh[BATCH * SEQ * DIM];
__device__ __align__(128) bf16 g_xl[BATCH * SEQ * DIM];
__device__ __align__(128) bf16 g_wqh[TRIPLE * DIM];
__device__ __align__(128) bf16 g_wql[TRIPLE * DIM];
__device__ __align__(128) bf16 g_woh[DIM * INNER];
__device__ __align__(128) bf16 g_wol[DIM * INNER];
__device__ __align__(128) bf16 g_qh[BATCH * HEADS * SEQ * HDIM];
__device__ __align__(128) bf16 g_ql[BATCH * HEADS * SEQ * HDIM];
__device__ __align__(128) bf16 g_kh[BATCH * HEADS * SEQ * HDIM];
__device__ __align__(128) bf16 g_kl[BATCH * HEADS * SEQ * HDIM];
__device__ __align__(128) bf16 g_oh[BATCH * SEQ * INNER];
__device__ __align__(128) bf16 g_ol[BATCH * SEQ * INNER];
// fp16 hi/lo V for the fp16 AV MMA
__device__ __align__(128) f16 g_vh16[BATCH * HEADS * SEQ * HDIM];
__device__ __align__(128) f16 g_vl16[BATCH * HEADS * SEQ * HDIM];

// ================= helpers =================
__device__ __forceinline__ uint32_t smem_to_u32(const void* p) {
    uint32_t a;
    asm("{ .reg .u64 t; cvta.to.shared.u64 t, %1; cvt.u32.u64 %0, t; }"
        : "=r"(a) : "l"(p));
    return a;
}
__device__ __forceinline__ void ldmatrix_x4(uint32_t& r0, uint32_t& r1,
                                            uint32_t& r2, uint32_t& r3,
                                            uint32_t addr) {
    asm volatile("ldmatrix.sync.aligned.m8n8.x4.shared.b16 {%0,%1,%2,%3}, [%4];"
                 : "=r"(r0), "=r"(r1), "=r"(r2), "=r"(r3) : "r"(addr));
}
__device__ __forceinline__ void ldmatrix_x4_trans(uint32_t& r0, uint32_t& r1,
                                                  uint32_t& r2, uint32_t& r3,
                                                  uint32_t addr) {
    asm volatile("ldmatrix.sync.aligned.m8n8.x4.trans.shared.b16 {%0,%1,%2,%3}, [%4];"
                 : "=r"(r0), "=r"(r1), "=r"(r2), "=r"(r3) : "r"(addr));
}
__device__ __forceinline__ void mma_bf16(float* c, const uint32_t* a,
                                         uint32_t b0, uint32_t b1) {
    asm volatile("mma.sync.aligned.m16n8k16.row.col.f32.bf16.bf16.f32 "
                 "{%0,%1,%2,%3}, {%4,%5,%6,%7}, {%8,%9}, {%0,%1,%2,%3};"
                 : "+f"(c[0]), "+f"(c[1]), "+f"(c[2]), "+f"(c[3])
                 : "r"(a[0]), "r"(a[1]), "r"(a[2]), "r"(a[3]),
                   "r"(b0), "r"(b1));
}
__device__ __forceinline__ void mma_f16(float* c, const uint32_t* a,
                                        uint32_t b0, uint32_t b1) {
    asm volatile("mma.sync.aligned.m16n8k16.row.col.f32.f16.f16.f32 "
                 "{%0,%1,%2,%3}, {%4,%5,%6,%7}, {%8,%9}, {%0,%1,%2,%3};"
                 : "+f"(c[0]), "+f"(c[1]), "+f"(c[2]), "+f"(c[3])
                 : "r"(a[0]), "r"(a[1]), "r"(a[2]), "r"(a[3]),
                   "r"(b0), "r"(b1));
}
#define CP_ASYNC16(sa, g) \
    asm volatile("cp.async.cg.shared.global [%0], [%1], 16;" :: "r"(sa), "l"(g))
#define CP_COMMIT() asm volatile("cp.async.commit_group;" ::: "memory")
#define CP_WAIT1()  asm volatile("cp.async.wait_group 1;" ::: "memory")
#define CP_WAIT0()  asm volatile("cp.async.wait_group 0;" ::: "memory")

// exp(x) * 2^-4, FMA-pipe only
__device__ __forceinline__ float fast_exp_s(float x) {
    const float LOG2E = 1.4426950408889634f;
    const float MAGIC = 12582912.0f;
    float z = fmaf(x, LOG2E, MAGIC);
    int   e = __float_as_int(z) - 0x4B400000;
    float i = z - MAGIC;
    float f = fmaf(x, LOG2E, -i);
    float p = 1.5403531e-4f;
    p = fmaf(p, f, 1.3333558e-3f);
    p = fmaf(p, f, 9.6181291e-3f);
    p = fmaf(p, f, 5.5504109e-2f);
    p = fmaf(p, f, 2.4022651e-1f);
    p = fmaf(p, f, 6.9314718e-1f);
    p = fmaf(p, f, 1.0f);
    return __int_as_float(__float_as_int(p) + ((e - 4) << 23));
}
__device__ __forceinline__ void split2(float2 v, __nv_bfloat162& h, __nv_bfloat162& l) {
    bf16 hx = __float2bfloat16(v.x), hy = __float2bfloat16(v.y);
    h = __nv_bfloat162(hx, hy);
    l = __nv_bfloat162(__float2bfloat16(v.x - __bfloat162float(hx)),
                       __float2bfloat16(v.y - __bfloat162float(hy)));
}
__device__ __forceinline__ void split2h(float2 v, __half2& h, __half2& l) {
    f16 hx = __float2half_rn(v.x), hy = __float2half_rn(v.y);
    h = __half2(hx, hy);
    l = __half2(__float2half_rn(v.x - __half2float(hx)),
                __float2half_rn(v.y - __half2float(hy)));
}

// =========================================================================
// Prep kernels
// =========================================================================
__global__ __launch_bounds__(256) void split_kernel(
    const float* __restrict__ in, bf16* __restrict__ hi, bf16* __restrict__ lo, int n4)
{
    int i = blockIdx.x * 256 + threadIdx.x;
    if (i >= n4) return;
    float4 v = ((const float4*)in)[i];
    __nv_bfloat162 h0, l0, h1, l1;
    split2(make_float2(v.x, v.y), h0, l0);
    split2(make_float2(v.z, v.w), h1, l1);
    __nv_bfloat162* H = (__nv_bfloat162*)hi;
    __nv_bfloat162* L = (__nv_bfloat162*)lo;
    H[2 * i] = h0; H[2 * i + 1] = h1;
    L[2 * i] = l0; L[2 * i + 1] = l1;
}

__global__ __launch_bounds__(256) void transpose_split_kernel(
    const float* __restrict__ in, bf16* __restrict__ oh, bf16* __restrict__ ol,
    int R, int C)
{
    __shared__ float t[32][33];
    const int tx = threadIdx.x, ty = threadIdx.y;
    const int bx = blockIdx.x, by = blockIdx.y;
    #pragma unroll
    for (int i = 0; i < 4; i++) {
        int r = by * 32 + ty + i * 8;
        t[ty + i * 8][tx] = in[(size_t)r * C + bx * 32 + tx];
    }
    __syncthreads();
    #pragma unroll
    for (int i = 0; i < 4; i++) {
        int c = bx * 32 + ty + i * 8;
        int r = by * 32 + tx;
        float v = t[tx][ty + i * 8];
        bf16 h = __float2bfloat16(v);
        bf16 l = __float2bfloat16(v - __bfloat162float(h));
        oh[(size_t)c * R + r] = h;
        ol[(size_t)c * R + r] = l;
    }
}

// =========================================================================
// HMMA GEMM (hi/lo 3-MMA). 128x128x32 tiles, 8 warps, warp 32x64.
// mode 0: qkv — Q/K bf16 hi/lo (Q pre-scaled by SCALE), V fp16 hi/lo.
// mode 1: oproj — adds bias, writes fp32 out.
// =========================================================================
#define GS 40
#define MAT_ELEMS (128 * GS)
#define BUF_ELEMS (4 * MAT_ELEMS)
#define HM_SMEM_BYTES (2 * BUF_ELEMS * 2)   // 81920

__global__ __launch_bounds__(256, 2) void hmma_gemm_kernel(
    const bf16* __restrict__ Ah, const bf16* __restrict__ Al,
    const bf16* __restrict__ Bh, const bf16* __restrict__ Bl,
    const float* __restrict__ bias, float* __restrict__ outp, int mode)
{
    extern __shared__ bf16 sm[];
    const int tid = threadIdx.x, lane = tid & 31, wid = tid >> 5;
    const int wr = wid >> 1, wc = wid & 1;
    const int bn = blockIdx.x * 128, bm = blockIdx.y * 128;
    const uint32_t smem_base = smem_to_u32(sm);

    const int row0 = tid >> 2;
    const int row1 = row0 + 64;
    const int ch = tid & 3;

    const bf16* srcs[4] = {Ah, Al, Bh, Bl};
    const int rb[4] = {bm, bm, bn, bn};

    float acc[2][8][4] = {};

    auto issue = [&](int it, int b) {
        const int k0 = it * 32;
        #pragma unroll
        for (int m = 0; m < 4; m++) {
            const bf16* s = srcs[m];
            const bf16* g0 = s + (size_t)(rb[m] + row0) * DIM + k0 + ch * 8;
            const bf16* g1 = s + (size_t)(rb[m] + row1) * DIM + k0 + ch * 8;
            uint32_t d0 = smem_base + (uint32_t)(b * BUF_ELEMS + m * MAT_ELEMS + row0 * GS + ch * 8) * 2;
            uint32_t d1 = smem_base + (uint32_t)(b * BUF_ELEMS + m * MAT_ELEMS + row1 * GS + ch * 8) * 2;
            CP_ASYNC16(d0, g0);
            CP_ASYNC16(d1, g1);
        }
        CP_COMMIT();
    };

    issue(0, 0);
    const int NIT = DIM / 32;

    for (int it = 0; it < NIT; ++it) {
        const int b = it & 1;
        if (it + 1 < NIT) { issue(it + 1, b ^ 1); CP_WAIT1(); }
        else              { CP_WAIT0(); }
        __syncthreads();

        const uint32_t bufb = smem_base + (uint32_t)(b * BUF_ELEMS) * 2;
        #pragma unroll
        for (int ks = 0; ks < 2; ks++) {
            const uint32_t col = ks * 16 + (lane >> 4) * 8;
            uint32_t ah[2][4], al[2][4];
            #pragma unroll
            for (int mt = 0; mt < 2; mt++) {
                uint32_t r = wr * 32 + mt * 16 + (lane & 15);
                ldmatrix_x4(ah[mt][0], ah[mt][1], ah[mt][2], ah[mt][3],
                            bufb + (0 * MAT_ELEMS + r * GS + col) * 2);
                ldmatrix_x4(al[mt][0], al[mt][1], al[mt][2], al[mt][3],
                            bufb + (1 * MAT_ELEMS + r * GS + col) * 2);
            }
            #pragma unroll
            for (int p = 0; p < 4; p++) {
                uint32_t r = wc * 64 + p * 16 + (lane & 15);
                uint32_t bh0, bh1, bh2, bh3, bl0, bl1, bl2, bl3;
                ldmatrix_x4(bh0, bh1, bh2, bh3,
                            bufb + (2 * MAT_ELEMS + r * GS + col) * 2);
                ldmatrix_x4(bl0, bl1, bl2, bl3,
                            bufb + (3 * MAT_ELEMS + r * GS + col) * 2);
                #pragma unroll
                for (int mt = 0; mt < 2; mt++) {
                    mma_bf16(acc[mt][2 * p + 0], ah[mt], bh0, bh2);
                    mma_bf16(acc[mt][2 * p + 1], ah[mt], bh1, bh3);
                }
                #pragma unroll
                for (int mt = 0; mt < 2; mt++) {
                    mma_bf16(acc[mt][2 * p + 0], al[mt], bh0, bh2);
                    mma_bf16(acc[mt][2 * p + 1], al[mt], bh1, bh3);
                }
                #pragma unroll
                for (int mt = 0; mt < 2; mt++) {
                    mma_bf16(acc[mt][2 * p + 0], ah[mt], bl0, bl2);
                    mma_bf16(acc[mt][2 * p + 1], ah[mt], bl1, bl3);
                }
            }
        }
        __syncthreads();
    }

    // ---- epilogue ----
    #pragma unroll
    for (int mt = 0; mt < 2; mt++) {
        const int r = bm + wr * 32 + mt * 16 + (lane >> 2);
        #pragma unroll
        for (int nt = 0; nt < 8; nt++) {
            const int c = bn + wc * 64 + nt * 8 + 2 * (lane & 3);
            float2 v0 = make_float2(acc[mt][nt][0], acc[mt][nt][1]);
            float2 v1 = make_float2(acc[mt][nt][2], acc[mt][nt][3]);
            if (mode == 0) {
                int chunk = c / INNER;
                int e = c % INNER;
                int h = e >> 6, d = e & 63;
                int b0 = r >> 10, n0 = r & 1023;
                int r2 = r + 8;
                int b1 = r2 >> 10, n1 = r2 & 1023;
                size_t i0 = (((size_t)(b0 * HEADS + h) * SEQ) + n0) * HDIM + d;
                size_t i1 = (((size_t)(b1 * HEADS + h) * SEQ) + n1) * HDIM + d;
                if (chunk == 2) {
                    // V: fp16 hi/lo for the fp16 AV MMA
                    __half2 hh, ll;
                    split2h(v0, hh, ll);
                    *(__half2*)&g_vh16[i0] = hh;
                    *(__half2*)&g_vl16[i0] = ll;
                    split2h(v1, hh, ll);
                    *(__half2*)&g_vh16[i1] = hh;
                    *(__half2*)&g_vl16[i1] = ll;
                } else {
                    bf16 *dh, *dl;
                    if (chunk == 0) {
                        dh = g_qh; dl = g_ql;
                        v0.x *= SCALE; v0.y *= SCALE;
                        v1.x *= SCALE; v1.y *= SCALE;
                    } else { dh = g_kh; dl = g_kl; }
                    __nv_bfloat162 hh, ll;
                    split2(v0, hh, ll);
                    *(__nv_bfloat162*)&dh[i0] = hh;
                    *(__nv_bfloat162*)&dl[i0] = ll;
                    split2(v1, hh, ll);
                    *(__nv_bfloat162*)&dh[i1] = hh;
                    *(__nv_bfloat162*)&dl[i1] = ll;
                }
            } else {
                float2 bq = *(const float2*)&bias[c];
                v0.x += bq.x; v0.y += bq.y;
                v1.x += bq.x; v1.y += bq.y;
                *(float2*)&outp[(size_t)r * DIM + c] = v0;
                *(float2*)&outp[(size_t)(r + 8) * DIM + c] = v1;
            }
        }
    }
}

// =========================================================================
// Score HMMA: E[b,h,n,m] = exp(Q . K) / 16, stored fp16. 128x128 tile, K=64.
// =========================================================================
#define SGS 72
#define SC_MAT (128 * SGS)
#define SC_SMEM_BYTES (4 * SC_MAT * 2)   // 73728

__global__ __launch_bounds__(256, 2) void score_hmma_kernel()
{
    extern __shared__ bf16 sm[];
    const int tid = threadIdx.x, lane = tid & 31, wid = tid >> 5;
    const int wr = wid >> 1, wc = wid & 1;
    const int bh = blockIdx.z;
    const int n0 = blockIdx.y * 128;
    const int m0 = blockIdx.x * 128;
    const uint32_t smem_base = smem_to_u32(sm);

    const bf16* srcs[4] = {
        g_qh + ((size_t)bh * SEQ + n0) * HDIM,
        g_ql + ((size_t)bh * SEQ + n0) * HDIM,
        g_kh + ((size_t)bh * SEQ + m0) * HDIM,
        g_kl + ((size_t)bh * SEQ + m0) * HDIM
    };
    #pragma unroll
    for (int m = 0; m < 4; m++) {
        #pragma unroll
        for (int t = 0; t < 4; t++) {
            int i = tid + t * 256;
            int row = i >> 3, ch = i & 7;
            *(uint4*)&sm[m * SC_MAT + row * SGS + ch * 8] =
                *(const uint4*)(srcs[m] + (size_t)row * HDIM + ch * 8);
        }
    }
    __syncthreads();

    float acc[2][8][4] = {};

    #pragma unroll
    for (int ks = 0; ks < 4; ks++) {
        const uint32_t col = ks * 16 + (lane >> 4) * 8;
        uint32_t ah[2][4], al[2][4];
        #pragma unroll
        for (int mt = 0; mt < 2; mt++) {
            uint32_t r = wr * 32 + mt * 16 + (lane & 15);
            ldmatrix_x4(ah[mt][0], ah[mt][1], ah[mt][2], ah[mt][3],
                        smem_base + (0 * SC_MAT + r * SGS + col) * 2);
            ldmatrix_x4(al[mt][0], al[mt][1], al[mt][2], al[mt][3],
                        smem_base + (1 * SC_MAT + r * SGS + col) * 2);
        }
        #pragma unroll
        for (int p = 0; p < 4; p++) {
            uint32_t r = wc * 64 + p * 16 + (lane & 15);
            uint32_t bh0, bh1, bh2, bh3, bl0, bl1, bl2, bl3;
            ldmatrix_x4(bh0, bh1, bh2, bh3,
                        smem_base + (2 * SC_MAT + r * SGS + col) * 2);
            ldmatrix_x4(bl0, bl1, bl2, bl3,
                        smem_base + (3 * SC_MAT + r * SGS + col) * 2);
            #pragma unroll
            for (int mt = 0; mt < 2; mt++) {
                mma_bf16(acc[mt][2 * p + 0], ah[mt], bh0, bh2);
                mma_bf16(acc[mt][2 * p + 1], ah[mt], bh1, bh3);
            }
            #pragma unroll
            for (int mt = 0; mt < 2; mt++) {
                mma_bf16(acc[mt][2 * p + 0], al[mt], bh0, bh2);
                mma_bf16(acc[mt][2 * p + 1], al[mt], bh1, bh3);
            }
            #pragma unroll
            for (int mt = 0; mt < 2; mt++) {
                mma_bf16(acc[mt][2 * p + 0], ah[mt], bl0, bl2);
                mma_bf16(acc[mt][2 * p + 1], ah[mt], bl1, bl3);
            }
        }
    }

    // epilogue: exp/16 -> fp16 E
    f16* ebase = g_e + (size_t)bh * SEQ * SEQ;
    #pragma unroll
    for (int mt = 0; mt < 2; mt++) {
        const int r = n0 + wr * 32 + mt * 16 + (lane >> 2);
        #pragma unroll
        for (int nt = 0; nt < 8; nt++) {
            const int c = m0 + wc * 64 + nt * 8 + 2 * (lane & 3);
            __half2 e0 = __floats2half2_rn(fast_exp_s(acc[mt][nt][0]),
                                           fast_exp_s(acc[mt][nt][1]));
            __half2 e1 = __floats2half2_rn(fast_exp_s(acc[mt][nt][2]),
                                           fast_exp_s(acc[mt][nt][3]));
            *(__half2*)&ebase[(size_t)r * SEQ + c] = e0;
            *(__half2*)&ebase[(size_t)(r + 8) * SEQ + c] = e1;
        }
    }
}

// =========================================================================
// Norm: P = E / sum_h E ; fp16 in, fp16 out. 4 m-elements per thread.
// =========================================================================
__global__ __launch_bounds__(256) void norm_kernel()
{
    size_t idx = (size_t)blockIdx.x * 256 + threadIdx.x;  // < 2M
    int m4 = idx & 255;
    int n = (idx >> 8) & 1023;
    int b = (int)(idx >> 18);

    const uint2* E = (const uint2*)g_e;
    uint2* P = (uint2*)g_p;

    float4 v[HEADS];
    float4 s = make_float4(0.f, 0.f, 0.f, 0.f);
    #pragma unroll
    for (int h = 0; h < HEADS; h++) {
        size_t off = ((size_t)(b * HEADS + h) * SEQ + n) * (SEQ / 4) + m4;
        uint2 u = E[off];
        float2 f0 = __half22float2(*(__half2*)&u.x);
        float2 f1 = __half22float2(*(__half2*)&u.y);
        v[h] = make_float4(f0.x, f0.y, f1.x, f1.y);
        s.x += f0.x; s.y += f0.y; s.z += f1.x; s.w += f1.y;
    }
    float rx = 1.0f / s.x, ry = 1.0f / s.y, rz = 1.0f / s.z, rw = 1.0f / s.w;
    #pragma unroll
    for (int h = 0; h < HEADS; h++) {
        size_t off = ((size_t)(b * HEADS + h) * SEQ + n) * (SEQ / 4) + m4;
        uint2 o;
        *(__half2*)&o.x = __floats2half2_rn(v[h].x * rx, v[h].y * ry);
        *(__half2*)&o.y = __floats2half2_rn(v[h].z * rz, v[h].w * rw);
        P[off] = o;
    }
}

// =========================================================================
// AV HMMA (fp16): O = P @ V per (b,h). 128(n) x 64(d), K=1024 in 32-chunks.
// A = P (single fp16); B = V fp16 hi/lo via ldmatrix.trans. 2 MMAs per tile.
// =========================================================================
#define AGS 40
#define VGS 72
#define AV_P_ELEMS (128 * AGS)                     // 5120
#define AV_V_ELEMS (32 * VGS)                      // 2304
#define AV_STAGE (AV_P_ELEMS + 2 * AV_V_ELEMS)     // 9728
#define AV_SMEM_BYTES (2 * AV_STAGE * 2)           // 38912

__global__ __launch_bounds__(256, 2) void av_hmma_kernel()
{
    extern __shared__ f16 smh[];
    const int tid = threadIdx.x, lane = tid & 31, wid = tid >> 5;
    const int wr = wid >> 1, wc = wid & 1;
    const int n0 = blockIdx.x * 128;
    const int bh = blockIdx.y;
    const int b = bh / HEADS, h = bh % HEADS;
    const uint32_t smem_base = smem_to_u32(smh);

    const f16* pp  = g_p    + ((size_t)bh * SEQ + n0) * SEQ;
    const f16* vhp = g_vh16 + (size_t)bh * SEQ * HDIM;
    const f16* vlp = g_vl16 + (size_t)bh * SEQ * HDIM;

    float acc[2][4][4] = {};

    auto issue = [&](int it, int bb) {
        const int k0 = it * 32;
        const uint32_t sb = smem_base + (uint32_t)(bb * AV_STAGE) * 2;
        #pragma unroll
        for (int t = 0; t < 2; t++) {
            int i = tid + t * 256;
            int row = i >> 2, ch = i & 3;
            CP_ASYNC16(sb + (uint32_t)(row * AGS + ch * 8) * 2,
                       pp + (size_t)row * SEQ + k0 + ch * 8);
        }
        {
            int row = tid >> 3, ch = tid & 7;
            uint32_t doff = (uint32_t)(row * VGS + ch * 8) * 2;
            CP_ASYNC16(sb + (uint32_t)AV_P_ELEMS * 2 + doff,
                       vhp + (size_t)(k0 + row) * HDIM + ch * 8);
            CP_ASYNC16(sb + (uint32_t)(AV_P_ELEMS + AV_V_ELEMS) * 2 + doff,
                       vlp + (size_t)(k0 + row) * HDIM + ch * 8);
        }
        CP_COMMIT();
    };

    issue(0, 0);
    const int NIT = SEQ / 32;

    for (int it = 0; it < NIT; ++it) {
        const int bb = it & 1;
        if (it + 1 < NIT) { issue(it + 1, bb ^ 1); CP_WAIT1(); }
        else              { CP_WAIT0(); }
        __syncthreads();

        const uint32_t sb = smem_base + (uint32_t)(bb * AV_STAGE) * 2;
        const uint32_t vhb = sb + (uint32_t)AV_P_ELEMS * 2;
        const uint32_t vlb = vhb + (uint32_t)AV_V_ELEMS * 2;

        #pragma unroll
        for (int ks = 0; ks < 2; ks++) {
            const uint32_t colA = ks * 16 + (lane >> 4) * 8;
            uint32_t a[2][4];
            #pragma unroll
            for (int mt = 0; mt < 2; mt++) {
                uint32_t r = wr * 32 + mt * 16 + (lane & 15);
                ldmatrix_x4(a[mt][0], a[mt][1], a[mt][2], a[mt][3],
                            sb + (r * AGS + colA) * 2);
            }
            const uint32_t kb = ks * 16;
            #pragma unroll
            for (int nb = 0; nb < 2; nb++) {
                const uint32_t d0 = wc * 32 + nb * 16;
                uint32_t vrow = kb + (lane & 7) + ((lane >> 3) & 1) * 8;
                uint32_t vcol = d0 + (lane >> 4) * 8;
                uint32_t bh0, bh1, bh2, bh3, bl0, bl1, bl2, bl3;
                ldmatrix_x4_trans(bh0, bh1, bh2, bh3, vhb + (vrow * VGS + vcol) * 2);
                ldmatrix_x4_trans(bl0, bl1, bl2, bl3, vlb + (vrow * VGS + vcol) * 2);
                const int nt0 = nb * 2, nt1 = nb * 2 + 1;
                #pragma unroll
                for (int mt = 0; mt < 2; mt++) {
                    mma_f16(acc[mt][nt0], a[mt], bh0, bh1);
                    mma_f16(acc[mt][nt1], a[mt], bh2, bh3);
                }
                #pragma unroll
                for (int mt = 0; mt < 2; mt++) {
                    mma_f16(acc[mt][nt0], a[mt], bl0, bl1);
                    mma_f16(acc[mt][nt1], a[mt], bl2, bl3);
                }
            }
        }
        __syncthreads();
    }

    // epilogue: O -> bf16 hi/lo at [b, n, h*64+d]
    #pragma unroll
    for (int mt = 0; mt < 2; mt++) {
        const int r = n0 + wr * 32 + mt * 16 + (lane >> 2);
        #pragma unroll
        for (int nt = 0; nt < 4; nt++) {
            const int c = wc * 32 + nt * 8 + 2 * (lane & 3);
            float2 v0 = make_float2(acc[mt][nt][0], acc[mt][nt][1]);
            float2 v1 = make_float2(acc[mt][nt][2], acc[mt][nt][3]);
            __nv_bfloat162 hh, ll;
            size_t i0 = ((size_t)(b * SEQ + r)) * INNER + h * HDIM + c;
            split2(v0, hh, ll);
            *(__nv_bfloat162*)&g_oh[i0] = hh;
            *(__nv_bfloat162*)&g_ol[i0] = ll;
            size_t i1 = ((size_t)(b * SEQ + r + 8)) * INNER + h * HDIM + c;
            split2(v1, hh, ll);
            *(__nv_bfloat162*)&g_oh[i1] = hh;
            *(__nv_bfloat162*)&g_ol[i1] = ll;
        }
    }
}

// =========================================================================
extern "C" void kernel_launch(void* const* d_in, const int* in_sizes, int n_in,
                              void* d_out, int out_size)
{
    const float* x     = (const float*)d_in[0];
    const float* w_qkv = (const float*)d_in[1];
    const float* w_out = (const float*)d_in[2];
    const float* b_out = (const float*)d_in[3];
    float* out = (float*)d_out;

    cudaFuncSetAttribute(hmma_gemm_kernel,
                         cudaFuncAttributeMaxDynamicSharedMemorySize, HM_SMEM_BYTES);
    cudaFuncSetAttribute(score_hmma_kernel,
                         cudaFuncAttributeMaxDynamicSharedMemorySize, SC_SMEM_BYTES);
    cudaFuncSetAttribute(av_hmma_kernel,
                         cudaFuncAttributeMaxDynamicSharedMemorySize, AV_SMEM_BYTES);

    bf16 *xh, *xl, *wqh, *wql, *woh, *wol, *oh, *ol;
    cudaGetSymbolAddress((void**)&xh,  g_xh);
    cudaGetSymbolAddress((void**)&xl,  g_xl);
    cudaGetSymbolAddress((void**)&wqh, g_wqh);
    cudaGetSymbolAddress((void**)&wql, g_wql);
    cudaGetSymbolAddress((void**)&woh, g_woh);
    cudaGetSymbolAddress((void**)&wol, g_wol);
    cudaGetSymbolAddress((void**)&oh,  g_oh);
    cudaGetSymbolAddress((void**)&ol,  g_ol);

    // Prep
    {
        int n4 = BATCH * SEQ * DIM / 4;
        split_kernel<<<(n4 + 255) / 256, 256>>>(x, xh, xl, n4);
    }
    {
        dim3 grid(TRIPLE / 32, DIM / 32);
        transpose_split_kernel<<<grid, dim3(32, 8)>>>(w_qkv, wqh, wql, DIM, TRIPLE);
    }
    {
        dim3 grid(DIM / 32, INNER / 32);
        transpose_split_kernel<<<grid, dim3(32, 8)>>>(w_out, woh, wol, INNER, DIM);
    }

    // K1: QKV projection (HMMA) -> Q/K bf16 hi/lo (Q pre-scaled), V fp16 hi/lo
    {
        dim3 grid(TRIPLE / 128, (BATCH * SEQ) / 128);
        hmma_gemm_kernel<<<grid, 256, HM_SMEM_BYTES>>>(xh, xl, wqh, wql, nullptr, nullptr, 0);
    }
    // K2: scores -> exp/16 (fp16 E)
    {
        dim3 grid(SEQ / 128, SEQ / 128, BATCH * HEADS);
        score_hmma_kernel<<<grid, 256, SC_SMEM_BYTES>>>();
    }
    // K3: normalize over heads -> P fp16
    {
        int total = BATCH * SEQ * (SEQ / 4);
        norm_kernel<<<total / 256, 256>>>();
    }
    // K4: O = P @ V (fp16 HMMA) -> O bf16 hi/lo
    {
        dim3 grid(SEQ / 128, BATCH * HEADS);
        av_hmma_kernel<<<grid, 256, AV_SMEM_BYTES>>>();
    }
    // K5: output projection (HMMA) + bias
    {
        dim3 grid(DIM / 128, (BATCH * SEQ) / 128);
        hmma_gemm_kernel<<<grid, 256, HM_SMEM_BYTES>>>(oh, ol, woh, wol, b_out, out, 1);
    }
}

// round 8
// speedup vs baseline: 2.8164x; 1.1082x over previous
#include <cuda_runtime.h>
#include <cuda_bf16.h>
#include <cuda_fp16.h>
#include <cstdint>

// Problem constants
#define BATCH   8
#define SEQ     1024
#define DIM     768
#define HEADS   12
#define HDIM    64
#define INNER   768
#define TRIPLE  2304
#define SCALE   0.125f

typedef __nv_bfloat16 bf16;
typedef __half f16;

// ---------------- static scratch ----------------
__device__ __align__(128) f16 g_e[(size_t)BATCH * HEADS * SEQ * SEQ];   // E = exp(S)/16
__device__ __align__(128) f16 g_p[(size_t)BATCH * HEADS * SEQ * SEQ];   // P

__device__ __align__(128) bf16 g_xh[BATCH * SEQ * DIM];
__device__ __align__(128) bf16 g_xl[BATCH * SEQ * DIM];
__device__ __align__(128) bf16 g_wqh[TRIPLE * DIM];
__device__ __align__(128) bf16 g_wql[TRIPLE * DIM];
__device__ __align__(128) bf16 g_woh[DIM * INNER];
__device__ __align__(128) bf16 g_wol[DIM * INNER];
__device__ __align__(128) bf16 g_qh[BATCH * HEADS * SEQ * HDIM];
__device__ __align__(128) bf16 g_ql[BATCH * HEADS * SEQ * HDIM];
__device__ __align__(128) bf16 g_kh[BATCH * HEADS * SEQ * HDIM];
__device__ __align__(128) bf16 g_kl[BATCH * HEADS * SEQ * HDIM];
__device__ __align__(128) bf16 g_oh[BATCH * SEQ * INNER];
__device__ __align__(128) bf16 g_ol[BATCH * SEQ * INNER];
__device__ __align__(128) f16 g_vh16[BATCH * HEADS * SEQ * HDIM];
__device__ __align__(128) f16 g_vl16[BATCH * HEADS * SEQ * HDIM];

// ================= helpers =================
__device__ __forceinline__ uint32_t smem_to_u32(const void* p) {
    uint32_t a;
    asm("{ .reg .u64 t; cvta.to.shared.u64 t, %1; cvt.u32.u64 %0, t; }"
        : "=r"(a) : "l"(p));
    return a;
}
// swizzled byte offset within a [rows x 32 bf16] tile (64B per row):
// chunk c in [0,4) XORed with (row>>1)&3 -> conflict-free ldmatrix & stores.
__device__ __forceinline__ uint32_t swz(uint32_t r, uint32_t c) {
    return (r * 4 + (c ^ ((r >> 1) & 3))) * 16;
}
__device__ __forceinline__ void ldmatrix_x4(uint32_t& r0, uint32_t& r1,
                                            uint32_t& r2, uint32_t& r3,
                                            uint32_t addr) {
    asm volatile("ldmatrix.sync.aligned.m8n8.x4.shared.b16 {%0,%1,%2,%3}, [%4];"
                 : "=r"(r0), "=r"(r1), "=r"(r2), "=r"(r3) : "r"(addr));
}
__device__ __forceinline__ void ldmatrix_x4_trans(uint32_t& r0, uint32_t& r1,
                                                  uint32_t& r2, uint32_t& r3,
                                                  uint32_t addr) {
    asm volatile("ldmatrix.sync.aligned.m8n8.x4.trans.shared.b16 {%0,%1,%2,%3}, [%4];"
                 : "=r"(r0), "=r"(r1), "=r"(r2), "=r"(r3) : "r"(addr));
}
__device__ __forceinline__ void mma_bf16(float* c, const uint32_t* a,
                                         uint32_t b0, uint32_t b1) {
    asm volatile("mma.sync.aligned.m16n8k16.row.col.f32.bf16.bf16.f32 "
                 "{%0,%1,%2,%3}, {%4,%5,%6,%7}, {%8,%9}, {%0,%1,%2,%3};"
                 : "+f"(c[0]), "+f"(c[1]), "+f"(c[2]), "+f"(c[3])
                 : "r"(a[0]), "r"(a[1]), "r"(a[2]), "r"(a[3]),
                   "r"(b0), "r"(b1));
}
__device__ __forceinline__ void mma_f16(float* c, const uint32_t* a,
                                        uint32_t b0, uint32_t b1) {
    asm volatile("mma.sync.aligned.m16n8k16.row.col.f32.f16.f16.f32 "
                 "{%0,%1,%2,%3}, {%4,%5,%6,%7}, {%8,%9}, {%0,%1,%2,%3};"
                 : "+f"(c[0]), "+f"(c[1]), "+f"(c[2]), "+f"(c[3])
                 : "r"(a[0]), "r"(a[1]), "r"(a[2]), "r"(a[3]),
                   "r"(b0), "r"(b1));
}
#define CP_ASYNC16(sa, g) \
    asm volatile("cp.async.cg.shared.global [%0], [%1], 16;" :: "r"(sa), "l"(g))
#define CP_COMMIT() asm volatile("cp.async.commit_group;" ::: "memory")
#define CP_WAIT1()  asm volatile("cp.async.wait_group 1;" ::: "memory")
#define CP_WAIT0()  asm volatile("cp.async.wait_group 0;" ::: "memory")

__device__ __forceinline__ float fast_exp_s(float x) {
    const float LOG2E = 1.4426950408889634f;
    const float MAGIC = 12582912.0f;
    float z = fmaf(x, LOG2E, MAGIC);
    int   e = __float_as_int(z) - 0x4B400000;
    float i = z - MAGIC;
    float f = fmaf(x, LOG2E, -i);
    float p = 1.5403531e-4f;
    p = fmaf(p, f, 1.3333558e-3f);
    p = fmaf(p, f, 9.6181291e-3f);
    p = fmaf(p, f, 5.5504109e-2f);
    p = fmaf(p, f, 2.4022651e-1f);
    p = fmaf(p, f, 6.9314718e-1f);
    p = fmaf(p, f, 1.0f);
    return __int_as_float(__float_as_int(p) + ((e - 4) << 23));
}
__device__ __forceinline__ void split2(float2 v, __nv_bfloat162& h, __nv_bfloat162& l) {
    bf16 hx = __float2bfloat16(v.x), hy = __float2bfloat16(v.y);
    h = __nv_bfloat162(hx, hy);
    l = __nv_bfloat162(__float2bfloat16(v.x - __bfloat162float(hx)),
                       __float2bfloat16(v.y - __bfloat162float(hy)));
}
__device__ __forceinline__ void split2h(float2 v, __half2& h, __half2& l) {
    f16 hx = __float2half_rn(v.x), hy = __float2half_rn(v.y);
    h = __half2(hx, hy);
    l = __half2(__float2half_rn(v.x - __half2float(hx)),
                __float2half_rn(v.y - __half2float(hy)));
}

// =========================================================================
// Prep kernels
// =========================================================================
__global__ __launch_bounds__(256) void split_kernel(
    const float* __restrict__ in, bf16* __restrict__ hi, bf16* __restrict__ lo, int n4)
{
    int i = blockIdx.x * 256 + threadIdx.x;
    if (i >= n4) return;
    float4 v = ((const float4*)in)[i];
    __nv_bfloat162 h0, l0, h1, l1;
    split2(make_float2(v.x, v.y), h0, l0);
    split2(make_float2(v.z, v.w), h1, l1);
    __nv_bfloat162* H = (__nv_bfloat162*)hi;
    __nv_bfloat162* L = (__nv_bfloat162*)lo;
    H[2 * i] = h0; H[2 * i + 1] = h1;
    L[2 * i] = l0; L[2 * i + 1] = l1;
}

__global__ __launch_bounds__(256) void transpose_split_kernel(
    const float* __restrict__ in, bf16* __restrict__ oh, bf16* __restrict__ ol,
    int R, int C)
{
    __shared__ float t[32][33];
    const int tx = threadIdx.x, ty = threadIdx.y;
    const int bx = blockIdx.x, by = blockIdx.y;
    #pragma unroll
    for (int i = 0; i < 4; i++) {
        int r = by * 32 + ty + i * 8;
        t[ty + i * 8][tx] = in[(size_t)r * C + bx * 32 + tx];
    }
    __syncthreads();
    #pragma unroll
    for (int i = 0; i < 4; i++) {
        int c = bx * 32 + ty + i * 8;
        int r = by * 32 + tx;
        float v = t[tx][ty + i * 8];
        bf16 h = __float2bfloat16(v);
        bf16 l = __float2bfloat16(v - __bfloat162float(h));
        oh[(size_t)c * R + r] = h;
        ol[(size_t)c * R + r] = l;
    }
}

// =========================================================================
// HMMA GEMM (hi/lo 3-MMA). 128x128x32 tiles, 8 warps.
// 3-stage cp.async pipeline, 1 barrier/iter, swizzled 64B-row smem tiles.
// mode 0: qkv epilogue; mode 1: oproj + bias.
// =========================================================================
#define MAT_BYTES  8192                 // 128 rows x 32 bf16 (swizzled)
#define STG_BYTES  (4 * MAT_BYTES)      // Ah, Al, Bh, Bl
#define HM_SMEM_BYTES (3 * STG_BYTES)   // 98304

__global__ __launch_bounds__(256, 2) void hmma_gemm_kernel(
    const bf16* __restrict__ Ah, const bf16* __restrict__ Al,
    const bf16* __restrict__ Bh, const bf16* __restrict__ Bl,
    const float* __restrict__ bias, float* __restrict__ outp, int mode)
{
    extern __shared__ bf16 sm[];
    const int tid = threadIdx.x, lane = tid & 31, wid = tid >> 5;
    const int wr = wid >> 1, wc = wid & 1;
    const int bn = blockIdx.x * 128, bm = blockIdx.y * 128;
    const uint32_t smem_base = smem_to_u32(sm);

    const bf16* srcs[4] = {Ah, Al, Bh, Bl};
    const int rb[4] = {bm, bm, bn, bn};

    float acc[2][8][4] = {};

    // per-thread load coords: 512 chunks per matrix, 2 per thread
    const int lr0 = tid >> 2, lr1 = (tid + 256) >> 2;
    const int lc = tid & 3;

    auto issue = [&](int it, int s) {
        const int k0 = it * 32;
        const uint32_t sb = smem_base + (uint32_t)(s * STG_BYTES);
        #pragma unroll
        for (int m = 0; m < 4; m++) {
            const bf16* src = srcs[m];
            CP_ASYNC16(sb + m * MAT_BYTES + swz(lr0, lc),
                       src + (size_t)(rb[m] + lr0) * DIM + k0 + lc * 8);
            CP_ASYNC16(sb + m * MAT_BYTES + swz(lr1, lc),
                       src + (size_t)(rb[m] + lr1) * DIM + k0 + lc * 8);
        }
        CP_COMMIT();
    };

    const int NIT = DIM / 32;   // 24
    issue(0, 0);
    issue(1, 1);

    for (int it = 0; it < NIT; ++it) {
        if (it + 1 < NIT) { CP_WAIT1(); } else { CP_WAIT0(); }
        __syncthreads();
        if (it + 2 < NIT) issue(it + 2, (it + 2) % 3);

        const uint32_t sb = smem_base + (uint32_t)((it % 3) * STG_BYTES);
        #pragma unroll
        for (int ks = 0; ks < 2; ks++) {
            const uint32_t c0 = ks * 2 + (lane >> 4);   // 16B chunk index
            uint32_t ah[2][4], al[2][4];
            #pragma unroll
            for (int mt = 0; mt < 2; mt++) {
                uint32_t r = wr * 32 + mt * 16 + (lane & 15);
                ldmatrix_x4(ah[mt][0], ah[mt][1], ah[mt][2], ah[mt][3],
                            sb + 0 * MAT_BYTES + swz(r, c0));
                ldmatrix_x4(al[mt][0], al[mt][1], al[mt][2], al[mt][3],
                            sb + 1 * MAT_BYTES + swz(r, c0));
            }
            #pragma unroll
            for (int p = 0; p < 4; p++) {
                uint32_t r = wc * 64 + p * 16 + (lane & 15);
                uint32_t bh0, bh1, bh2, bh3, bl0, bl1, bl2, bl3;
                ldmatrix_x4(bh0, bh1, bh2, bh3, sb + 2 * MAT_BYTES + swz(r, c0));
                ldmatrix_x4(bl0, bl1, bl2, bl3, sb + 3 * MAT_BYTES + swz(r, c0));
                #pragma unroll
                for (int mt = 0; mt < 2; mt++) {
                    mma_bf16(acc[mt][2 * p + 0], ah[mt], bh0, bh2);
                    mma_bf16(acc[mt][2 * p + 1], ah[mt], bh1, bh3);
                }
                #pragma unroll
                for (int mt = 0; mt < 2; mt++) {
                    mma_bf16(acc[mt][2 * p + 0], al[mt], bh0, bh2);
                    mma_bf16(acc[mt][2 * p + 1], al[mt], bh1, bh3);
                }
                #pragma unroll
                for (int mt = 0; mt < 2; mt++) {
                    mma_bf16(acc[mt][2 * p + 0], ah[mt], bl0, bl2);
                    mma_bf16(acc[mt][2 * p + 1], ah[mt], bl1, bl3);
                }
            }
        }
    }

    // ---- epilogue ----
    #pragma unroll
    for (int mt = 0; mt < 2; mt++) {
        const int r = bm + wr * 32 + mt * 16 + (lane >> 2);
        #pragma unroll
        for (int nt = 0; nt < 8; nt++) {
            const int c = bn + wc * 64 + nt * 8 + 2 * (lane & 3);
            float2 v0 = make_float2(acc[mt][nt][0], acc[mt][nt][1]);
            float2 v1 = make_float2(acc[mt][nt][2], acc[mt][nt][3]);
            if (mode == 0) {
                int chunk = c / INNER;
                int e = c % INNER;
                int h = e >> 6, d = e & 63;
                int b0 = r >> 10, n0 = r & 1023;
                int r2 = r + 8;
                int b1 = r2 >> 10, n1 = r2 & 1023;
                size_t i0 = (((size_t)(b0 * HEADS + h) * SEQ) + n0) * HDIM + d;
                size_t i1 = (((size_t)(b1 * HEADS + h) * SEQ) + n1) * HDIM + d;
                if (chunk == 2) {
                    __half2 hh, ll;
                    split2h(v0, hh, ll);
                    *(__half2*)&g_vh16[i0] = hh;
                    *(__half2*)&g_vl16[i0] = ll;
                    split2h(v1, hh, ll);
                    *(__half2*)&g_vh16[i1] = hh;
                    *(__half2*)&g_vl16[i1] = ll;
                } else {
                    bf16 *dh, *dl;
                    if (chunk == 0) {
                        dh = g_qh; dl = g_ql;
                        v0.x *= SCALE; v0.y *= SCALE;
                        v1.x *= SCALE; v1.y *= SCALE;
                    } else { dh = g_kh; dl = g_kl; }
                    __nv_bfloat162 hh, ll;
                    split2(v0, hh, ll);
                    *(__nv_bfloat162*)&dh[i0] = hh;
                    *(__nv_bfloat162*)&dl[i0] = ll;
                    split2(v1, hh, ll);
                    *(__nv_bfloat162*)&dh[i1] = hh;
                    *(__nv_bfloat162*)&dl[i1] = ll;
                }
            } else {
                float2 bq = *(const float2*)&bias[c];
                v0.x += bq.x; v0.y += bq.y;
                v1.x += bq.x; v1.y += bq.y;
                *(float2*)&outp[(size_t)r * DIM + c] = v0;
                *(float2*)&outp[(size_t)(r + 8) * DIM + c] = v1;
            }
        }
    }
}

// =========================================================================
// Score HMMA: E = exp(Q.K)/16 (fp16). 128x128 tile, K=64, one-shot loads.
// =========================================================================
#define SGS 72
#define SC_MAT (128 * SGS)
#define SC_SMEM_BYTES (4 * SC_MAT * 2)   // 73728

__global__ __launch_bounds__(256, 2) void score_hmma_kernel()
{
    extern __shared__ bf16 sm[];
    const int tid = threadIdx.x, lane = tid & 31, wid = tid >> 5;
    const int wr = wid >> 1, wc = wid & 1;
    const int bh = blockIdx.z;
    const int n0 = blockIdx.y * 128;
    const int m0 = blockIdx.x * 128;
    const uint32_t smem_base = smem_to_u32(sm);

    const bf16* srcs[4] = {
        g_qh + ((size_t)bh * SEQ + n0) * HDIM,
        g_ql + ((size_t)bh * SEQ + n0) * HDIM,
        g_kh + ((size_t)bh * SEQ + m0) * HDIM,
        g_kl + ((size_t)bh * SEQ + m0) * HDIM
    };
    #pragma unroll
    for (int m = 0; m < 4; m++) {
        #pragma unroll
        for (int t = 0; t < 4; t++) {
            int i = tid + t * 256;
            int row = i >> 3, ch = i & 7;
            *(uint4*)&sm[m * SC_MAT + row * SGS + ch * 8] =
                *(const uint4*)(srcs[m] + (size_t)row * HDIM + ch * 8);
        }
    }
    __syncthreads();

    float acc[2][8][4] = {};

    #pragma unroll
    for (int ks = 0; ks < 4; ks++) {
        const uint32_t col = ks * 16 + (lane >> 4) * 8;
        uint32_t ah[2][4], al[2][4];
        #pragma unroll
        for (int mt = 0; mt < 2; mt++) {
            uint32_t r = wr * 32 + mt * 16 + (lane & 15);
            ldmatrix_x4(ah[mt][0], ah[mt][1], ah[mt][2], ah[mt][3],
                        smem_base + (0 * SC_MAT + r * SGS + col) * 2);
            ldmatrix_x4(al[mt][0], al[mt][1], al[mt][2], al[mt][3],
                        smem_base + (1 * SC_MAT + r * SGS + col) * 2);
        }
        #pragma unroll
        for (int p = 0; p < 4; p++) {
            uint32_t r = wc * 64 + p * 16 + (lane & 15);
            uint32_t bh0, bh1, bh2, bh3, bl0, bl1, bl2, bl3;
            ldmatrix_x4(bh0, bh1, bh2, bh3,
                        smem_base + (2 * SC_MAT + r * SGS + col) * 2);
            ldmatrix_x4(bl0, bl1, bl2, bl3,
                        smem_base + (3 * SC_MAT + r * SGS + col) * 2);
            #pragma unroll
            for (int mt = 0; mt < 2; mt++) {
                mma_bf16(acc[mt][2 * p + 0], ah[mt], bh0, bh2);
                mma_bf16(acc[mt][2 * p + 1], ah[mt], bh1, bh3);
            }
            #pragma unroll
            for (int mt = 0; mt < 2; mt++) {
                mma_bf16(acc[mt][2 * p + 0], al[mt], bh0, bh2);
                mma_bf16(acc[mt][2 * p + 1], al[mt], bh1, bh3);
            }
            #pragma unroll
            for (int mt = 0; mt < 2; mt++) {
                mma_bf16(acc[mt][2 * p + 0], ah[mt], bl0, bl2);
                mma_bf16(acc[mt][2 * p + 1], ah[mt], bl1, bl3);
            }
        }
    }

    f16* ebase = g_e + (size_t)bh * SEQ * SEQ;
    #pragma unroll
    for (int mt = 0; mt < 2; mt++) {
        const int r = n0 + wr * 32 + mt * 16 + (lane >> 2);
        #pragma unroll
        for (int nt = 0; nt < 8; nt++) {
            const int c = m0 + wc * 64 + nt * 8 + 2 * (lane & 3);
            __half2 e0 = __floats2half2_rn(fast_exp_s(acc[mt][nt][0]),
                                           fast_exp_s(acc[mt][nt][1]));
            __half2 e1 = __floats2half2_rn(fast_exp_s(acc[mt][nt][2]),
                                           fast_exp_s(acc[mt][nt][3]));
            *(__half2*)&ebase[(size_t)r * SEQ + c] = e0;
            *(__half2*)&ebase[(size_t)(r + 8) * SEQ + c] = e1;
        }
    }
}

// =========================================================================
// Norm: P = E / sum_h E ; fp16 in/out.
// =========================================================================
__global__ __launch_bounds__(256) void norm_kernel()
{
    size_t idx = (size_t)blockIdx.x * 256 + threadIdx.x;
    int m4 = idx & 255;
    int n = (idx >> 8) & 1023;
    int b = (int)(idx >> 18);

    const uint2* E = (const uint2*)g_e;
    uint2* P = (uint2*)g_p;

    float4 v[HEADS];
    float4 s = make_float4(0.f, 0.f, 0.f, 0.f);
    #pragma unroll
    for (int h = 0; h < HEADS; h++) {
        size_t off = ((size_t)(b * HEADS + h) * SEQ + n) * (SEQ / 4) + m4;
        uint2 u = E[off];
        float2 f0 = __half22float2(*(__half2*)&u.x);
        float2 f1 = __half22float2(*(__half2*)&u.y);
        v[h] = make_float4(f0.x, f0.y, f1.x, f1.y);
        s.x += f0.x; s.y += f0.y; s.z += f1.x; s.w += f1.y;
    }
    float rx = 1.0f / s.x, ry = 1.0f / s.y, rz = 1.0f / s.z, rw = 1.0f / s.w;
    #pragma unroll
    for (int h = 0; h < HEADS; h++) {
        size_t off = ((size_t)(b * HEADS + h) * SEQ + n) * (SEQ / 4) + m4;
        uint2 o;
        *(__half2*)&o.x = __floats2half2_rn(v[h].x * rx, v[h].y * ry);
        *(__half2*)&o.y = __floats2half2_rn(v[h].z * rz, v[h].w * rw);
        P[off] = o;
    }
}

// =========================================================================
// AV HMMA (fp16): O = P @ V. 128(n) x 64(d), K=1024 in 32-chunks.
// 3-stage pipeline, 1 barrier/iter. P swizzled; V padded-72 (trans loads).
// =========================================================================
#define AVP_BYTES 8192                          // 128 x 32 f16 swizzled
#define AVV_BYTES 4608                          // 32 x 72 f16
#define AV_STG_BYTES (AVP_BYTES + 2 * AVV_BYTES)  // 17408
#define AV_SMEM_BYTES (3 * AV_STG_BYTES)          // 52224
#define VGS 72

__global__ __launch_bounds__(256, 3) void av_hmma_kernel()
{
    extern __shared__ f16 smh[];
    const int tid = threadIdx.x, lane = tid & 31, wid = tid >> 5;
    const int wr = wid >> 1, wc = wid & 1;
    const int n0 = blockIdx.x * 128;
    const int bh = blockIdx.y;
    const int b = bh / HEADS, h = bh % HEADS;
    const uint32_t smem_base = smem_to_u32(smh);

    const f16* pp  = g_p    + ((size_t)bh * SEQ + n0) * SEQ;
    const f16* vhp = g_vh16 + (size_t)bh * SEQ * HDIM;
    const f16* vlp = g_vl16 + (size_t)bh * SEQ * HDIM;

    float acc[2][4][4] = {};

    const int lr0 = tid >> 2, lr1 = (tid + 256) >> 2;
    const int lc = tid & 3;
    const int vrow_ld = tid >> 3, vch_ld = tid & 7;

    auto issue = [&](int it, int s) {
        const int k0 = it * 32;
        const uint32_t sb = smem_base + (uint32_t)(s * AV_STG_BYTES);
        CP_ASYNC16(sb + swz(lr0, lc), pp + (size_t)lr0 * SEQ + k0 + lc * 8);
        CP_ASYNC16(sb + swz(lr1, lc), pp + (size_t)lr1 * SEQ + k0 + lc * 8);
        uint32_t doff = (uint32_t)(vrow_ld * VGS + vch_ld * 8) * 2;
        CP_ASYNC16(sb + AVP_BYTES + doff,
                   vhp + (size_t)(k0 + vrow_ld) * HDIM + vch_ld * 8);
        CP_ASYNC16(sb + AVP_BYTES + AVV_BYTES + doff,
                   vlp + (size_t)(k0 + vrow_ld) * HDIM + vch_ld * 8);
        CP_COMMIT();
    };

    const int NIT = SEQ / 32;   // 32
    issue(0, 0);
    issue(1, 1);

    for (int it = 0; it < NIT; ++it) {
        if (it + 1 < NIT) { CP_WAIT1(); } else { CP_WAIT0(); }
        __syncthreads();
        if (it + 2 < NIT) issue(it + 2, (it + 2) % 3);

        const uint32_t sb = smem_base + (uint32_t)((it % 3) * AV_STG_BYTES);
        const uint32_t vhb = sb + AVP_BYTES;
        const uint32_t vlb = vhb + AVV_BYTES;

        #pragma unroll
        for (int ks = 0; ks < 2; ks++) {
            const uint32_t c0 = ks * 2 + (lane >> 4);
            uint32_t a[2][4];
            #pragma unroll
            for (int mt = 0; mt < 2; mt++) {
                uint32_t r = wr * 32 + mt * 16 + (lane & 15);
                ldmatrix_x4(a[mt][0], a[mt][1], a[mt][2], a[mt][3],
                            sb + swz(r, c0));
            }
            const uint32_t kb = ks * 16;
            #pragma unroll
            for (int nb = 0; nb < 2; nb++) {
                const uint32_t d0 = wc * 32 + nb * 16;
                uint32_t vrow = kb + (lane & 7) + ((lane >> 3) & 1) * 8;
                uint32_t vcol = d0 + (lane >> 4) * 8;
                uint32_t bh0, bh1, bh2, bh3, bl0, bl1, bl2, bl3;
                ldmatrix_x4_trans(bh0, bh1, bh2, bh3, vhb + (vrow * VGS + vcol) * 2);
                ldmatrix_x4_trans(bl0, bl1, bl2, bl3, vlb + (vrow * VGS + vcol) * 2);
                const int nt0 = nb * 2, nt1 = nb * 2 + 1;
                #pragma unroll
                for (int mt = 0; mt < 2; mt++) {
                    mma_f16(acc[mt][nt0], a[mt], bh0, bh1);
                    mma_f16(acc[mt][nt1], a[mt], bh2, bh3);
                }
                #pragma unroll
                for (int mt = 0; mt < 2; mt++) {
                    mma_f16(acc[mt][nt0], a[mt], bl0, bl1);
                    mma_f16(acc[mt][nt1], a[mt], bl2, bl3);
                }
            }
        }
    }

    #pragma unroll
    for (int mt = 0; mt < 2; mt++) {
        const int r = n0 + wr * 32 + mt * 16 + (lane >> 2);
        #pragma unroll
        for (int nt = 0; nt < 4; nt++) {
            const int c = wc * 32 + nt * 8 + 2 * (lane & 3);
            float2 v0 = make_float2(acc[mt][nt][0], acc[mt][nt][1]);
            float2 v1 = make_float2(acc[mt][nt][2], acc[mt][nt][3]);
            __nv_bfloat162 hh, ll;
            size_t i0 = ((size_t)(b * SEQ + r)) * INNER + h * HDIM + c;
            split2(v0, hh, ll);
            *(__nv_bfloat162*)&g_oh[i0] = hh;
            *(__nv_bfloat162*)&g_ol[i0] = ll;
            size_t i1 = ((size_t)(b * SEQ + r + 8)) * INNER + h * HDIM + c;
            split2(v1, hh, ll);
            *(__nv_bfloat162*)&g_oh[i1] = hh;
            *(__nv_bfloat162*)&g_ol[i1] = ll;
        }
    }
}

// =========================================================================
extern "C" void kernel_launch(void* const* d_in, const int* in_sizes, int n_in,
                              void* d_out, int out_size)
{
    const float* x     = (const float*)d_in[0];
    const float* w_qkv = (const float*)d_in[1];
    const float* w_out = (const float*)d_in[2];
    const float* b_out = (const float*)d_in[3];
    float* out = (float*)d_out;

    cudaFuncSetAttribute(hmma_gemm_kernel,
                         cudaFuncAttributeMaxDynamicSharedMemorySize, HM_SMEM_BYTES);
    cudaFuncSetAttribute(score_hmma_kernel,
                         cudaFuncAttributeMaxDynamicSharedMemorySize, SC_SMEM_BYTES);
    cudaFuncSetAttribute(av_hmma_kernel,
                         cudaFuncAttributeMaxDynamicSharedMemorySize, AV_SMEM_BYTES);

    bf16 *xh, *xl, *wqh, *wql, *woh, *wol, *oh, *ol;
    cudaGetSymbolAddress((void**)&xh,  g_xh);
    cudaGetSymbolAddress((void**)&xl,  g_xl);
    cudaGetSymbolAddress((void**)&wqh, g_wqh);
    cudaGetSymbolAddress((void**)&wql, g_wql);
    cudaGetSymbolAddress((void**)&woh, g_woh);
    cudaGetSymbolAddress((void**)&wol, g_wol);
    cudaGetSymbolAddress((void**)&oh,  g_oh);
    cudaGetSymbolAddress((void**)&ol,  g_ol);

    // Prep
    {
        int n4 = BATCH * SEQ * DIM / 4;
        split_kernel<<<(n4 + 255) / 256, 256>>>(x, xh, xl, n4);
    }
    {
        dim3 grid(TRIPLE / 32, DIM / 32);
        transpose_split_kernel<<<grid, dim3(32, 8)>>>(w_qkv, wqh, wql, DIM, TRIPLE);
    }
    {
        dim3 grid(DIM / 32, INNER / 32);
        transpose_split_kernel<<<grid, dim3(32, 8)>>>(w_out, woh, wol, INNER, DIM);
    }

    // K1: QKV projection
    {
        dim3 grid(TRIPLE / 128, (BATCH * SEQ) / 128);
        hmma_gemm_kernel<<<grid, 256, HM_SMEM_BYTES>>>(xh, xl, wqh, wql, nullptr, nullptr, 0);
    }
    // K2: scores -> exp/16 (fp16 E)
    {
        dim3 grid(SEQ / 128, SEQ / 128, BATCH * HEADS);
        score_hmma_kernel<<<grid, 256, SC_SMEM_BYTES>>>();
    }
    // K3: normalize over heads -> P fp16
    {
        int total = BATCH * SEQ * (SEQ / 4);
        norm_kernel<<<total / 256, 256>>>();
    }
    // K4: O = P @ V (fp16 HMMA)
    {
        dim3 grid(SEQ / 128, BATCH * HEADS);
        av_hmma_kernel<<<grid, 256, AV_SMEM_BYTES>>>();
    }
    // K5: output projection + bias
    {
        dim3 grid(DIM / 128, (BATCH * SEQ) / 128);
        hmma_gemm_kernel<<<grid, 256, HM_SMEM_BYTES>>>(oh, ol, woh, wol, b_out, out, 1);
    }
}

// round 9
// speedup vs baseline: 3.3315x; 1.1829x over previous
#include <cuda_runtime.h>
#include <cuda_bf16.h>
#include <cuda_fp16.h>
#include <cstdint>

// Problem constants
#define BATCH   8
#define SEQ     1024
#define DIM     768
#define HEADS   12
#define HDIM    64
#define INNER   768
#define TRIPLE  2304
#define SCALE   0.125f

typedef __nv_bfloat16 bf16;
typedef __half f16;

// ---------------- static scratch ----------------
__device__ __align__(128) f16 g_e[(size_t)BATCH * HEADS * SEQ * SEQ];   // E = exp(S)/16
__device__ __align__(128) f16 g_p[(size_t)BATCH * HEADS * SEQ * SEQ];   // P

// fp16 operands for the 2-MMA weight GEMMs
__device__ __align__(128) f16 g_xh16[BATCH * SEQ * DIM];
__device__ __align__(128) f16 g_xl16[BATCH * SEQ * DIM];
__device__ __align__(128) f16 g_wq16[TRIPLE * DIM];     // transposed, hi only
__device__ __align__(128) f16 g_wo16[DIM * INNER];      // transposed, hi only
__device__ __align__(128) f16 g_oh16[BATCH * SEQ * INNER];
__device__ __align__(128) f16 g_ol16[BATCH * SEQ * INNER];

// bf16 hi/lo Q/K for the high-accuracy score GEMM
__device__ __align__(128) bf16 g_qh[BATCH * HEADS * SEQ * HDIM];
__device__ __align__(128) bf16 g_ql[BATCH * HEADS * SEQ * HDIM];
__device__ __align__(128) bf16 g_kh[BATCH * HEADS * SEQ * HDIM];
__device__ __align__(128) bf16 g_kl[BATCH * HEADS * SEQ * HDIM];
// fp16 hi/lo V for the fp16 AV MMA
__device__ __align__(128) f16 g_vh16[BATCH * HEADS * SEQ * HDIM];
__device__ __align__(128) f16 g_vl16[BATCH * HEADS * SEQ * HDIM];

// ================= helpers =================
__device__ __forceinline__ uint32_t smem_to_u32(const void* p) {
    uint32_t a;
    asm("{ .reg .u64 t; cvta.to.shared.u64 t, %1; cvt.u32.u64 %0, t; }"
        : "=r"(a) : "l"(p));
    return a;
}
// swizzled byte offset within a [rows x 32 elems(16b)] tile (64B per row)
__device__ __forceinline__ uint32_t swz(uint32_t r, uint32_t c) {
    return (r * 4 + (c ^ ((r >> 1) & 3))) * 16;
}
__device__ __forceinline__ void ldmatrix_x4(uint32_t& r0, uint32_t& r1,
                                            uint32_t& r2, uint32_t& r3,
                                            uint32_t addr) {
    asm volatile("ldmatrix.sync.aligned.m8n8.x4.shared.b16 {%0,%1,%2,%3}, [%4];"
                 : "=r"(r0), "=r"(r1), "=r"(r2), "=r"(r3) : "r"(addr));
}
__device__ __forceinline__ void ldmatrix_x4_trans(uint32_t& r0, uint32_t& r1,
                                                  uint32_t& r2, uint32_t& r3,
                                                  uint32_t addr) {
    asm volatile("ldmatrix.sync.aligned.m8n8.x4.trans.shared.b16 {%0,%1,%2,%3}, [%4];"
                 : "=r"(r0), "=r"(r1), "=r"(r2), "=r"(r3) : "r"(addr));
}
__device__ __forceinline__ void mma_bf16(float* c, const uint32_t* a,
                                         uint32_t b0, uint32_t b1) {
    asm volatile("mma.sync.aligned.m16n8k16.row.col.f32.bf16.bf16.f32 "
                 "{%0,%1,%2,%3}, {%4,%5,%6,%7}, {%8,%9}, {%0,%1,%2,%3};"
                 : "+f"(c[0]), "+f"(c[1]), "+f"(c[2]), "+f"(c[3])
                 : "r"(a[0]), "r"(a[1]), "r"(a[2]), "r"(a[3]),
                   "r"(b0), "r"(b1));
}
__device__ __forceinline__ void mma_f16(float* c, const uint32_t* a,
                                        uint32_t b0, uint32_t b1) {
    asm volatile("mma.sync.aligned.m16n8k16.row.col.f32.f16.f16.f32 "
                 "{%0,%1,%2,%3}, {%4,%5,%6,%7}, {%8,%9}, {%0,%1,%2,%3};"
                 : "+f"(c[0]), "+f"(c[1]), "+f"(c[2]), "+f"(c[3])
                 : "r"(a[0]), "r"(a[1]), "r"(a[2]), "r"(a[3]),
                   "r"(b0), "r"(b1));
}
#define CP_ASYNC16(sa, g) \
    asm volatile("cp.async.cg.shared.global [%0], [%1], 16;" :: "r"(sa), "l"(g))
#define CP_COMMIT() asm volatile("cp.async.commit_group;" ::: "memory")
#define CP_WAIT1()  asm volatile("cp.async.wait_group 1;" ::: "memory")
#define CP_WAIT0()  asm volatile("cp.async.wait_group 0;" ::: "memory")

__device__ __forceinline__ float fast_exp_s(float x) {
    const float LOG2E = 1.4426950408889634f;
    const float MAGIC = 12582912.0f;
    float z = fmaf(x, LOG2E, MAGIC);
    int   e = __float_as_int(z) - 0x4B400000;
    float i = z - MAGIC;
    float f = fmaf(x, LOG2E, -i);
    float p = 1.5403531e-4f;
    p = fmaf(p, f, 1.3333558e-3f);
    p = fmaf(p, f, 9.6181291e-3f);
    p = fmaf(p, f, 5.5504109e-2f);
    p = fmaf(p, f, 2.4022651e-1f);
    p = fmaf(p, f, 6.9314718e-1f);
    p = fmaf(p, f, 1.0f);
    return __int_as_float(__float_as_int(p) + ((e - 4) << 23));
}
__device__ __forceinline__ void split2(float2 v, __nv_bfloat162& h, __nv_bfloat162& l) {
    bf16 hx = __float2bfloat16(v.x), hy = __float2bfloat16(v.y);
    h = __nv_bfloat162(hx, hy);
    l = __nv_bfloat162(__float2bfloat16(v.x - __bfloat162float(hx)),
                       __float2bfloat16(v.y - __bfloat162float(hy)));
}
__device__ __forceinline__ void split2h(float2 v, __half2& h, __half2& l) {
    f16 hx = __float2half_rn(v.x), hy = __float2half_rn(v.y);
    h = __half2(hx, hy);
    l = __half2(__float2half_rn(v.x - __half2float(hx)),
                __float2half_rn(v.y - __half2float(hy)));
}

// =========================================================================
// Prep kernels
// =========================================================================
__global__ __launch_bounds__(256) void split_f16_kernel(
    const float* __restrict__ in, f16* __restrict__ hi, f16* __restrict__ lo, int n4)
{
    int i = blockIdx.x * 256 + threadIdx.x;
    if (i >= n4) return;
    float4 v = ((const float4*)in)[i];
    __half2 h0, l0, h1, l1;
    split2h(make_float2(v.x, v.y), h0, l0);
    split2h(make_float2(v.z, v.w), h1, l1);
    __half2* H = (__half2*)hi;
    __half2* L = (__half2*)lo;
    H[2 * i] = h0; H[2 * i + 1] = h1;
    L[2 * i] = l0; L[2 * i + 1] = l1;
}

// transpose fp32 [R][C] -> fp16 [C][R] (hi only)
__global__ __launch_bounds__(256) void transpose_f16_kernel(
    const float* __restrict__ in, f16* __restrict__ outp, int R, int C)
{
    __shared__ float t[32][33];
    const int tx = threadIdx.x, ty = threadIdx.y;
    const int bx = blockIdx.x, by = blockIdx.y;
    #pragma unroll
    for (int i = 0; i < 4; i++) {
        int r = by * 32 + ty + i * 8;
        t[ty + i * 8][tx] = in[(size_t)r * C + bx * 32 + tx];
    }
    __syncthreads();
    #pragma unroll
    for (int i = 0; i < 4; i++) {
        int c = bx * 32 + ty + i * 8;
        int r = by * 32 + tx;
        outp[(size_t)c * R + r] = __float2half_rn(t[tx][ty + i * 8]);
    }
}

// =========================================================================
// fp16 2-MMA GEMM: C = (Ah+Al) @ Bw^T. A fp16 hi/lo, B fp16 hi only.
// 128x128x32 tiles, 8 warps, 3-stage cp.async pipeline, 1 barrier/iter.
// mode 0: qkv epilogue (Q/K bf16 hi/lo + SCALE on Q; V fp16 hi/lo).
// mode 1: oproj + bias -> fp32 out.
// =========================================================================
#define MAT_BYTES  8192                  // 128 rows x 32 f16 (swizzled)
#define STG_BYTES  (3 * MAT_BYTES)       // Ah, Al, Bw
#define HM_SMEM_BYTES (3 * STG_BYTES)    // 73728

__global__ __launch_bounds__(256, 2) void hmma_f16_gemm_kernel(
    const f16* __restrict__ Ah, const f16* __restrict__ Al,
    const f16* __restrict__ Bw,
    const float* __restrict__ bias, float* __restrict__ outp, int mode)
{
    extern __shared__ f16 sm[];
    const int tid = threadIdx.x, lane = tid & 31, wid = tid >> 5;
    const int wr = wid >> 1, wc = wid & 1;
    const int bn = blockIdx.x * 128, bm = blockIdx.y * 128;
    const uint32_t smem_base = smem_to_u32(sm);

    const f16* srcs[3] = {Ah, Al, Bw};
    const int rb[3] = {bm, bm, bn};

    float acc[2][8][4] = {};

    const int lr0 = tid >> 2, lr1 = (tid + 256) >> 2;
    const int lc = tid & 3;

    auto issue = [&](int it, int s) {
        const int k0 = it * 32;
        const uint32_t sb = smem_base + (uint32_t)(s * STG_BYTES);
        #pragma unroll
        for (int m = 0; m < 3; m++) {
            const f16* src = srcs[m];
            CP_ASYNC16(sb + m * MAT_BYTES + swz(lr0, lc),
                       src + (size_t)(rb[m] + lr0) * DIM + k0 + lc * 8);
            CP_ASYNC16(sb + m * MAT_BYTES + swz(lr1, lc),
                       src + (size_t)(rb[m] + lr1) * DIM + k0 + lc * 8);
        }
        CP_COMMIT();
    };

    const int NIT = DIM / 32;   // 24
    issue(0, 0);
    issue(1, 1);

    for (int it = 0; it < NIT; ++it) {
        if (it + 1 < NIT) { CP_WAIT1(); } else { CP_WAIT0(); }
        __syncthreads();
        if (it + 2 < NIT) issue(it + 2, (it + 2) % 3);

        const uint32_t sb = smem_base + (uint32_t)((it % 3) * STG_BYTES);
        #pragma unroll
        for (int ks = 0; ks < 2; ks++) {
            const uint32_t c0 = ks * 2 + (lane >> 4);
            uint32_t ah[2][4], al[2][4];
            #pragma unroll
            for (int mt = 0; mt < 2; mt++) {
                uint32_t r = wr * 32 + mt * 16 + (lane & 15);
                ldmatrix_x4(ah[mt][0], ah[mt][1], ah[mt][2], ah[mt][3],
                            sb + 0 * MAT_BYTES + swz(r, c0));
                ldmatrix_x4(al[mt][0], al[mt][1], al[mt][2], al[mt][3],
                            sb + 1 * MAT_BYTES + swz(r, c0));
            }
            #pragma unroll
            for (int p = 0; p < 4; p++) {
                uint32_t r = wc * 64 + p * 16 + (lane & 15);
                uint32_t b0, b1, b2, b3;
                ldmatrix_x4(b0, b1, b2, b3, sb + 2 * MAT_BYTES + swz(r, c0));
                #pragma unroll
                for (int mt = 0; mt < 2; mt++) {
                    mma_f16(acc[mt][2 * p + 0], ah[mt], b0, b2);
                    mma_f16(acc[mt][2 * p + 1], ah[mt], b1, b3);
                }
                #pragma unroll
                for (int mt = 0; mt < 2; mt++) {
                    mma_f16(acc[mt][2 * p + 0], al[mt], b0, b2);
                    mma_f16(acc[mt][2 * p + 1], al[mt], b1, b3);
                }
            }
        }
    }

    // ---- epilogue ----
    #pragma unroll
    for (int mt = 0; mt < 2; mt++) {
        const int r = bm + wr * 32 + mt * 16 + (lane >> 2);
        #pragma unroll
        for (int nt = 0; nt < 8; nt++) {
            const int c = bn + wc * 64 + nt * 8 + 2 * (lane & 3);
            float2 v0 = make_float2(acc[mt][nt][0], acc[mt][nt][1]);
            float2 v1 = make_float2(acc[mt][nt][2], acc[mt][nt][3]);
            if (mode == 0) {
                int chunk = c / INNER;
                int e = c % INNER;
                int h = e >> 6, d = e & 63;
                int b0 = r >> 10, n0 = r & 1023;
                int r2 = r + 8;
                int b1 = r2 >> 10, n1 = r2 & 1023;
                size_t i0 = (((size_t)(b0 * HEADS + h) * SEQ) + n0) * HDIM + d;
                size_t i1 = (((size_t)(b1 * HEADS + h) * SEQ) + n1) * HDIM + d;
                if (chunk == 2) {
                    __half2 hh, ll;
                    split2h(v0, hh, ll);
                    *(__half2*)&g_vh16[i0] = hh;
                    *(__half2*)&g_vl16[i0] = ll;
                    split2h(v1, hh, ll);
                    *(__half2*)&g_vh16[i1] = hh;
                    *(__half2*)&g_vl16[i1] = ll;
                } else {
                    bf16 *dh, *dl;
                    if (chunk == 0) {
                        dh = g_qh; dl = g_ql;
                        v0.x *= SCALE; v0.y *= SCALE;
                        v1.x *= SCALE; v1.y *= SCALE;
                    } else { dh = g_kh; dl = g_kl; }
                    __nv_bfloat162 hh, ll;
                    split2(v0, hh, ll);
                    *(__nv_bfloat162*)&dh[i0] = hh;
                    *(__nv_bfloat162*)&dl[i0] = ll;
                    split2(v1, hh, ll);
                    *(__nv_bfloat162*)&dh[i1] = hh;
                    *(__nv_bfloat162*)&dl[i1] = ll;
                }
            } else {
                float2 bq = *(const float2*)&bias[c];
                v0.x += bq.x; v0.y += bq.y;
                v1.x += bq.x; v1.y += bq.y;
                *(float2*)&outp[(size_t)r * DIM + c] = v0;
                *(float2*)&outp[(size_t)(r + 8) * DIM + c] = v1;
            }
        }
    }
}

// =========================================================================
// Score HMMA (bf16 3-MMA, high accuracy): E = exp(Q.K)/16 (fp16).
// =========================================================================
#define SGS 72
#define SC_MAT (128 * SGS)
#define SC_SMEM_BYTES (4 * SC_MAT * 2)   // 73728

__global__ __launch_bounds__(256, 2) void score_hmma_kernel()
{
    extern __shared__ bf16 smb[];
    const int tid = threadIdx.x, lane = tid & 31, wid = tid >> 5;
    const int wr = wid >> 1, wc = wid & 1;
    const int bh = blockIdx.z;
    const int n0 = blockIdx.y * 128;
    const int m0 = blockIdx.x * 128;
    const uint32_t smem_base = smem_to_u32(smb);

    const bf16* srcs[4] = {
        g_qh + ((size_t)bh * SEQ + n0) * HDIM,
        g_ql + ((size_t)bh * SEQ + n0) * HDIM,
        g_kh + ((size_t)bh * SEQ + m0) * HDIM,
        g_kl + ((size_t)bh * SEQ + m0) * HDIM
    };
    #pragma unroll
    for (int m = 0; m < 4; m++) {
        #pragma unroll
        for (int t = 0; t < 4; t++) {
            int i = tid + t * 256;
            int row = i >> 3, ch = i & 7;
            *(uint4*)&smb[m * SC_MAT + row * SGS + ch * 8] =
                *(const uint4*)(srcs[m] + (size_t)row * HDIM + ch * 8);
        }
    }
    __syncthreads();

    float acc[2][8][4] = {};

    #pragma unroll
    for (int ks = 0; ks < 4; ks++) {
        const uint32_t col = ks * 16 + (lane >> 4) * 8;
        uint32_t ah[2][4], al[2][4];
        #pragma unroll
        for (int mt = 0; mt < 2; mt++) {
            uint32_t r = wr * 32 + mt * 16 + (lane & 15);
            ldmatrix_x4(ah[mt][0], ah[mt][1], ah[mt][2], ah[mt][3],
                        smem_base + (0 * SC_MAT + r * SGS + col) * 2);
            ldmatrix_x4(al[mt][0], al[mt][1], al[mt][2], al[mt][3],
                        smem_base + (1 * SC_MAT + r * SGS + col) * 2);
        }
        #pragma unroll
        for (int p = 0; p < 4; p++) {
            uint32_t r = wc * 64 + p * 16 + (lane & 15);
            uint32_t bh0, bh1, bh2, bh3, bl0, bl1, bl2, bl3;
            ldmatrix_x4(bh0, bh1, bh2, bh3,
                        smem_base + (2 * SC_MAT + r * SGS + col) * 2);
            ldmatrix_x4(bl0, bl1, bl2, bl3,
                        smem_base + (3 * SC_MAT + r * SGS + col) * 2);
            #pragma unroll
            for (int mt = 0; mt < 2; mt++) {
                mma_bf16(acc[mt][2 * p + 0], ah[mt], bh0, bh2);
                mma_bf16(acc[mt][2 * p + 1], ah[mt], bh1, bh3);
            }
            #pragma unroll
            for (int mt = 0; mt < 2; mt++) {
                mma_bf16(acc[mt][2 * p + 0], al[mt], bh0, bh2);
                mma_bf16(acc[mt][2 * p + 1], al[mt], bh1, bh3);
            }
            #pragma unroll
            for (int mt = 0; mt < 2; mt++) {
                mma_bf16(acc[mt][2 * p + 0], ah[mt], bl0, bl2);
                mma_bf16(acc[mt][2 * p + 1], ah[mt], bl1, bl3);
            }
        }
    }

    f16* ebase = g_e + (size_t)bh * SEQ * SEQ;
    #pragma unroll
    for (int mt = 0; mt < 2; mt++) {
        const int r = n0 + wr * 32 + mt * 16 + (lane >> 2);
        #pragma unroll
        for (int nt = 0; nt < 8; nt++) {
            const int c = m0 + wc * 64 + nt * 8 + 2 * (lane & 3);
            __half2 e0 = __floats2half2_rn(fast_exp_s(acc[mt][nt][0]),
                                           fast_exp_s(acc[mt][nt][1]));
            __half2 e1 = __floats2half2_rn(fast_exp_s(acc[mt][nt][2]),
                                           fast_exp_s(acc[mt][nt][3]));
            *(__half2*)&ebase[(size_t)r * SEQ + c] = e0;
            *(__half2*)&ebase[(size_t)(r + 8) * SEQ + c] = e1;
        }
    }
}

// =========================================================================
// Norm: P = E / sum_h E ; fp16 in/out.
// =========================================================================
__global__ __launch_bounds__(256) void norm_kernel()
{
    size_t idx = (size_t)blockIdx.x * 256 + threadIdx.x;
    int m4 = idx & 255;
    int n = (idx >> 8) & 1023;
    int b = (int)(idx >> 18);

    const uint2* E = (const uint2*)g_e;
    uint2* P = (uint2*)g_p;

    float4 v[HEADS];
    float4 s = make_float4(0.f, 0.f, 0.f, 0.f);
    #pragma unroll
    for (int h = 0; h < HEADS; h++) {
        size_t off = ((size_t)(b * HEADS + h) * SEQ + n) * (SEQ / 4) + m4;
        uint2 u = E[off];
        float2 f0 = __half22float2(*(__half2*)&u.x);
        float2 f1 = __half22float2(*(__half2*)&u.y);
        v[h] = make_float4(f0.x, f0.y, f1.x, f1.y);
        s.x += f0.x; s.y += f0.y; s.z += f1.x; s.w += f1.y;
    }
    float rx = 1.0f / s.x, ry = 1.0f / s.y, rz = 1.0f / s.z, rw = 1.0f / s.w;
    #pragma unroll
    for (int h = 0; h < HEADS; h++) {
        size_t off = ((size_t)(b * HEADS + h) * SEQ + n) * (SEQ / 4) + m4;
        uint2 o;
        *(__half2*)&o.x = __floats2half2_rn(v[h].x * rx, v[h].y * ry);
        *(__half2*)&o.y = __floats2half2_rn(v[h].z * rz, v[h].w * rw);
        P[off] = o;
    }
}

// =========================================================================
// AV HMMA (fp16): O = P @ V. 128(n) x 64(d), K=1024 in 32-chunks.
// 3-stage pipeline, 1 barrier/iter. Epilogue writes O fp16 hi/lo.
// =========================================================================
#define AVP_BYTES 8192
#define AVV_BYTES 4608
#define AV_STG_BYTES (AVP_BYTES + 2 * AVV_BYTES)   // 17408
#define AV_SMEM_BYTES (3 * AV_STG_BYTES)           // 52224
#define VGS 72

__global__ __launch_bounds__(256, 3) void av_hmma_kernel()
{
    extern __shared__ f16 smh[];
    const int tid = threadIdx.x, lane = tid & 31, wid = tid >> 5;
    const int wr = wid >> 1, wc = wid & 1;
    const int n0 = blockIdx.x * 128;
    const int bh = blockIdx.y;
    const int b = bh / HEADS, h = bh % HEADS;
    const uint32_t smem_base = smem_to_u32(smh);

    const f16* pp  = g_p    + ((size_t)bh * SEQ + n0) * SEQ;
    const f16* vhp = g_vh16 + (size_t)bh * SEQ * HDIM;
    const f16* vlp = g_vl16 + (size_t)bh * SEQ * HDIM;

    float acc[2][4][4] = {};

    const int lr0 = tid >> 2, lr1 = (tid + 256) >> 2;
    const int lc = tid & 3;
    const int vrow_ld = tid >> 3, vch_ld = tid & 7;

    auto issue = [&](int it, int s) {
        const int k0 = it * 32;
        const uint32_t sb = smem_base + (uint32_t)(s * AV_STG_BYTES);
        CP_ASYNC16(sb + swz(lr0, lc), pp + (size_t)lr0 * SEQ + k0 + lc * 8);
        CP_ASYNC16(sb + swz(lr1, lc), pp + (size_t)lr1 * SEQ + k0 + lc * 8);
        uint32_t doff = (uint32_t)(vrow_ld * VGS + vch_ld * 8) * 2;
        CP_ASYNC16(sb + AVP_BYTES + doff,
                   vhp + (size_t)(k0 + vrow_ld) * HDIM + vch_ld * 8);
        CP_ASYNC16(sb + AVP_BYTES + AVV_BYTES + doff,
                   vlp + (size_t)(k0 + vrow_ld) * HDIM + vch_ld * 8);
        CP_COMMIT();
    };

    const int NIT = SEQ / 32;
    issue(0, 0);
    issue(1, 1);

    for (int it = 0; it < NIT; ++it) {
        if (it + 1 < NIT) { CP_WAIT1(); } else { CP_WAIT0(); }
        __syncthreads();
        if (it + 2 < NIT) issue(it + 2, (it + 2) % 3);

        const uint32_t sb = smem_base + (uint32_t)((it % 3) * AV_STG_BYTES);
        const uint32_t vhb = sb + AVP_BYTES;
        const uint32_t vlb = vhb + AVV_BYTES;

        #pragma unroll
        for (int ks = 0; ks < 2; ks++) {
            const uint32_t c0 = ks * 2 + (lane >> 4);
            uint32_t a[2][4];
            #pragma unroll
            for (int mt = 0; mt < 2; mt++) {
                uint32_t r = wr * 32 + mt * 16 + (lane & 15);
                ldmatrix_x4(a[mt][0], a[mt][1], a[mt][2], a[mt][3],
                            sb + swz(r, c0));
            }
            const uint32_t kb = ks * 16;
            #pragma unroll
            for (int nb = 0; nb < 2; nb++) {
                const uint32_t d0 = wc * 32 + nb * 16;
                uint32_t vrow = kb + (lane & 7) + ((lane >> 3) & 1) * 8;
                uint32_t vcol = d0 + (lane >> 4) * 8;
                uint32_t bh0, bh1, bh2, bh3, bl0, bl1, bl2, bl3;
                ldmatrix_x4_trans(bh0, bh1, bh2, bh3, vhb + (vrow * VGS + vcol) * 2);
                ldmatrix_x4_trans(bl0, bl1, bl2, bl3, vlb + (vrow * VGS + vcol) * 2);
                const int nt0 = nb * 2, nt1 = nb * 2 + 1;
                #pragma unroll
                for (int mt = 0; mt < 2; mt++) {
                    mma_f16(acc[mt][nt0], a[mt], bh0, bh1);
                    mma_f16(acc[mt][nt1], a[mt], bh2, bh3);
                }
                #pragma unroll
                for (int mt = 0; mt < 2; mt++) {
                    mma_f16(acc[mt][nt0], a[mt], bl0, bl1);
                    mma_f16(acc[mt][nt1], a[mt], bl2, bl3);
                }
            }
        }
    }

    // epilogue: O -> fp16 hi/lo at [b, n, h*64+d]
    #pragma unroll
    for (int mt = 0; mt < 2; mt++) {
        const int r = n0 + wr * 32 + mt * 16 + (lane >> 2);
        #pragma unroll
        for (int nt = 0; nt < 4; nt++) {
            const int c = wc * 32 + nt * 8 + 2 * (lane & 3);
            float2 v0 = make_float2(acc[mt][nt][0], acc[mt][nt][1]);
            float2 v1 = make_float2(acc[mt][nt][2], acc[mt][nt][3]);
            __half2 hh, ll;
            size_t i0 = ((size_t)(b * SEQ + r)) * INNER + h * HDIM + c;
            split2h(v0, hh, ll);
            *(__half2*)&g_oh16[i0] = hh;
            *(__half2*)&g_ol16[i0] = ll;
            size_t i1 = ((size_t)(b * SEQ + r + 8)) * INNER + h * HDIM + c;
            split2h(v1, hh, ll);
            *(__half2*)&g_oh16[i1] = hh;
            *(__half2*)&g_ol16[i1] = ll;
        }
    }
}

// =========================================================================
extern "C" void kernel_launch(void* const* d_in, const int* in_sizes, int n_in,
                              void* d_out, int out_size)
{
    const float* x     = (const float*)d_in[0];
    const float* w_qkv = (const float*)d_in[1];
    const float* w_out = (const float*)d_in[2];
    const float* b_out = (const float*)d_in[3];
    float* out = (float*)d_out;

    cudaFuncSetAttribute(hmma_f16_gemm_kernel,
                         cudaFuncAttributeMaxDynamicSharedMemorySize, HM_SMEM_BYTES);
    cudaFuncSetAttribute(score_hmma_kernel,
                         cudaFuncAttributeMaxDynamicSharedMemorySize, SC_SMEM_BYTES);
    cudaFuncSetAttribute(av_hmma_kernel,
                         cudaFuncAttributeMaxDynamicSharedMemorySize, AV_SMEM_BYTES);

    f16 *xh, *xl, *wq, *wo, *oh, *ol;
    cudaGetSymbolAddress((void**)&xh, g_xh16);
    cudaGetSymbolAddress((void**)&xl, g_xl16);
    cudaGetSymbolAddress((void**)&wq, g_wq16);
    cudaGetSymbolAddress((void**)&wo, g_wo16);
    cudaGetSymbolAddress((void**)&oh, g_oh16);
    cudaGetSymbolAddress((void**)&ol, g_ol16);

    // Prep
    {
        int n4 = BATCH * SEQ * DIM / 4;
        split_f16_kernel<<<(n4 + 255) / 256, 256>>>(x, xh, xl, n4);
    }
    {
        dim3 grid(TRIPLE / 32, DIM / 32);
        transpose_f16_kernel<<<grid, dim3(32, 8)>>>(w_qkv, wq, DIM, TRIPLE);
    }
    {
        dim3 grid(DIM / 32, INNER / 32);
        transpose_f16_kernel<<<grid, dim3(32, 8)>>>(w_out, wo, INNER, DIM);
    }

    // K1: QKV projection (fp16 2-MMA)
    {
        dim3 grid(TRIPLE / 128, (BATCH * SEQ) / 128);
        hmma_f16_gemm_kernel<<<grid, 256, HM_SMEM_BYTES>>>(xh, xl, wq, nullptr, nullptr, 0);
    }
    // K2: scores -> exp/16 (fp16 E)
    {
        dim3 grid(SEQ / 128, SEQ / 128, BATCH * HEADS);
        score_hmma_kernel<<<grid, 256, SC_SMEM_BYTES>>>();
    }
    // K3: normalize over heads -> P fp16
    {
        int total = BATCH * SEQ * (SEQ / 4);
        norm_kernel<<<total / 256, 256>>>();
    }
    // K4: O = P @ V (fp16 HMMA) -> O fp16 hi/lo
    {
        dim3 grid(SEQ / 128, BATCH * HEADS);
        av_hmma_kernel<<<grid, 256, AV_SMEM_BYTES>>>();
    }
    // K5: output projection (fp16 2-MMA) + bias
    {
        dim3 grid(DIM / 128, (BATCH * SEQ) / 128);
        hmma_f16_gemm_kernel<<<grid, 256, HM_SMEM_BYTES>>>(oh, ol, wo, b_out, out, 1);
    }
}

// round 10
// speedup vs baseline: 3.5412x; 1.0629x over previous
#include <cuda_runtime.h>
#include <cuda_bf16.h>
#include <cuda_fp16.h>
#include <cstdint>

// Problem constants
#define BATCH   8
#define SEQ     1024
#define DIM     768
#define HEADS   12
#define HDIM    64
#define INNER   768
#define TRIPLE  2304
#define SCALE   0.125f

typedef __nv_bfloat16 bf16;
typedef __half f16;

// ---------------- static scratch ----------------
__device__ __align__(128) f16 g_e[(size_t)BATCH * HEADS * SEQ * SEQ];   // E = exp(S)/16
__device__ __align__(128) f16 g_rinv[(size_t)BATCH * SEQ * SEQ];        // 1/sum_h E

// fp16 operands for the 2-MMA weight GEMMs
__device__ __align__(128) f16 g_xh16[BATCH * SEQ * DIM];
__device__ __align__(128) f16 g_xl16[BATCH * SEQ * DIM];
__device__ __align__(128) f16 g_wq16[TRIPLE * DIM];     // transposed, hi only
__device__ __align__(128) f16 g_wo16[DIM * INNER];      // transposed, hi only
__device__ __align__(128) f16 g_oh16[BATCH * SEQ * INNER];
__device__ __align__(128) f16 g_ol16[BATCH * SEQ * INNER];

// fp16 Q (hi/lo) and K (hi) for the score GEMM
__device__ __align__(128) f16 g_qh16[BATCH * HEADS * SEQ * HDIM];
__device__ __align__(128) f16 g_ql16[BATCH * HEADS * SEQ * HDIM];
__device__ __align__(128) f16 g_kh16[BATCH * HEADS * SEQ * HDIM];
// fp16 hi/lo V for the fp16 AV MMA
__device__ __align__(128) f16 g_vh16[BATCH * HEADS * SEQ * HDIM];
__device__ __align__(128) f16 g_vl16[BATCH * HEADS * SEQ * HDIM];

// ================= helpers =================
__device__ __forceinline__ uint32_t smem_to_u32(const void* p) {
    uint32_t a;
    asm("{ .reg .u64 t; cvta.to.shared.u64 t, %1; cvt.u32.u64 %0, t; }"
        : "=r"(a) : "l"(p));
    return a;
}
// swizzled byte offset within a [rows x 32 elems(16b)] tile (64B per row)
__device__ __forceinline__ uint32_t swz(uint32_t r, uint32_t c) {
    return (r * 4 + (c ^ ((r >> 1) & 3))) * 16;
}
__device__ __forceinline__ void ldmatrix_x4(uint32_t& r0, uint32_t& r1,
                                            uint32_t& r2, uint32_t& r3,
                                            uint32_t addr) {
    asm volatile("ldmatrix.sync.aligned.m8n8.x4.shared.b16 {%0,%1,%2,%3}, [%4];"
                 : "=r"(r0), "=r"(r1), "=r"(r2), "=r"(r3) : "r"(addr));
}
__device__ __forceinline__ void ldmatrix_x4_trans(uint32_t& r0, uint32_t& r1,
                                                  uint32_t& r2, uint32_t& r3,
                                                  uint32_t addr) {
    asm volatile("ldmatrix.sync.aligned.m8n8.x4.trans.shared.b16 {%0,%1,%2,%3}, [%4];"
                 : "=r"(r0), "=r"(r1), "=r"(r2), "=r"(r3) : "r"(addr));
}
__device__ __forceinline__ void mma_f16(float* c, const uint32_t* a,
                                        uint32_t b0, uint32_t b1) {
    asm volatile("mma.sync.aligned.m16n8k16.row.col.f32.f16.f16.f32 "
                 "{%0,%1,%2,%3}, {%4,%5,%6,%7}, {%8,%9}, {%0,%1,%2,%3};"
                 : "+f"(c[0]), "+f"(c[1]), "+f"(c[2]), "+f"(c[3])
                 : "r"(a[0]), "r"(a[1]), "r"(a[2]), "r"(a[3]),
                   "r"(b0), "r"(b1));
}
__device__ __forceinline__ uint32_t hmul2u(uint32_t a, uint32_t b) {
    __half2 r = __hmul2(*(__half2*)&a, *(__half2*)&b);
    return *(uint32_t*)&r;
}
#define CP_ASYNC16(sa, g) \
    asm volatile("cp.async.cg.shared.global [%0], [%1], 16;" :: "r"(sa), "l"(g))
#define CP_COMMIT() asm volatile("cp.async.commit_group;" ::: "memory")
#define CP_WAIT1()  asm volatile("cp.async.wait_group 1;" ::: "memory")
#define CP_WAIT0()  asm volatile("cp.async.wait_group 0;" ::: "memory")

__device__ __forceinline__ float fast_exp_s(float x) {
    const float LOG2E = 1.4426950408889634f;
    const float MAGIC = 12582912.0f;
    float z = fmaf(x, LOG2E, MAGIC);
    int   e = __float_as_int(z) - 0x4B400000;
    float i = z - MAGIC;
    float f = fmaf(x, LOG2E, -i);
    float p = 1.5403531e-4f;
    p = fmaf(p, f, 1.3333558e-3f);
    p = fmaf(p, f, 9.6181291e-3f);
    p = fmaf(p, f, 5.5504109e-2f);
    p = fmaf(p, f, 2.4022651e-1f);
    p = fmaf(p, f, 6.9314718e-1f);
    p = fmaf(p, f, 1.0f);
    return __int_as_float(__float_as_int(p) + ((e - 4) << 23));
}
__device__ __forceinline__ void split2h(float2 v, __half2& h, __half2& l) {
    f16 hx = __float2half_rn(v.x), hy = __float2half_rn(v.y);
    h = __half2(hx, hy);
    l = __half2(__float2half_rn(v.x - __half2float(hx)),
                __float2half_rn(v.y - __half2float(hy)));
}

// =========================================================================
// Prep kernels
// =========================================================================
__global__ __launch_bounds__(256) void split_f16_kernel(
    const float* __restrict__ in, f16* __restrict__ hi, f16* __restrict__ lo, int n4)
{
    int i = blockIdx.x * 256 + threadIdx.x;
    if (i >= n4) return;
    float4 v = ((const float4*)in)[i];
    __half2 h0, l0, h1, l1;
    split2h(make_float2(v.x, v.y), h0, l0);
    split2h(make_float2(v.z, v.w), h1, l1);
    __half2* H = (__half2*)hi;
    __half2* L = (__half2*)lo;
    H[2 * i] = h0; H[2 * i + 1] = h1;
    L[2 * i] = l0; L[2 * i + 1] = l1;
}

__global__ __launch_bounds__(256) void transpose_f16_kernel(
    const float* __restrict__ in, f16* __restrict__ outp, int R, int C)
{
    __shared__ float t[32][33];
    const int tx = threadIdx.x, ty = threadIdx.y;
    const int bx = blockIdx.x, by = blockIdx.y;
    #pragma unroll
    for (int i = 0; i < 4; i++) {
        int r = by * 32 + ty + i * 8;
        t[ty + i * 8][tx] = in[(size_t)r * C + bx * 32 + tx];
    }
    __syncthreads();
    #pragma unroll
    for (int i = 0; i < 4; i++) {
        int c = bx * 32 + ty + i * 8;
        int r = by * 32 + tx;
        outp[(size_t)c * R + r] = __float2half_rn(t[tx][ty + i * 8]);
    }
}

// =========================================================================
// fp16 2-MMA GEMM: C = (Ah+Al) @ Bw^T. 128x128x32, 3-stage, 1 barrier/iter.
// mode 0: qkv epilogue (Q fp16 hi/lo w/ SCALE; K fp16 hi; V fp16 hi/lo).
// mode 1: oproj + bias -> fp32 out.
// =========================================================================
#define MAT_BYTES  8192
#define STG_BYTES  (3 * MAT_BYTES)
#define HM_SMEM_BYTES (3 * STG_BYTES)    // 73728

__global__ __launch_bounds__(256, 2) void hmma_f16_gemm_kernel(
    const f16* __restrict__ Ah, const f16* __restrict__ Al,
    const f16* __restrict__ Bw,
    const float* __restrict__ bias, float* __restrict__ outp, int mode)
{
    extern __shared__ f16 sm[];
    const int tid = threadIdx.x, lane = tid & 31, wid = tid >> 5;
    const int wr = wid >> 1, wc = wid & 1;
    const int bn = blockIdx.x * 128, bm = blockIdx.y * 128;
    const uint32_t smem_base = smem_to_u32(sm);

    const f16* srcs[3] = {Ah, Al, Bw};
    const int rb[3] = {bm, bm, bn};

    float acc[2][8][4] = {};

    const int lr0 = tid >> 2, lr1 = (tid + 256) >> 2;
    const int lc = tid & 3;

    auto issue = [&](int it, int s) {
        const int k0 = it * 32;
        const uint32_t sb = smem_base + (uint32_t)(s * STG_BYTES);
        #pragma unroll
        for (int m = 0; m < 3; m++) {
            const f16* src = srcs[m];
            CP_ASYNC16(sb + m * MAT_BYTES + swz(lr0, lc),
                       src + (size_t)(rb[m] + lr0) * DIM + k0 + lc * 8);
            CP_ASYNC16(sb + m * MAT_BYTES + swz(lr1, lc),
                       src + (size_t)(rb[m] + lr1) * DIM + k0 + lc * 8);
        }
        CP_COMMIT();
    };

    const int NIT = DIM / 32;   // 24
    issue(0, 0);
    issue(1, 1);

    for (int it = 0; it < NIT; ++it) {
        if (it + 1 < NIT) { CP_WAIT1(); } else { CP_WAIT0(); }
        __syncthreads();
        if (it + 2 < NIT) issue(it + 2, (it + 2) % 3);

        const uint32_t sb = smem_base + (uint32_t)((it % 3) * STG_BYTES);
        #pragma unroll
        for (int ks = 0; ks < 2; ks++) {
            const uint32_t c0 = ks * 2 + (lane >> 4);
            uint32_t ah[2][4], al[2][4];
            #pragma unroll
            for (int mt = 0; mt < 2; mt++) {
                uint32_t r = wr * 32 + mt * 16 + (lane & 15);
                ldmatrix_x4(ah[mt][0], ah[mt][1], ah[mt][2], ah[mt][3],
                            sb + 0 * MAT_BYTES + swz(r, c0));
                ldmatrix_x4(al[mt][0], al[mt][1], al[mt][2], al[mt][3],
                            sb + 1 * MAT_BYTES + swz(r, c0));
            }
            #pragma unroll
            for (int p = 0; p < 4; p++) {
                uint32_t r = wc * 64 + p * 16 + (lane & 15);
                uint32_t b0, b1, b2, b3;
                ldmatrix_x4(b0, b1, b2, b3, sb + 2 * MAT_BYTES + swz(r, c0));
                #pragma unroll
                for (int mt = 0; mt < 2; mt++) {
                    mma_f16(acc[mt][2 * p + 0], ah[mt], b0, b2);
                    mma_f16(acc[mt][2 * p + 1], ah[mt], b1, b3);
                }
                #pragma unroll
                for (int mt = 0; mt < 2; mt++) {
                    mma_f16(acc[mt][2 * p + 0], al[mt], b0, b2);
                    mma_f16(acc[mt][2 * p + 1], al[mt], b1, b3);
                }
            }
        }
    }

    // ---- epilogue ----
    #pragma unroll
    for (int mt = 0; mt < 2; mt++) {
        const int r = bm + wr * 32 + mt * 16 + (lane >> 2);
        #pragma unroll
        for (int nt = 0; nt < 8; nt++) {
            const int c = bn + wc * 64 + nt * 8 + 2 * (lane & 3);
            float2 v0 = make_float2(acc[mt][nt][0], acc[mt][nt][1]);
            float2 v1 = make_float2(acc[mt][nt][2], acc[mt][nt][3]);
            if (mode == 0) {
                int chunk = c / INNER;
                int e = c % INNER;
                int h = e >> 6, d = e & 63;
                int b0 = r >> 10, n0 = r & 1023;
                int r2 = r + 8;
                int b1 = r2 >> 10, n1 = r2 & 1023;
                size_t i0 = (((size_t)(b0 * HEADS + h) * SEQ) + n0) * HDIM + d;
                size_t i1 = (((size_t)(b1 * HEADS + h) * SEQ) + n1) * HDIM + d;
                if (chunk == 2) {
                    __half2 hh, ll;
                    split2h(v0, hh, ll);
                    *(__half2*)&g_vh16[i0] = hh;
                    *(__half2*)&g_vl16[i0] = ll;
                    split2h(v1, hh, ll);
                    *(__half2*)&g_vh16[i1] = hh;
                    *(__half2*)&g_vl16[i1] = ll;
                } else if (chunk == 0) {
                    // Q: scale + fp16 hi/lo split
                    v0.x *= SCALE; v0.y *= SCALE;
                    v1.x *= SCALE; v1.y *= SCALE;
                    __half2 hh, ll;
                    split2h(v0, hh, ll);
                    *(__half2*)&g_qh16[i0] = hh;
                    *(__half2*)&g_ql16[i0] = ll;
                    split2h(v1, hh, ll);
                    *(__half2*)&g_qh16[i1] = hh;
                    *(__half2*)&g_ql16[i1] = ll;
                } else {
                    // K: fp16 hi only
                    *(__half2*)&g_kh16[i0] = __floats2half2_rn(v0.x, v0.y);
                    *(__half2*)&g_kh16[i1] = __floats2half2_rn(v1.x, v1.y);
                }
            } else {
                float2 bq = *(const float2*)&bias[c];
                v0.x += bq.x; v0.y += bq.y;
                v1.x += bq.x; v1.y += bq.y;
                *(float2*)&outp[(size_t)r * DIM + c] = v0;
                *(float2*)&outp[(size_t)(r + 8) * DIM + c] = v1;
            }
        }
    }
}

// =========================================================================
// Score HMMA (fp16 2-MMA): E = exp((Qh+Ql).Kh)/16 -> fp16.
// 128x128 tile per (b,h), K=64 one-shot.
// =========================================================================
#define SGS 72
#define SC_MAT (128 * SGS)
#define SC_SMEM_BYTES (3 * SC_MAT * 2)   // 55296

__global__ __launch_bounds__(256, 2) void score_hmma_kernel()
{
    extern __shared__ f16 smh[];
    const int tid = threadIdx.x, lane = tid & 31, wid = tid >> 5;
    const int wr = wid >> 1, wc = wid & 1;
    const int bh = blockIdx.z;
    const int n0 = blockIdx.y * 128;
    const int m0 = blockIdx.x * 128;
    const uint32_t smem_base = smem_to_u32(smh);

    const f16* srcs[3] = {
        g_qh16 + ((size_t)bh * SEQ + n0) * HDIM,
        g_ql16 + ((size_t)bh * SEQ + n0) * HDIM,
        g_kh16 + ((size_t)bh * SEQ + m0) * HDIM
    };
    #pragma unroll
    for (int m = 0; m < 3; m++) {
        #pragma unroll
        for (int t = 0; t < 4; t++) {
            int i = tid + t * 256;
            int row = i >> 3, ch = i & 7;
            *(uint4*)&smh[m * SC_MAT + row * SGS + ch * 8] =
                *(const uint4*)(srcs[m] + (size_t)row * HDIM + ch * 8);
        }
    }
    __syncthreads();

    float acc[2][8][4] = {};

    #pragma unroll
    for (int ks = 0; ks < 4; ks++) {
        const uint32_t col = ks * 16 + (lane >> 4) * 8;
        uint32_t ah[2][4], al[2][4];
        #pragma unroll
        for (int mt = 0; mt < 2; mt++) {
            uint32_t r = wr * 32 + mt * 16 + (lane & 15);
            ldmatrix_x4(ah[mt][0], ah[mt][1], ah[mt][2], ah[mt][3],
                        smem_base + (0 * SC_MAT + r * SGS + col) * 2);
            ldmatrix_x4(al[mt][0], al[mt][1], al[mt][2], al[mt][3],
                        smem_base + (1 * SC_MAT + r * SGS + col) * 2);
        }
        #pragma unroll
        for (int p = 0; p < 4; p++) {
            uint32_t r = wc * 64 + p * 16 + (lane & 15);
            uint32_t b0, b1, b2, b3;
            ldmatrix_x4(b0, b1, b2, b3,
                        smem_base + (2 * SC_MAT + r * SGS + col) * 2);
            #pragma unroll
            for (int mt = 0; mt < 2; mt++) {
                mma_f16(acc[mt][2 * p + 0], ah[mt], b0, b2);
                mma_f16(acc[mt][2 * p + 1], ah[mt], b1, b3);
            }
            #pragma unroll
            for (int mt = 0; mt < 2; mt++) {
                mma_f16(acc[mt][2 * p + 0], al[mt], b0, b2);
                mma_f16(acc[mt][2 * p + 1], al[mt], b1, b3);
            }
        }
    }

    f16* ebase = g_e + (size_t)bh * SEQ * SEQ;
    #pragma unroll
    for (int mt = 0; mt < 2; mt++) {
        const int r = n0 + wr * 32 + mt * 16 + (lane >> 2);
        #pragma unroll
        for (int nt = 0; nt < 8; nt++) {
            const int c = m0 + wc * 64 + nt * 8 + 2 * (lane & 3);
            __half2 e0 = __floats2half2_rn(fast_exp_s(acc[mt][nt][0]),
                                           fast_exp_s(acc[mt][nt][1]));
            __half2 e1 = __floats2half2_rn(fast_exp_s(acc[mt][nt][2]),
                                           fast_exp_s(acc[mt][nt][3]));
            *(__half2*)&ebase[(size_t)r * SEQ + c] = e0;
            *(__half2*)&ebase[(size_t)(r + 8) * SEQ + c] = e1;
        }
    }
}

// =========================================================================
// Sum: rinv[b,n,m] = 1 / sum_h E  (fp16; L2-resident, 16.8 MB)
// =========================================================================
__global__ __launch_bounds__(256) void sum_kernel()
{
    size_t idx = (size_t)blockIdx.x * 256 + threadIdx.x;   // < 2M (uint2 units)
    int m4 = idx & 255;
    int n = (idx >> 8) & 1023;
    int b = (int)(idx >> 18);

    const uint2* E = (const uint2*)g_e;
    float4 s = make_float4(0.f, 0.f, 0.f, 0.f);
    #pragma unroll
    for (int h = 0; h < HEADS; h++) {
        size_t off = ((size_t)(b * HEADS + h) * SEQ + n) * (SEQ / 4) + m4;
        uint2 u = E[off];
        float2 f0 = __half22float2(*(__half2*)&u.x);
        float2 f1 = __half22float2(*(__half2*)&u.y);
        s.x += f0.x; s.y += f0.y; s.z += f1.x; s.w += f1.y;
    }
    uint2 o;
    *(__half2*)&o.x = __floats2half2_rn(1.0f / s.x, 1.0f / s.y);
    *(__half2*)&o.y = __floats2half2_rn(1.0f / s.z, 1.0f / s.w);
    ((uint2*)g_rinv)[((size_t)(b * SEQ + n)) * (SEQ / 4) + m4] = o;
}

// =========================================================================
// AV HMMA (fp16): O = (E*rinv) @ V. 128(n) x 64(d), K=1024 in 32-chunks.
// Normalization done in MMA fragments via HMUL2 (rinv ldmatrix'd with the
// identical swizzle -> elementwise correspondence).
// =========================================================================
#define AVE_BYTES 8192                  // E tile 128x32 f16 swizzled
#define AVR_BYTES 8192                  // rinv tile, same layout
#define AVV_BYTES 4608                  // V tile 32x72 f16
#define AV_STG_BYTES (AVE_BYTES + AVR_BYTES + 2 * AVV_BYTES)  // 25600
#define AV_SMEM_BYTES (3 * AV_STG_BYTES)                      // 76800
#define VGS 72

__global__ __launch_bounds__(256, 3) void av_hmma_kernel()
{
    extern __shared__ f16 smh[];
    const int tid = threadIdx.x, lane = tid & 31, wid = tid >> 5;
    const int wr = wid >> 1, wc = wid & 1;
    const int n0 = blockIdx.x * 128;
    const int bh = blockIdx.y;
    const int b = bh / HEADS, h = bh % HEADS;
    const uint32_t smem_base = smem_to_u32(smh);

    const f16* ep  = g_e    + ((size_t)bh * SEQ + n0) * SEQ;
    const f16* rp  = g_rinv + ((size_t)(b * SEQ + n0)) * SEQ;
    const f16* vhp = g_vh16 + (size_t)bh * SEQ * HDIM;
    const f16* vlp = g_vl16 + (size_t)bh * SEQ * HDIM;

    float acc[2][4][4] = {};

    const int lr0 = tid >> 2, lr1 = (tid + 256) >> 2;
    const int lc = tid & 3;
    const int vrow_ld = tid >> 3, vch_ld = tid & 7;

    auto issue = [&](int it, int s) {
        const int k0 = it * 32;
        const uint32_t sb = smem_base + (uint32_t)(s * AV_STG_BYTES);
        // E tile
        CP_ASYNC16(sb + swz(lr0, lc), ep + (size_t)lr0 * SEQ + k0 + lc * 8);
        CP_ASYNC16(sb + swz(lr1, lc), ep + (size_t)lr1 * SEQ + k0 + lc * 8);
        // rinv tile (same swizzle)
        CP_ASYNC16(sb + AVE_BYTES + swz(lr0, lc), rp + (size_t)lr0 * SEQ + k0 + lc * 8);
        CP_ASYNC16(sb + AVE_BYTES + swz(lr1, lc), rp + (size_t)lr1 * SEQ + k0 + lc * 8);
        // V hi/lo
        uint32_t doff = (uint32_t)(vrow_ld * VGS + vch_ld * 8) * 2;
        CP_ASYNC16(sb + AVE_BYTES + AVR_BYTES + doff,
                   vhp + (size_t)(k0 + vrow_ld) * HDIM + vch_ld * 8);
        CP_ASYNC16(sb + AVE_BYTES + AVR_BYTES + AVV_BYTES + doff,
                   vlp + (size_t)(k0 + vrow_ld) * HDIM + vch_ld * 8);
        CP_COMMIT();
    };

    const int NIT = SEQ / 32;
    issue(0, 0);
    issue(1, 1);

    for (int it = 0; it < NIT; ++it) {
        if (it + 1 < NIT) { CP_WAIT1(); } else { CP_WAIT0(); }
        __syncthreads();
        if (it + 2 < NIT) issue(it + 2, (it + 2) % 3);

        const uint32_t sb = smem_base + (uint32_t)((it % 3) * AV_STG_BYTES);
        const uint32_t rvb = sb + AVE_BYTES;
        const uint32_t vhb = rvb + AVR_BYTES;
        const uint32_t vlb = vhb + AVV_BYTES;

        #pragma unroll
        for (int ks = 0; ks < 2; ks++) {
            const uint32_t c0 = ks * 2 + (lane >> 4);
            uint32_t a[2][4];
            #pragma unroll
            for (int mt = 0; mt < 2; mt++) {
                uint32_t r = wr * 32 + mt * 16 + (lane & 15);
                uint32_t rv[4];
                ldmatrix_x4(a[mt][0], a[mt][1], a[mt][2], a[mt][3],
                            sb + swz(r, c0));
                ldmatrix_x4(rv[0], rv[1], rv[2], rv[3],
                            rvb + swz(r, c0));
                #pragma unroll
                for (int j = 0; j < 4; j++) a[mt][j] = hmul2u(a[mt][j], rv[j]);
            }
            const uint32_t kb = ks * 16;
            #pragma unroll
            for (int nb = 0; nb < 2; nb++) {
                const uint32_t d0 = wc * 32 + nb * 16;
                uint32_t vrow = kb + (lane & 7) + ((lane >> 3) & 1) * 8;
                uint32_t vcol = d0 + (lane >> 4) * 8;
                uint32_t bh0, bh1, bh2, bh3, bl0, bl1, bl2, bl3;
                ldmatrix_x4_trans(bh0, bh1, bh2, bh3, vhb + (vrow * VGS + vcol) * 2);
                ldmatrix_x4_trans(bl0, bl1, bl2, bl3, vlb + (vrow * VGS + vcol) * 2);
                const int nt0 = nb * 2, nt1 = nb * 2 + 1;
                #pragma unroll
                for (int mt = 0; mt < 2; mt++) {
                    mma_f16(acc[mt][nt0], a[mt], bh0, bh1);
                    mma_f16(acc[mt][nt1], a[mt], bh2, bh3);
                }
                #pragma unroll
                for (int mt = 0; mt < 2; mt++) {
                    mma_f16(acc[mt][nt0], a[mt], bl0, bl1);
                    mma_f16(acc[mt][nt1], a[mt], bl2, bl3);
                }
            }
        }
    }

    // epilogue: O -> fp16 hi/lo at [b, n, h*64+d]
    #pragma unroll
    for (int mt = 0; mt < 2; mt++) {
        const int r = n0 + wr * 32 + mt * 16 + (lane >> 2);
        #pragma unroll
        for (int nt = 0; nt < 4; nt++) {
            const int c = wc * 32 + nt * 8 + 2 * (lane & 3);
            float2 v0 = make_float2(acc[mt][nt][0], acc[mt][nt][1]);
            float2 v1 = make_float2(acc[mt][nt][2], acc[mt][nt][3]);
            __half2 hh, ll;
            size_t i0 = ((size_t)(b * SEQ + r)) * INNER + h * HDIM + c;
            split2h(v0, hh, ll);
            *(__half2*)&g_oh16[i0] = hh;
            *(__half2*)&g_ol16[i0] = ll;
            size_t i1 = ((size_t)(b * SEQ + r + 8)) * INNER + h * HDIM + c;
            split2h(v1, hh, ll);
            *(__half2*)&g_oh16[i1] = hh;
            *(__half2*)&g_ol16[i1] = ll;
        }
    }
}

// =========================================================================
extern "C" void kernel_launch(void* const* d_in, const int* in_sizes, int n_in,
                              void* d_out, int out_size)
{
    const float* x     = (const float*)d_in[0];
    const float* w_qkv = (const float*)d_in[1];
    const float* w_out = (const float*)d_in[2];
    const float* b_out = (const float*)d_in[3];
    float* out = (float*)d_out;

    cudaFuncSetAttribute(hmma_f16_gemm_kernel,
                         cudaFuncAttributeMaxDynamicSharedMemorySize, HM_SMEM_BYTES);
    cudaFuncSetAttribute(score_hmma_kernel,
                         cudaFuncAttributeMaxDynamicSharedMemorySize, SC_SMEM_BYTES);
    cudaFuncSetAttribute(av_hmma_kernel,
                         cudaFuncAttributeMaxDynamicSharedMemorySize, AV_SMEM_BYTES);

    f16 *xh, *xl, *wq, *wo, *oh, *ol;
    cudaGetSymbolAddress((void**)&xh, g_xh16);
    cudaGetSymbolAddress((void**)&xl, g_xl16);
    cudaGetSymbolAddress((void**)&wq, g_wq16);
    cudaGetSymbolAddress((void**)&wo, g_wo16);
    cudaGetSymbolAddress((void**)&oh, g_oh16);
    cudaGetSymbolAddress((void**)&ol, g_ol16);

    // Prep
    {
        int n4 = BATCH * SEQ * DIM / 4;
        split_f16_kernel<<<(n4 + 255) / 256, 256>>>(x, xh, xl, n4);
    }
    {
        dim3 grid(TRIPLE / 32, DIM / 32);
        transpose_f16_kernel<<<grid, dim3(32, 8)>>>(w_qkv, wq, DIM, TRIPLE);
    }
    {
        dim3 grid(DIM / 32, INNER / 32);
        transpose_f16_kernel<<<grid, dim3(32, 8)>>>(w_out, wo, INNER, DIM);
    }

    // K1: QKV projection (fp16 2-MMA)
    {
        dim3 grid(TRIPLE / 128, (BATCH * SEQ) / 128);
        hmma_f16_gemm_kernel<<<grid, 256, HM_SMEM_BYTES>>>(xh, xl, wq, nullptr, nullptr, 0);
    }
    // K2: scores -> exp/16 (fp16 E), fp16 2-MMA
    {
        dim3 grid(SEQ / 128, SEQ / 128, BATCH * HEADS);
        score_hmma_kernel<<<grid, 256, SC_SMEM_BYTES>>>();
    }
    // K3: rinv = 1/sum_h E
    {
        int total = BATCH * SEQ * (SEQ / 4);
        sum_kernel<<<total / 256, 256>>>();
    }
    // K4: O = (E*rinv) @ V (fp16 HMMA)
    {
        dim3 grid(SEQ / 128, BATCH * HEADS);
        av_hmma_kernel<<<grid, 256, AV_SMEM_BYTES>>>();
    }
    // K5: output projection (fp16 2-MMA) + bias
    {
        dim3 grid(DIM / 128, (BATCH * SEQ) / 128);
        hmma_f16_gemm_kernel<<<grid, 256, HM_SMEM_BYTES>>>(oh, ol, wo, b_out, out, 1);
    }
}

// round 11
// speedup vs baseline: 3.5549x; 1.0039x over previous
#include <cuda_runtime.h>
#include <cuda_bf16.h>
#include <cuda_fp16.h>
#include <cstdint>

// Problem constants
#define BATCH   8
#define SEQ     1024
#define DIM     768
#define HEADS   12
#define HDIM    64
#define INNER   768
#define TRIPLE  2304
#define SCALE   0.125f

typedef __nv_bfloat16 bf16;
typedef __half f16;

// ---------------- static scratch ----------------
__device__ __align__(128) f16 g_e[(size_t)BATCH * HEADS * SEQ * SEQ];   // E = exp(S)/16
__device__ __align__(128) f16 g_rinv[(size_t)BATCH * SEQ * SEQ];        // 1/sum_h E

// fp16 operands for the 2-MMA weight GEMMs
__device__ __align__(128) f16 g_xh16[BATCH * SEQ * DIM];
__device__ __align__(128) f16 g_xl16[BATCH * SEQ * DIM];
__device__ __align__(128) f16 g_wq16[TRIPLE * DIM];     // transposed, hi only
__device__ __align__(128) f16 g_wo16[DIM * INNER];      // transposed, hi only
__device__ __align__(128) f16 g_oh16[BATCH * SEQ * INNER];
__device__ __align__(128) f16 g_ol16[BATCH * SEQ * INNER];

// fp16 Q (hi/lo) and K (hi) for the score GEMM
__device__ __align__(128) f16 g_qh16[BATCH * HEADS * SEQ * HDIM];
__device__ __align__(128) f16 g_ql16[BATCH * HEADS * SEQ * HDIM];
__device__ __align__(128) f16 g_kh16[BATCH * HEADS * SEQ * HDIM];
// fp16 hi/lo V for the fp16 AV MMA
__device__ __align__(128) f16 g_vh16[BATCH * HEADS * SEQ * HDIM];
__device__ __align__(128) f16 g_vl16[BATCH * HEADS * SEQ * HDIM];

// ================= helpers =================
__device__ __forceinline__ uint32_t smem_to_u32(const void* p) {
    uint32_t a;
    asm("{ .reg .u64 t; cvta.to.shared.u64 t, %1; cvt.u32.u64 %0, t; }"
        : "=r"(a) : "l"(p));
    return a;
}
// swizzled byte offset within a [rows x 32 elems(16b)] tile (64B per row)
__device__ __forceinline__ uint32_t swz(uint32_t r, uint32_t c) {
    return (r * 4 + (c ^ ((r >> 1) & 3))) * 16;
}
__device__ __forceinline__ void ldmatrix_x4(uint32_t& r0, uint32_t& r1,
                                            uint32_t& r2, uint32_t& r3,
                                            uint32_t addr) {
    asm volatile("ldmatrix.sync.aligned.m8n8.x4.shared.b16 {%0,%1,%2,%3}, [%4];"
                 : "=r"(r0), "=r"(r1), "=r"(r2), "=r"(r3) : "r"(addr));
}
__device__ __forceinline__ void ldmatrix_x4_trans(uint32_t& r0, uint32_t& r1,
                                                  uint32_t& r2, uint32_t& r3,
                                                  uint32_t addr) {
    asm volatile("ldmatrix.sync.aligned.m8n8.x4.trans.shared.b16 {%0,%1,%2,%3}, [%4];"
                 : "=r"(r0), "=r"(r1), "=r"(r2), "=r"(r3) : "r"(addr));
}
__device__ __forceinline__ void mma_f16(float* c, const uint32_t* a,
                                        uint32_t b0, uint32_t b1) {
    asm volatile("mma.sync.aligned.m16n8k16.row.col.f32.f16.f16.f32 "
                 "{%0,%1,%2,%3}, {%4,%5,%6,%7}, {%8,%9}, {%0,%1,%2,%3};"
                 : "+f"(c[0]), "+f"(c[1]), "+f"(c[2]), "+f"(c[3])
                 : "r"(a[0]), "r"(a[1]), "r"(a[2]), "r"(a[3]),
                   "r"(b0), "r"(b1));
}
__device__ __forceinline__ uint32_t hmul2u(uint32_t a, uint32_t b) {
    __half2 r = __hmul2(*(__half2*)&a, *(__half2*)&b);
    return *(uint32_t*)&r;
}
#define CP_ASYNC16(sa, g) \
    asm volatile("cp.async.cg.shared.global [%0], [%1], 16;" :: "r"(sa), "l"(g))
#define CP_COMMIT() asm volatile("cp.async.commit_group;" ::: "memory")
#define CP_WAIT1()  asm volatile("cp.async.wait_group 1;" ::: "memory")
#define CP_WAIT0()  asm volatile("cp.async.wait_group 0;" ::: "memory")

__device__ __forceinline__ float fast_exp_s(float x) {
    const float LOG2E = 1.4426950408889634f;
    const float MAGIC = 12582912.0f;
    float z = fmaf(x, LOG2E, MAGIC);
    int   e = __float_as_int(z) - 0x4B400000;
    float i = z - MAGIC;
    float f = fmaf(x, LOG2E, -i);
    float p = 1.5403531e-4f;
    p = fmaf(p, f, 1.3333558e-3f);
    p = fmaf(p, f, 9.6181291e-3f);
    p = fmaf(p, f, 5.5504109e-2f);
    p = fmaf(p, f, 2.4022651e-1f);
    p = fmaf(p, f, 6.9314718e-1f);
    p = fmaf(p, f, 1.0f);
    return __int_as_float(__float_as_int(p) + ((e - 4) << 23));
}
__device__ __forceinline__ void split2h(float2 v, __half2& h, __half2& l) {
    f16 hx = __float2half_rn(v.x), hy = __float2half_rn(v.y);
    h = __half2(hx, hy);
    l = __half2(__float2half_rn(v.x - __half2float(hx)),
                __float2half_rn(v.y - __half2float(hy)));
}

// =========================================================================
// Prep kernels
// =========================================================================
__global__ __launch_bounds__(256) void split_f16_kernel(
    const float* __restrict__ in, f16* __restrict__ hi, f16* __restrict__ lo, int n4)
{
    int i = blockIdx.x * 256 + threadIdx.x;
    if (i >= n4) return;
    float4 v = ((const float4*)in)[i];
    __half2 h0, l0, h1, l1;
    split2h(make_float2(v.x, v.y), h0, l0);
    split2h(make_float2(v.z, v.w), h1, l1);
    __half2* H = (__half2*)hi;
    __half2* L = (__half2*)lo;
    H[2 * i] = h0; H[2 * i + 1] = h1;
    L[2 * i] = l0; L[2 * i + 1] = l1;
}

__global__ __launch_bounds__(256) void transpose_f16_kernel(
    const float* __restrict__ in, f16* __restrict__ outp, int R, int C)
{
    __shared__ float t[32][33];
    const int tx = threadIdx.x, ty = threadIdx.y;
    const int bx = blockIdx.x, by = blockIdx.y;
    #pragma unroll
    for (int i = 0; i < 4; i++) {
        int r = by * 32 + ty + i * 8;
        t[ty + i * 8][tx] = in[(size_t)r * C + bx * 32 + tx];
    }
    __syncthreads();
    #pragma unroll
    for (int i = 0; i < 4; i++) {
        int c = bx * 32 + ty + i * 8;
        int r = by * 32 + tx;
        outp[(size_t)c * R + r] = __float2half_rn(t[tx][ty + i * 8]);
    }
}

// =========================================================================
// fp16 2-MMA GEMM: C = (Ah+Al) @ Bw^T. 128x128x32, 3-stage, 1 barrier/iter.
// MMA order: all-B-frags loaded, then 16 ah-MMAs, then 16 al-MMAs
// (same-accumulator reuse distance 16 -> hides HMMA latency).
// =========================================================================
#define MAT_BYTES  8192
#define STG_BYTES  (3 * MAT_BYTES)
#define HM_SMEM_BYTES (3 * STG_BYTES)    // 73728

__global__ __launch_bounds__(256, 2) void hmma_f16_gemm_kernel(
    const f16* __restrict__ Ah, const f16* __restrict__ Al,
    const f16* __restrict__ Bw,
    const float* __restrict__ bias, float* __restrict__ outp, int mode)
{
    extern __shared__ f16 sm[];
    const int tid = threadIdx.x, lane = tid & 31, wid = tid >> 5;
    const int wr = wid >> 1, wc = wid & 1;
    const int bn = blockIdx.x * 128, bm = blockIdx.y * 128;
    const uint32_t smem_base = smem_to_u32(sm);

    const f16* srcs[3] = {Ah, Al, Bw};
    const int rb[3] = {bm, bm, bn};

    float acc[2][8][4] = {};

    const int lr0 = tid >> 2, lr1 = (tid + 256) >> 2;
    const int lc = tid & 3;

    auto issue = [&](int it, int s) {
        const int k0 = it * 32;
        const uint32_t sb = smem_base + (uint32_t)(s * STG_BYTES);
        #pragma unroll
        for (int m = 0; m < 3; m++) {
            const f16* src = srcs[m];
            CP_ASYNC16(sb + m * MAT_BYTES + swz(lr0, lc),
                       src + (size_t)(rb[m] + lr0) * DIM + k0 + lc * 8);
            CP_ASYNC16(sb + m * MAT_BYTES + swz(lr1, lc),
                       src + (size_t)(rb[m] + lr1) * DIM + k0 + lc * 8);
        }
        CP_COMMIT();
    };

    const int NIT = DIM / 32;   // 24
    issue(0, 0);
    issue(1, 1);

    for (int it = 0; it < NIT; ++it) {
        if (it + 1 < NIT) { CP_WAIT1(); } else { CP_WAIT0(); }
        __syncthreads();
        if (it + 2 < NIT) issue(it + 2, (it + 2) % 3);

        const uint32_t sb = smem_base + (uint32_t)((it % 3) * STG_BYTES);
        #pragma unroll
        for (int ks = 0; ks < 2; ks++) {
            const uint32_t c0 = ks * 2 + (lane >> 4);
            uint32_t ah[2][4], al[2][4], bf[4][4];
            #pragma unroll
            for (int mt = 0; mt < 2; mt++) {
                uint32_t r = wr * 32 + mt * 16 + (lane & 15);
                ldmatrix_x4(ah[mt][0], ah[mt][1], ah[mt][2], ah[mt][3],
                            sb + 0 * MAT_BYTES + swz(r, c0));
                ldmatrix_x4(al[mt][0], al[mt][1], al[mt][2], al[mt][3],
                            sb + 1 * MAT_BYTES + swz(r, c0));
            }
            #pragma unroll
            for (int p = 0; p < 4; p++) {
                uint32_t r = wc * 64 + p * 16 + (lane & 15);
                ldmatrix_x4(bf[p][0], bf[p][1], bf[p][2], bf[p][3],
                            sb + 2 * MAT_BYTES + swz(r, c0));
            }
            // phase 1: 16 ah-MMAs (all distinct accumulators)
            #pragma unroll
            for (int p = 0; p < 4; p++)
                #pragma unroll
                for (int mt = 0; mt < 2; mt++) {
                    mma_f16(acc[mt][2 * p + 0], ah[mt], bf[p][0], bf[p][2]);
                    mma_f16(acc[mt][2 * p + 1], ah[mt], bf[p][1], bf[p][3]);
                }
            // phase 2: 16 al-MMAs
            #pragma unroll
            for (int p = 0; p < 4; p++)
                #pragma unroll
                for (int mt = 0; mt < 2; mt++) {
                    mma_f16(acc[mt][2 * p + 0], al[mt], bf[p][0], bf[p][2]);
                    mma_f16(acc[mt][2 * p + 1], al[mt], bf[p][1], bf[p][3]);
                }
        }
    }

    // ---- epilogue ----
    #pragma unroll
    for (int mt = 0; mt < 2; mt++) {
        const int r = bm + wr * 32 + mt * 16 + (lane >> 2);
        #pragma unroll
        for (int nt = 0; nt < 8; nt++) {
            const int c = bn + wc * 64 + nt * 8 + 2 * (lane & 3);
            float2 v0 = make_float2(acc[mt][nt][0], acc[mt][nt][1]);
            float2 v1 = make_float2(acc[mt][nt][2], acc[mt][nt][3]);
            if (mode == 0) {
                int chunk = c / INNER;
                int e = c % INNER;
                int h = e >> 6, d = e & 63;
                int b0 = r >> 10, n0 = r & 1023;
                int r2 = r + 8;
                int b1 = r2 >> 10, n1 = r2 & 1023;
                size_t i0 = (((size_t)(b0 * HEADS + h) * SEQ) + n0) * HDIM + d;
                size_t i1 = (((size_t)(b1 * HEADS + h) * SEQ) + n1) * HDIM + d;
                if (chunk == 2) {
                    __half2 hh, ll;
                    split2h(v0, hh, ll);
                    *(__half2*)&g_vh16[i0] = hh;
                    *(__half2*)&g_vl16[i0] = ll;
                    split2h(v1, hh, ll);
                    *(__half2*)&g_vh16[i1] = hh;
                    *(__half2*)&g_vl16[i1] = ll;
                } else if (chunk == 0) {
                    v0.x *= SCALE; v0.y *= SCALE;
                    v1.x *= SCALE; v1.y *= SCALE;
                    __half2 hh, ll;
                    split2h(v0, hh, ll);
                    *(__half2*)&g_qh16[i0] = hh;
                    *(__half2*)&g_ql16[i0] = ll;
                    split2h(v1, hh, ll);
                    *(__half2*)&g_qh16[i1] = hh;
                    *(__half2*)&g_ql16[i1] = ll;
                } else {
                    *(__half2*)&g_kh16[i0] = __floats2half2_rn(v0.x, v0.y);
                    *(__half2*)&g_kh16[i1] = __floats2half2_rn(v1.x, v1.y);
                }
            } else {
                float2 bq = *(const float2*)&bias[c];
                v0.x += bq.x; v0.y += bq.y;
                v1.x += bq.x; v1.y += bq.y;
                *(float2*)&outp[(size_t)r * DIM + c] = v0;
                *(float2*)&outp[(size_t)(r + 8) * DIM + c] = v1;
            }
        }
    }
}

// =========================================================================
// Score HMMA (fp16 2-MMA): E = exp((Qh+Ql).Kh)/16 -> fp16.
// Same two-phase MMA ordering as the weight GEMM.
// =========================================================================
#define SGS 72
#define SC_MAT (128 * SGS)
#define SC_SMEM_BYTES (3 * SC_MAT * 2)   // 55296

__global__ __launch_bounds__(256, 2) void score_hmma_kernel()
{
    extern __shared__ f16 smh[];
    const int tid = threadIdx.x, lane = tid & 31, wid = tid >> 5;
    const int wr = wid >> 1, wc = wid & 1;
    const int bh = blockIdx.z;
    const int n0 = blockIdx.y * 128;
    const int m0 = blockIdx.x * 128;
    const uint32_t smem_base = smem_to_u32(smh);

    const f16* srcs[3] = {
        g_qh16 + ((size_t)bh * SEQ + n0) * HDIM,
        g_ql16 + ((size_t)bh * SEQ + n0) * HDIM,
        g_kh16 + ((size_t)bh * SEQ + m0) * HDIM
    };
    #pragma unroll
    for (int m = 0; m < 3; m++) {
        #pragma unroll
        for (int t = 0; t < 4; t++) {
            int i = tid + t * 256;
            int row = i >> 3, ch = i & 7;
            *(uint4*)&smh[m * SC_MAT + row * SGS + ch * 8] =
                *(const uint4*)(srcs[m] + (size_t)row * HDIM + ch * 8);
        }
    }
    __syncthreads();

    float acc[2][8][4] = {};

    #pragma unroll
    for (int ks = 0; ks < 4; ks++) {
        const uint32_t col = ks * 16 + (lane >> 4) * 8;
        uint32_t ah[2][4], al[2][4], bf[4][4];
        #pragma unroll
        for (int mt = 0; mt < 2; mt++) {
            uint32_t r = wr * 32 + mt * 16 + (lane & 15);
            ldmatrix_x4(ah[mt][0], ah[mt][1], ah[mt][2], ah[mt][3],
                        smem_base + (0 * SC_MAT + r * SGS + col) * 2);
            ldmatrix_x4(al[mt][0], al[mt][1], al[mt][2], al[mt][3],
                        smem_base + (1 * SC_MAT + r * SGS + col) * 2);
        }
        #pragma unroll
        for (int p = 0; p < 4; p++) {
            uint32_t r = wc * 64 + p * 16 + (lane & 15);
            ldmatrix_x4(bf[p][0], bf[p][1], bf[p][2], bf[p][3],
                        smem_base + (2 * SC_MAT + r * SGS + col) * 2);
        }
        #pragma unroll
        for (int p = 0; p < 4; p++)
            #pragma unroll
            for (int mt = 0; mt < 2; mt++) {
                mma_f16(acc[mt][2 * p + 0], ah[mt], bf[p][0], bf[p][2]);
                mma_f16(acc[mt][2 * p + 1], ah[mt], bf[p][1], bf[p][3]);
            }
        #pragma unroll
        for (int p = 0; p < 4; p++)
            #pragma unroll
            for (int mt = 0; mt < 2; mt++) {
                mma_f16(acc[mt][2 * p + 0], al[mt], bf[p][0], bf[p][2]);
                mma_f16(acc[mt][2 * p + 1], al[mt], bf[p][1], bf[p][3]);
            }
    }

    f16* ebase = g_e + (size_t)bh * SEQ * SEQ;
    #pragma unroll
    for (int mt = 0; mt < 2; mt++) {
        const int r = n0 + wr * 32 + mt * 16 + (lane >> 2);
        #pragma unroll
        for (int nt = 0; nt < 8; nt++) {
            const int c = m0 + wc * 64 + nt * 8 + 2 * (lane & 3);
            __half2 e0 = __floats2half2_rn(fast_exp_s(acc[mt][nt][0]),
                                           fast_exp_s(acc[mt][nt][1]));
            __half2 e1 = __floats2half2_rn(fast_exp_s(acc[mt][nt][2]),
                                           fast_exp_s(acc[mt][nt][3]));
            *(__half2*)&ebase[(size_t)r * SEQ + c] = e0;
            *(__half2*)&ebase[(size_t)(r + 8) * SEQ + c] = e1;
        }
    }
}

// =========================================================================
// Sum: rinv[b,n,m] = 1 / sum_h E  (fp16; L2-resident, 16.8 MB)
// =========================================================================
__global__ __launch_bounds__(256) void sum_kernel()
{
    size_t idx = (size_t)blockIdx.x * 256 + threadIdx.x;
    int m4 = idx & 255;
    int n = (idx >> 8) & 1023;
    int b = (int)(idx >> 18);

    const uint2* E = (const uint2*)g_e;
    float4 s = make_float4(0.f, 0.f, 0.f, 0.f);
    #pragma unroll
    for (int h = 0; h < HEADS; h++) {
        size_t off = ((size_t)(b * HEADS + h) * SEQ + n) * (SEQ / 4) + m4;
        uint2 u = E[off];
        float2 f0 = __half22float2(*(__half2*)&u.x);
        float2 f1 = __half22float2(*(__half2*)&u.y);
        s.x += f0.x; s.y += f0.y; s.z += f1.x; s.w += f1.y;
    }
    uint2 o;
    *(__half2*)&o.x = __floats2half2_rn(1.0f / s.x, 1.0f / s.y);
    *(__half2*)&o.y = __floats2half2_rn(1.0f / s.z, 1.0f / s.w);
    ((uint2*)g_rinv)[((size_t)(b * SEQ + n)) * (SEQ / 4) + m4] = o;
}

// =========================================================================
// AV HMMA (fp16): O = (E*rinv) @ V. Unchanged mainloop (occ-3 protected).
// =========================================================================
#define AVE_BYTES 8192
#define AVR_BYTES 8192
#define AVV_BYTES 4608
#define AV_STG_BYTES (AVE_BYTES + AVR_BYTES + 2 * AVV_BYTES)  // 25600
#define AV_SMEM_BYTES (3 * AV_STG_BYTES)                      // 76800
#define VGS 72

__global__ __launch_bounds__(256, 3) void av_hmma_kernel()
{
    extern __shared__ f16 smh[];
    const int tid = threadIdx.x, lane = tid & 31, wid = tid >> 5;
    const int wr = wid >> 1, wc = wid & 1;
    const int n0 = blockIdx.x * 128;
    const int bh = blockIdx.y;
    const int b = bh / HEADS, h = bh % HEADS;
    const uint32_t smem_base = smem_to_u32(smh);

    const f16* ep  = g_e    + ((size_t)bh * SEQ + n0) * SEQ;
    const f16* rp  = g_rinv + ((size_t)(b * SEQ + n0)) * SEQ;
    const f16* vhp = g_vh16 + (size_t)bh * SEQ * HDIM;
    const f16* vlp = g_vl16 + (size_t)bh * SEQ * HDIM;

    float acc[2][4][4] = {};

    const int lr0 = tid >> 2, lr1 = (tid + 256) >> 2;
    const int lc = tid & 3;
    const int vrow_ld = tid >> 3, vch_ld = tid & 7;

    auto issue = [&](int it, int s) {
        const int k0 = it * 32;
        const uint32_t sb = smem_base + (uint32_t)(s * AV_STG_BYTES);
        CP_ASYNC16(sb + swz(lr0, lc), ep + (size_t)lr0 * SEQ + k0 + lc * 8);
        CP_ASYNC16(sb + swz(lr1, lc), ep + (size_t)lr1 * SEQ + k0 + lc * 8);
        CP_ASYNC16(sb + AVE_BYTES + swz(lr0, lc), rp + (size_t)lr0 * SEQ + k0 + lc * 8);
        CP_ASYNC16(sb + AVE_BYTES + swz(lr1, lc), rp + (size_t)lr1 * SEQ + k0 + lc * 8);
        uint32_t doff = (uint32_t)(vrow_ld * VGS + vch_ld * 8) * 2;
        CP_ASYNC16(sb + AVE_BYTES + AVR_BYTES + doff,
                   vhp + (size_t)(k0 + vrow_ld) * HDIM + vch_ld * 8);
        CP_ASYNC16(sb + AVE_BYTES + AVR_BYTES + AVV_BYTES + doff,
                   vlp + (size_t)(k0 + vrow_ld) * HDIM + vch_ld * 8);
        CP_COMMIT();
    };

    const int NIT = SEQ / 32;
    issue(0, 0);
    issue(1, 1);

    for (int it = 0; it < NIT; ++it) {
        if (it + 1 < NIT) { CP_WAIT1(); } else { CP_WAIT0(); }
        __syncthreads();
        if (it + 2 < NIT) issue(it + 2, (it + 2) % 3);

        const uint32_t sb = smem_base + (uint32_t)((it % 3) * AV_STG_BYTES);
        const uint32_t rvb = sb + AVE_BYTES;
        const uint32_t vhb = rvb + AVR_BYTES;
        const uint32_t vlb = vhb + AVV_BYTES;

        #pragma unroll
        for (int ks = 0; ks < 2; ks++) {
            const uint32_t c0 = ks * 2 + (lane >> 4);
            uint32_t a[2][4];
            #pragma unroll
            for (int mt = 0; mt < 2; mt++) {
                uint32_t r = wr * 32 + mt * 16 + (lane & 15);
                uint32_t rv[4];
                ldmatrix_x4(a[mt][0], a[mt][1], a[mt][2], a[mt][3],
                            sb + swz(r, c0));
                ldmatrix_x4(rv[0], rv[1], rv[2], rv[3],
                            rvb + swz(r, c0));
                #pragma unroll
                for (int j = 0; j < 4; j++) a[mt][j] = hmul2u(a[mt][j], rv[j]);
            }
            const uint32_t kb = ks * 16;
            #pragma unroll
            for (int nb = 0; nb < 2; nb++) {
                const uint32_t d0 = wc * 32 + nb * 16;
                uint32_t vrow = kb + (lane & 7) + ((lane >> 3) & 1) * 8;
                uint32_t vcol = d0 + (lane >> 4) * 8;
                uint32_t bh0, bh1, bh2, bh3, bl0, bl1, bl2, bl3;
                ldmatrix_x4_trans(bh0, bh1, bh2, bh3, vhb + (vrow * VGS + vcol) * 2);
                ldmatrix_x4_trans(bl0, bl1, bl2, bl3, vlb + (vrow * VGS + vcol) * 2);
                const int nt0 = nb * 2, nt1 = nb * 2 + 1;
                #pragma unroll
                for (int mt = 0; mt < 2; mt++) {
                    mma_f16(acc[mt][nt0], a[mt], bh0, bh1);
                    mma_f16(acc[mt][nt1], a[mt], bh2, bh3);
                }
                #pragma unroll
                for (int mt = 0; mt < 2; mt++) {
                    mma_f16(acc[mt][nt0], a[mt], bl0, bl1);
                    mma_f16(acc[mt][nt1], a[mt], bl2, bl3);
                }
            }
        }
    }

    // epilogue: O -> fp16 hi/lo at [b, n, h*64+d]
    #pragma unroll
    for (int mt = 0; mt < 2; mt++) {
        const int r = n0 + wr * 32 + mt * 16 + (lane >> 2);
        #pragma unroll
        for (int nt = 0; nt < 4; nt++) {
            const int c = wc * 32 + nt * 8 + 2 * (lane & 3);
            float2 v0 = make_float2(acc[mt][nt][0], acc[mt][nt][1]);
            float2 v1 = make_float2(acc[mt][nt][2], acc[mt][nt][3]);
            __half2 hh, ll;
            size_t i0 = ((size_t)(b * SEQ + r)) * INNER + h * HDIM + c;
            split2h(v0, hh, ll);
            *(__half2*)&g_oh16[i0] = hh;
            *(__half2*)&g_ol16[i0] = ll;
            size_t i1 = ((size_t)(b * SEQ + r + 8)) * INNER + h * HDIM + c;
            split2h(v1, hh, ll);
            *(__half2*)&g_oh16[i1] = hh;
            *(__half2*)&g_ol16[i1] = ll;
        }
    }
}

// =========================================================================
extern "C" void kernel_launch(void* const* d_in, const int* in_sizes, int n_in,
                              void* d_out, int out_size)
{
    const float* x     = (const float*)d_in[0];
    const float* w_qkv = (const float*)d_in[1];
    const float* w_out = (const float*)d_in[2];
    const float* b_out = (const float*)d_in[3];
    float* out = (float*)d_out;

    cudaFuncSetAttribute(hmma_f16_gemm_kernel,
                         cudaFuncAttributeMaxDynamicSharedMemorySize, HM_SMEM_BYTES);
    cudaFuncSetAttribute(score_hmma_kernel,
                         cudaFuncAttributeMaxDynamicSharedMemorySize, SC_SMEM_BYTES);
    cudaFuncSetAttribute(av_hmma_kernel,
                         cudaFuncAttributeMaxDynamicSharedMemorySize, AV_SMEM_BYTES);

    f16 *xh, *xl, *wq, *wo, *oh, *ol;
    cudaGetSymbolAddress((void**)&xh, g_xh16);
    cudaGetSymbolAddress((void**)&xl, g_xl16);
    cudaGetSymbolAddress((void**)&wq, g_wq16);
    cudaGetSymbolAddress((void**)&wo, g_wo16);
    cudaGetSymbolAddress((void**)&oh, g_oh16);
    cudaGetSymbolAddress((void**)&ol, g_ol16);

    // Prep
    {
        int n4 = BATCH * SEQ * DIM / 4;
        split_f16_kernel<<<(n4 + 255) / 256, 256>>>(x, xh, xl, n4);
    }
    {
        dim3 grid(TRIPLE / 32, DIM / 32);
        transpose_f16_kernel<<<grid, dim3(32, 8)>>>(w_qkv, wq, DIM, TRIPLE);
    }
    {
        dim3 grid(DIM / 32, INNER / 32);
        transpose_f16_kernel<<<grid, dim3(32, 8)>>>(w_out, wo, INNER, DIM);
    }

    // K1: QKV projection (fp16 2-MMA)
    {
        dim3 grid(TRIPLE / 128, (BATCH * SEQ) / 128);
        hmma_f16_gemm_kernel<<<grid, 256, HM_SMEM_BYTES>>>(xh, xl, wq, nullptr, nullptr, 0);
    }
    // K2: scores -> exp/16 (fp16 E)
    {
        dim3 grid(SEQ / 128, SEQ / 128, BATCH * HEADS);
        score_hmma_kernel<<<grid, 256, SC_SMEM_BYTES>>>();
    }
    // K3: rinv = 1/sum_h E
    {
        int total = BATCH * SEQ * (SEQ / 4);
        sum_kernel<<<total / 256, 256>>>();
    }
    // K4: O = (E*rinv) @ V (fp16 HMMA)
    {
        dim3 grid(SEQ / 128, BATCH * HEADS);
        av_hmma_kernel<<<grid, 256, AV_SMEM_BYTES>>>();
    }
    // K5: output projection (fp16 2-MMA) + bias
    {
        dim3 grid(DIM / 128, (BATCH * SEQ) / 128);
        hmma_f16_gemm_kernel<<<grid, 256, HM_SMEM_BYTES>>>(oh, ol, wo, b_out, out, 1);
    }
}